// round 2
// baseline (speedup 1.0000x reference)
#include <cuda_runtime.h>
#include <math.h>

#define T_TOK   4096
#define HID     2048
#define H_HEADS 16
#define D_NOPE  128
#define D_ROPE  64
#define D_V     128
#define L_KV    512
#define D_QK    192   // D_NOPE + D_ROPE
#define KV_W    256   // D_NOPE + D_V per head in kv

// ---------------- scratch (device globals; no allocation allowed) ----------
__device__ float g_q[(size_t)T_TOK * H_HEADS * D_QK];          // 4096 x 3072
__device__ float g_latent[(size_t)T_TOK * (L_KV + D_ROPE)];    // 4096 x 576
__device__ float g_kva[(size_t)T_TOK * L_KV];                  // 4096 x 512
__device__ float g_kpe[(size_t)T_TOK * D_ROPE];                // 4096 x 64 (roped)
__device__ float g_kv[(size_t)T_TOK * H_HEADS * KV_W];         // 4096 x 4096
__device__ float g_attn[(size_t)T_TOK * H_HEADS * D_V];        // 4096 x 2048

// ---------------- classic 128x128x8 register-tiled SGEMM -------------------
#define GBM 128
#define GBN 128
#define GBK 8
__global__ __launch_bounds__(256) void sgemm_kernel(
    const float* __restrict__ A, const float* __restrict__ B,
    float* __restrict__ C, int M, int N, int K)
{
    __shared__ float As[GBK][GBM];
    __shared__ float Bs[GBK][GBN];

    int tid = threadIdx.x;
    int tx = tid & 15, ty = tid >> 4;
    int row0 = blockIdx.y * GBM;
    int col0 = blockIdx.x * GBN;

    float acc[8][8];
#pragma unroll
    for (int i = 0; i < 8; i++)
#pragma unroll
        for (int j = 0; j < 8; j++) acc[i][j] = 0.f;

    for (int k0 = 0; k0 < K; k0 += GBK) {
#pragma unroll
        for (int i = 0; i < 4; i++) {
            int idx = tid + i * 256;
            int ar = idx >> 3, ac = idx & 7;                 // A tile: 128 x 8
            As[ac][ar] = A[(size_t)(row0 + ar) * K + k0 + ac];
            int br = idx >> 7, bc = idx & 127;               // B tile: 8 x 128
            Bs[br][bc] = (col0 + bc < N) ? B[(size_t)(k0 + br) * N + col0 + bc] : 0.f;
        }
        __syncthreads();
#pragma unroll
        for (int kk = 0; kk < GBK; kk++) {
            float a[8], b[8];
#pragma unroll
            for (int i = 0; i < 8; i++) a[i] = As[kk][ty * 8 + i];
#pragma unroll
            for (int j = 0; j < 8; j++) b[j] = Bs[kk][tx * 8 + j];
#pragma unroll
            for (int i = 0; i < 8; i++)
#pragma unroll
                for (int j = 0; j < 8; j++) acc[i][j] += a[i] * b[j];
        }
        __syncthreads();
    }
#pragma unroll
    for (int i = 0; i < 8; i++) {
        int gr = row0 + ty * 8 + i;
#pragma unroll
        for (int j = 0; j < 8; j++) {
            int gc = col0 + tx * 8 + j;
            if (gc < N) C[(size_t)gr * N + gc] = acc[i][j];
        }
    }
}

// ---------------- rmsnorm on latent[:, :512] + RoPE on k_pe ----------------
__global__ __launch_bounds__(256) void rmsnorm_ropek_kernel(
    const float* __restrict__ latent, const float* __restrict__ w,
    const int* __restrict__ positions,
    float* __restrict__ kva, float* __restrict__ kpe)
{
    int t = blockIdx.x;
    const float* x = latent + (size_t)t * (L_KV + D_ROPE);
    __shared__ float red[256];
    float ss = 0.f;
    for (int i = threadIdx.x; i < L_KV; i += 256) { float v = x[i]; ss += v * v; }
    red[threadIdx.x] = ss;
    __syncthreads();
    for (int s = 128; s > 0; s >>= 1) {
        if (threadIdx.x < s) red[threadIdx.x] += red[threadIdx.x + s];
        __syncthreads();
    }
    float inv = rsqrtf(red[0] / (float)L_KV + 1e-6f);
    for (int i = threadIdx.x; i < L_KV; i += 256)
        kva[(size_t)t * L_KV + i] = x[i] * inv * w[i];

    if (threadIdx.x < 32) {
        int i = threadIdx.x;
        double pos  = (double)positions[t];
        double freq = pow(10000.0, -(double)i / 32.0);
        double ang  = pos * freq;
        float c = (float)cos(ang), s = (float)sin(ang);
        float x1 = x[L_KV + i], x2 = x[L_KV + 32 + i];
        kpe[(size_t)t * D_ROPE + i]      = x1 * c - x2 * s;
        kpe[(size_t)t * D_ROPE + 32 + i] = x2 * c + x1 * s;
    }
}

// ---------------- RoPE on q_pe (in place on g_q) ---------------------------
__global__ __launch_bounds__(512) void rope_q_kernel(
    float* __restrict__ q, const int* __restrict__ positions)
{
    int t = blockIdx.x;
    int h = threadIdx.x >> 5, i = threadIdx.x & 31;
    double pos  = (double)positions[t];
    double freq = pow(10000.0, -(double)i / 32.0);
    double ang  = pos * freq;
    float c = (float)cos(ang), s = (float)sin(ang);
    float* base = q + ((size_t)t * H_HEADS + h) * D_QK + D_NOPE;
    float x1 = base[i], x2 = base[32 + i];
    base[i]      = x1 * c - x2 * s;
    base[32 + i] = x2 * c + x1 * s;
}

// ---------------- causal flash attention (fp32) ----------------------------
// grid (T/64, H), 256 threads. smem: Qs[192][65], Ks[192][65], Vs[64][128], Ps[64][65]
#define BM 64
#define BN 64
#define QK_PAD 65
#define ATTN_SMEM ((D_QK * QK_PAD * 2 + BN * D_V + BN * QK_PAD) * 4)

__global__ __launch_bounds__(256, 1) void attn_kernel(
    const float* __restrict__ q, const float* __restrict__ kv,
    const float* __restrict__ kpe, float* __restrict__ out)
{
    extern __shared__ float sm[];
    float* Qs = sm;                        // [D_QK][65]
    float* Ks = Qs + D_QK * QK_PAD;        // [D_QK][65]
    float* Vs = Ks + D_QK * QK_PAD;        // [BN][D_V]
    float* Ps = Vs + BN * D_V;             // [BN][65] (transposed P)

    const int h  = blockIdx.y;
    const int q0 = blockIdx.x * BM;
    const int tid = threadIdx.x;
    const int tx = tid & 15, ty = tid >> 4;
    const float scale = 0.07216878364870323f;   // 1/sqrt(192)

    // load Q tile (pre-scaled), transposed
    for (int idx = tid; idx < BM * D_QK; idx += 256) {
        int r = idx / D_QK, d = idx % D_QK;
        Qs[d * QK_PAD + r] = q[((size_t)(q0 + r) * H_HEADS + h) * D_QK + d] * scale;
    }

    float m[4], l[4], acc[4][8];
#pragma unroll
    for (int i = 0; i < 4; i++) {
        m[i] = -1e30f; l[i] = 0.f;
#pragma unroll
        for (int j = 0; j < 8; j++) acc[i][j] = 0.f;
    }

    const int s_end = q0 + BM;
    for (int s0 = 0; s0 < s_end; s0 += BN) {
        __syncthreads();   // previous-iteration readers done (also covers Q load)
        for (int idx = tid; idx < BN * D_QK; idx += 256) {
            int r = idx / D_QK, d = idx % D_QK;
            float v = (d < D_NOPE)
                ? kv[((size_t)(s0 + r) * H_HEADS + h) * KV_W + d]
                : kpe[(size_t)(s0 + r) * D_ROPE + (d - D_NOPE)];
            Ks[d * QK_PAD + r] = v;
        }
        for (int idx = tid; idx < BN * D_V; idx += 256) {
            int r = idx >> 7, c = idx & 127;
            Vs[r * D_V + c] = kv[((size_t)(s0 + r) * H_HEADS + h) * KV_W + D_NOPE + c];
        }
        __syncthreads();

        // S tile: 4x4 per thread
        float sreg[4][4];
#pragma unroll
        for (int i = 0; i < 4; i++)
#pragma unroll
            for (int j = 0; j < 4; j++) sreg[i][j] = 0.f;

        for (int d = 0; d < D_QK; d++) {
            float a[4], b[4];
#pragma unroll
            for (int i = 0; i < 4; i++) a[i] = Qs[d * QK_PAD + ty * 4 + i];
#pragma unroll
            for (int j = 0; j < 4; j++) b[j] = Ks[d * QK_PAD + tx * 4 + j];
#pragma unroll
            for (int i = 0; i < 4; i++)
#pragma unroll
                for (int j = 0; j < 4; j++) sreg[i][j] += a[i] * b[j];
        }

        if (s0 + BN > q0) {   // diagonal tile: causal mask
#pragma unroll
            for (int i = 0; i < 4; i++) {
                int qi = q0 + ty * 4 + i;
#pragma unroll
                for (int j = 0; j < 4; j++)
                    if (s0 + tx * 4 + j > qi) sreg[i][j] = -1e30f;
            }
        }

        // online softmax per row (row group = 16 lanes sharing ty)
#pragma unroll
        for (int i = 0; i < 4; i++) {
            float mt = sreg[i][0];
#pragma unroll
            for (int j = 1; j < 4; j++) mt = fmaxf(mt, sreg[i][j]);
#pragma unroll
            for (int off = 8; off > 0; off >>= 1)
                mt = fmaxf(mt, __shfl_xor_sync(0xffffffffu, mt, off, 16));
            float mnew  = fmaxf(m[i], mt);
            float alpha = expf(m[i] - mnew);
            float lt = 0.f;
#pragma unroll
            for (int j = 0; j < 4; j++) {
                float p = expf(sreg[i][j] - mnew);
                sreg[i][j] = p;
                lt += p;
            }
#pragma unroll
            for (int off = 8; off > 0; off >>= 1)
                lt += __shfl_xor_sync(0xffffffffu, lt, off, 16);
            l[i] = l[i] * alpha + lt;
            m[i] = mnew;
#pragma unroll
            for (int c = 0; c < 8; c++) acc[i][c] *= alpha;
#pragma unroll
            for (int j = 0; j < 4; j++)
                Ps[(tx * 4 + j) * QK_PAD + ty * 4 + i] = sreg[i][j];
        }
        __syncthreads();

        // O += P @ V  (rows ty*4.., cols tx*8..)
        for (int j = 0; j < BN; j++) {
            float pv[4];
#pragma unroll
            for (int i = 0; i < 4; i++) pv[i] = Ps[j * QK_PAD + ty * 4 + i];
            const float4 v0 = *(const float4*)&Vs[j * D_V + tx * 8];
            const float4 v1 = *(const float4*)&Vs[j * D_V + tx * 8 + 4];
            float vv[8] = {v0.x, v0.y, v0.z, v0.w, v1.x, v1.y, v1.z, v1.w};
#pragma unroll
            for (int c = 0; c < 8; c++)
#pragma unroll
                for (int i = 0; i < 4; i++) acc[i][c] += pv[i] * vv[c];
        }
    }

#pragma unroll
    for (int i = 0; i < 4; i++) {
        int r = q0 + ty * 4 + i;
        float invl = 1.f / l[i];
#pragma unroll
        for (int c = 0; c < 8; c++)
            out[(size_t)r * (H_HEADS * D_V) + h * D_V + tx * 8 + c] = acc[i][c] * invl;
    }
}

// ---------------- launch ---------------------------------------------------
extern "C" void kernel_launch(void* const* d_in, const int* in_sizes, int n_in,
                              void* d_out, int out_size)
{
    const int*   positions = (const int*)d_in[0];
    const float* hidden    = (const float*)d_in[1];
    const float* Wq        = (const float*)d_in[2];
    const float* Wkva      = (const float*)d_in[3];
    const float* lnw       = (const float*)d_in[4];
    const float* Wkvb      = (const float*)d_in[5];
    const float* Wo        = (const float*)d_in[6];
    float* out = (float*)d_out;

    float *q, *latent, *kva, *kpe, *kv, *attn;
    cudaGetSymbolAddress((void**)&q,      g_q);
    cudaGetSymbolAddress((void**)&latent, g_latent);
    cudaGetSymbolAddress((void**)&kva,    g_kva);
    cudaGetSymbolAddress((void**)&kpe,    g_kpe);
    cudaGetSymbolAddress((void**)&kv,     g_kv);
    cudaGetSymbolAddress((void**)&attn,   g_attn);

    // 1. q = hidden @ Wq                    [4096,2048]x[2048,3072]
    sgemm_kernel<<<dim3(3072 / GBN, T_TOK / GBM), 256>>>(hidden, Wq, q, T_TOK, 3072, HID);
    // 2. latent = hidden @ Wkva             [4096,2048]x[2048,576]
    sgemm_kernel<<<dim3((576 + GBN - 1) / GBN, T_TOK / GBM), 256>>>(hidden, Wkva, latent, T_TOK, 576, HID);
    // 3. rmsnorm + k_pe rope
    rmsnorm_ropek_kernel<<<T_TOK, 256>>>(latent, lnw, positions, kva, kpe);
    // 4. q_pe rope (in place)
    rope_q_kernel<<<T_TOK, 512>>>(q, positions);
    // 5. kv = kv_a @ Wkvb                   [4096,512]x[512,4096]
    sgemm_kernel<<<dim3(4096 / GBN, T_TOK / GBM), 256>>>(kva, Wkvb, kv, T_TOK, 4096, L_KV);
    // 6. causal attention
    cudaFuncSetAttribute(attn_kernel, cudaFuncAttributeMaxDynamicSharedMemorySize, ATTN_SMEM);
    attn_kernel<<<dim3(T_TOK / BM, H_HEADS), 256, ATTN_SMEM>>>(q, kv, kpe, attn);
    // 7. out = attn @ Wo                    [4096,2048]x[2048,2048]
    sgemm_kernel<<<dim3(HID / GBN, T_TOK / GBM), 256>>>(attn, Wo, out, T_TOK, HID, 2048);
}

// round 3
// speedup vs baseline: 1.3965x; 1.3965x over previous
#include <cuda_runtime.h>
#include <cuda_bf16.h>
#include <math.h>

#define T_TOK   4096
#define HID     2048
#define H_HEADS 16
#define D_NOPE  128
#define D_ROPE  64
#define D_V     128
#define L_KV    512
#define D_QK    192   // D_NOPE + D_ROPE
#define KV_W    256   // D_NOPE + D_V per head in kv

// ---------------- scratch (device globals; no allocation allowed) ----------
__device__ float g_q[(size_t)T_TOK * H_HEADS * D_QK];          // 4096 x 3072
__device__ float g_latent[(size_t)T_TOK * (L_KV + D_ROPE)];    // 4096 x 576
__device__ float g_kva[(size_t)T_TOK * L_KV];                  // 4096 x 512
__device__ float g_kpe[(size_t)T_TOK * D_ROPE];                // 4096 x 64 (roped)
__device__ float g_kv[(size_t)T_TOK * H_HEADS * KV_W];         // 4096 x 4096
__device__ float g_attn[(size_t)T_TOK * H_HEADS * D_V];        // 4096 x 2048

// rope table
__device__ float g_cos[(size_t)T_TOK * 32];
__device__ float g_sin[(size_t)T_TOK * 32];

// bf16 hi/lo split buffers
__device__ __nv_bfloat16 g_hid_h [(size_t)T_TOK * HID];
__device__ __nv_bfloat16 g_hid_l [(size_t)T_TOK * HID];
__device__ __nv_bfloat16 g_Wq_h  [(size_t)HID * 3072];
__device__ __nv_bfloat16 g_Wq_l  [(size_t)HID * 3072];
__device__ __nv_bfloat16 g_Wkva_h[(size_t)HID * 576];
__device__ __nv_bfloat16 g_Wkva_l[(size_t)HID * 576];
__device__ __nv_bfloat16 g_kva_h [(size_t)T_TOK * L_KV];
__device__ __nv_bfloat16 g_kva_l [(size_t)T_TOK * L_KV];
__device__ __nv_bfloat16 g_Wkvb_h[(size_t)L_KV * 4096];
__device__ __nv_bfloat16 g_Wkvb_l[(size_t)L_KV * 4096];
__device__ __nv_bfloat16 g_attn_h[(size_t)T_TOK * 2048];
__device__ __nv_bfloat16 g_attn_l[(size_t)T_TOK * 2048];
__device__ __nv_bfloat16 g_Wo_h  [(size_t)2048 * 2048];
__device__ __nv_bfloat16 g_Wo_l  [(size_t)2048 * 2048];

static __device__ __forceinline__ unsigned smem_u32(const void* p) {
    return (unsigned)__cvta_generic_to_shared(p);
}

// ---------------- rope table (double math once) ----------------------------
__global__ __launch_bounds__(32) void rope_table_kernel(
    const int* __restrict__ positions, float* __restrict__ ct, float* __restrict__ st)
{
    int t = blockIdx.x, i = threadIdx.x;
    double pos  = (double)positions[t];
    double freq = pow(10000.0, -(double)i / 32.0);
    double ang  = pos * freq;
    ct[t * 32 + i] = (float)cos(ang);
    st[t * 32 + i] = (float)sin(ang);
}

// ---------------- fp32 -> bf16 hi/lo split ----------------------------------
__global__ __launch_bounds__(256) void split_kernel(
    const float* __restrict__ x, __nv_bfloat16* __restrict__ hi,
    __nv_bfloat16* __restrict__ lo, int n)
{
    int i = blockIdx.x * 256 + threadIdx.x;
    if (i < n) {
        float v = x[i];
        __nv_bfloat16 h = __float2bfloat16(v);
        hi[i] = h;
        lo[i] = __float2bfloat16(v - __bfloat162float(h));
    }
}

// ---------------- split-bf16 tensor-core GEMM -------------------------------
// C[M,N] = A[M,K] @ B[K,N], fp32 out. A,B given as bf16 hi/lo pairs.
// block 128x128x32, 256 threads (8 warps, warp tile 64x32).
#define XBM 128
#define XBN 128
#define XBK 32
#define SA  40    // A smem stride (bf16 elems): 80B, 16B-aligned rows
#define SB  136   // B smem stride: 272B

__global__ __launch_bounds__(256) void mma_gemm_kernel(
    const __nv_bfloat16* __restrict__ Ah, const __nv_bfloat16* __restrict__ Al,
    const __nv_bfloat16* __restrict__ Bh, const __nv_bfloat16* __restrict__ Bl,
    float* __restrict__ C, int M, int N, int K)
{
    __shared__ __nv_bfloat16 sAh[XBM * SA], sAl[XBM * SA];
    __shared__ __nv_bfloat16 sBh[XBK * SB], sBl[XBK * SB];

    const int tid  = threadIdx.x;
    const int lane = tid & 31, wid = tid >> 5;
    const int row0 = blockIdx.y * XBM;
    const int col0 = blockIdx.x * XBN;
    const int wm0  = (wid & 1) * 64;    // warp covers 64 rows
    const int wn0  = (wid >> 1) * 32;   // 32 cols
    const bool fullN = (col0 + XBN <= N);

    float acc[4][4][4];
#pragma unroll
    for (int a = 0; a < 4; a++)
#pragma unroll
        for (int b = 0; b < 4; b++)
#pragma unroll
            for (int c = 0; c < 4; c++) acc[a][b][c] = 0.f;

    for (int kb = 0; kb < K; kb += XBK) {
        // ---- load A tile: 128 x 32 bf16 (hi & lo), vectorized uint4 ----
#pragma unroll
        for (int j = 0; j < 2; j++) {
            int idx = tid + j * 256;           // 0..511
            int r = idx >> 2, c8 = idx & 3;    // 4 x (8 bf16) per row
            size_t g = (size_t)(row0 + r) * K + kb + c8 * 8;
            *(uint4*)&sAh[r * SA + c8 * 8] = *(const uint4*)&Ah[g];
            *(uint4*)&sAl[r * SA + c8 * 8] = *(const uint4*)&Al[g];
        }
        // ---- load B tile: 32 x 128 bf16 (hi & lo) ----
        if (fullN) {
#pragma unroll
            for (int j = 0; j < 2; j++) {
                int idx = tid + j * 256;          // 0..511
                int r = idx >> 4, c8 = idx & 15;  // 16 x (8 bf16) per row
                size_t g = (size_t)(kb + r) * N + col0 + c8 * 8;
                *(uint4*)&sBh[r * SB + c8 * 8] = *(const uint4*)&Bh[g];
                *(uint4*)&sBl[r * SB + c8 * 8] = *(const uint4*)&Bl[g];
            }
        } else {
            for (int idx = tid; idx < XBK * XBN; idx += 256) {
                int r = idx >> 7, c = idx & 127;
                int gc = col0 + c;
                __nv_bfloat16 vh = __float2bfloat16(0.f), vl = vh;
                if (gc < N) {
                    size_t g = (size_t)(kb + r) * N + gc;
                    vh = Bh[g]; vl = Bl[g];
                }
                sBh[r * SB + c] = vh;
                sBl[r * SB + c] = vl;
            }
        }
        __syncthreads();

#pragma unroll
        for (int ks = 0; ks < XBK; ks += 16) {
            // A fragments: 4 m-tiles x (hi,lo), ldmatrix.x4
            unsigned fah[4][4], fal[4][4];
            {
                int r = lane & 15, seg = lane >> 4;
#pragma unroll
                for (int mt = 0; mt < 4; mt++) {
                    unsigned ah = smem_u32(&sAh[(wm0 + mt * 16 + r) * SA + ks + seg * 8]);
                    unsigned al = smem_u32(&sAl[(wm0 + mt * 16 + r) * SA + ks + seg * 8]);
                    asm volatile("ldmatrix.sync.aligned.m8n8.x4.shared.b16 {%0,%1,%2,%3}, [%4];"
                        : "=r"(fah[mt][0]), "=r"(fah[mt][1]), "=r"(fah[mt][2]), "=r"(fah[mt][3]) : "r"(ah));
                    asm volatile("ldmatrix.sync.aligned.m8n8.x4.shared.b16 {%0,%1,%2,%3}, [%4];"
                        : "=r"(fal[mt][0]), "=r"(fal[mt][1]), "=r"(fal[mt][2]), "=r"(fal[mt][3]) : "r"(al));
                }
            }
            // B fragments: 4 n-tiles x (hi,lo), ldmatrix.x2.trans
            unsigned fbh[4][2], fbl[4][2];
            {
                int l = lane & 15;
#pragma unroll
                for (int nt = 0; nt < 4; nt++) {
                    unsigned bh = smem_u32(&sBh[(ks + l) * SB + wn0 + nt * 8]);
                    unsigned bl = smem_u32(&sBl[(ks + l) * SB + wn0 + nt * 8]);
                    asm volatile("ldmatrix.sync.aligned.m8n8.x2.trans.shared.b16 {%0,%1}, [%2];"
                        : "=r"(fbh[nt][0]), "=r"(fbh[nt][1]) : "r"(bh));
                    asm volatile("ldmatrix.sync.aligned.m8n8.x2.trans.shared.b16 {%0,%1}, [%2];"
                        : "=r"(fbl[nt][0]), "=r"(fbl[nt][1]) : "r"(bl));
                }
            }
#pragma unroll
            for (int mt = 0; mt < 4; mt++) {
#pragma unroll
                for (int nt = 0; nt < 4; nt++) {
                    float* d = acc[mt][nt];
#define MMA16816(Afrag, Bfrag)                                               \
    asm volatile(                                                            \
        "mma.sync.aligned.m16n8k16.row.col.f32.bf16.bf16.f32 "               \
        "{%0,%1,%2,%3}, {%4,%5,%6,%7}, {%8,%9}, {%0,%1,%2,%3};"              \
        : "+f"(d[0]), "+f"(d[1]), "+f"(d[2]), "+f"(d[3])                     \
        : "r"(Afrag[0]), "r"(Afrag[1]), "r"(Afrag[2]), "r"(Afrag[3]),        \
          "r"(Bfrag[0]), "r"(Bfrag[1]))
                    MMA16816(fah[mt], fbh[nt]);
                    MMA16816(fah[mt], fbl[nt]);
                    MMA16816(fal[mt], fbh[nt]);
#undef MMA16816
                }
            }
        }
        __syncthreads();
    }

    // ---- epilogue ----
#pragma unroll
    for (int mt = 0; mt < 4; mt++) {
        int gr = row0 + wm0 + mt * 16 + (lane >> 2);
#pragma unroll
        for (int nt = 0; nt < 4; nt++) {
            int gc = col0 + wn0 + nt * 8 + (lane & 3) * 2;
            if (gc < N) {
                *(float2*)&C[(size_t)gr * N + gc]       = make_float2(acc[mt][nt][0], acc[mt][nt][1]);
                *(float2*)&C[(size_t)(gr + 8) * N + gc] = make_float2(acc[mt][nt][2], acc[mt][nt][3]);
            }
        }
    }
}

// ---------------- rmsnorm on latent[:, :512] + RoPE on k_pe ----------------
__global__ __launch_bounds__(256) void rmsnorm_ropek_kernel(
    const float* __restrict__ latent, const float* __restrict__ w,
    const float* __restrict__ ct, const float* __restrict__ st,
    float* __restrict__ kva, float* __restrict__ kpe)
{
    int t = blockIdx.x;
    const float* x = latent + (size_t)t * (L_KV + D_ROPE);
    __shared__ float red[256];
    float ss = 0.f;
    for (int i = threadIdx.x; i < L_KV; i += 256) { float v = x[i]; ss += v * v; }
    red[threadIdx.x] = ss;
    __syncthreads();
    for (int s = 128; s > 0; s >>= 1) {
        if (threadIdx.x < s) red[threadIdx.x] += red[threadIdx.x + s];
        __syncthreads();
    }
    float inv = rsqrtf(red[0] / (float)L_KV + 1e-6f);
    for (int i = threadIdx.x; i < L_KV; i += 256)
        kva[(size_t)t * L_KV + i] = x[i] * inv * w[i];

    if (threadIdx.x < 32) {
        int i = threadIdx.x;
        float c = ct[t * 32 + i], s = st[t * 32 + i];
        float x1 = x[L_KV + i], x2 = x[L_KV + 32 + i];
        kpe[(size_t)t * D_ROPE + i]      = x1 * c - x2 * s;
        kpe[(size_t)t * D_ROPE + 32 + i] = x2 * c + x1 * s;
    }
}

// ---------------- RoPE on q_pe (in place on g_q) ---------------------------
__global__ __launch_bounds__(512) void rope_q_kernel(
    float* __restrict__ q, const float* __restrict__ ct, const float* __restrict__ st)
{
    int t = blockIdx.x;
    int h = threadIdx.x >> 5, i = threadIdx.x & 31;
    float c = ct[t * 32 + i], s = st[t * 32 + i];
    float* base = q + ((size_t)t * H_HEADS + h) * D_QK + D_NOPE;
    float x1 = base[i], x2 = base[32 + i];
    base[i]      = x1 * c - x2 * s;
    base[32 + i] = x2 * c + x1 * s;
}

// ---------------- causal flash attention (fp32) ----------------------------
#define BM 64
#define BN 64
#define QK_PAD 65
#define ATTN_SMEM ((D_QK * QK_PAD * 2 + BN * D_V + BN * QK_PAD) * 4)

__global__ __launch_bounds__(256, 1) void attn_kernel(
    const float* __restrict__ q, const float* __restrict__ kv,
    const float* __restrict__ kpe, float* __restrict__ out)
{
    extern __shared__ float sm[];
    float* Qs = sm;                        // [D_QK][65]
    float* Ks = Qs + D_QK * QK_PAD;        // [D_QK][65]
    float* Vs = Ks + D_QK * QK_PAD;        // [BN][D_V]
    float* Ps = Vs + BN * D_V;             // [BN][65] (transposed P)

    const int h  = blockIdx.y;
    const int q0 = blockIdx.x * BM;
    const int tid = threadIdx.x;
    const int tx = tid & 15, ty = tid >> 4;
    const float scale = 0.07216878364870323f;   // 1/sqrt(192)

    for (int idx = tid; idx < BM * D_QK; idx += 256) {
        int r = idx / D_QK, d = idx % D_QK;
        Qs[d * QK_PAD + r] = q[((size_t)(q0 + r) * H_HEADS + h) * D_QK + d] * scale;
    }

    float m[4], l[4], acc[4][8];
#pragma unroll
    for (int i = 0; i < 4; i++) {
        m[i] = -1e30f; l[i] = 0.f;
#pragma unroll
        for (int j = 0; j < 8; j++) acc[i][j] = 0.f;
    }

    const int s_end = q0 + BM;
    for (int s0 = 0; s0 < s_end; s0 += BN) {
        __syncthreads();
        for (int idx = tid; idx < BN * D_QK; idx += 256) {
            int r = idx / D_QK, d = idx % D_QK;
            float v = (d < D_NOPE)
                ? kv[((size_t)(s0 + r) * H_HEADS + h) * KV_W + d]
                : kpe[(size_t)(s0 + r) * D_ROPE + (d - D_NOPE)];
            Ks[d * QK_PAD + r] = v;
        }
        for (int idx = tid; idx < BN * D_V; idx += 256) {
            int r = idx >> 7, c = idx & 127;
            Vs[r * D_V + c] = kv[((size_t)(s0 + r) * H_HEADS + h) * KV_W + D_NOPE + c];
        }
        __syncthreads();

        float sreg[4][4];
#pragma unroll
        for (int i = 0; i < 4; i++)
#pragma unroll
            for (int j = 0; j < 4; j++) sreg[i][j] = 0.f;

        for (int d = 0; d < D_QK; d++) {
            float a[4], b[4];
#pragma unroll
            for (int i = 0; i < 4; i++) a[i] = Qs[d * QK_PAD + ty * 4 + i];
#pragma unroll
            for (int j = 0; j < 4; j++) b[j] = Ks[d * QK_PAD + tx * 4 + j];
#pragma unroll
            for (int i = 0; i < 4; i++)
#pragma unroll
                for (int j = 0; j < 4; j++) sreg[i][j] += a[i] * b[j];
        }

        if (s0 + BN > q0) {
#pragma unroll
            for (int i = 0; i < 4; i++) {
                int qi = q0 + ty * 4 + i;
#pragma unroll
                for (int j = 0; j < 4; j++)
                    if (s0 + tx * 4 + j > qi) sreg[i][j] = -1e30f;
            }
        }

#pragma unroll
        for (int i = 0; i < 4; i++) {
            float mt = sreg[i][0];
#pragma unroll
            for (int j = 1; j < 4; j++) mt = fmaxf(mt, sreg[i][j]);
#pragma unroll
            for (int off = 8; off > 0; off >>= 1)
                mt = fmaxf(mt, __shfl_xor_sync(0xffffffffu, mt, off, 16));
            float mnew  = fmaxf(m[i], mt);
            float alpha = expf(m[i] - mnew);
            float lt = 0.f;
#pragma unroll
            for (int j = 0; j < 4; j++) {
                float p = expf(sreg[i][j] - mnew);
                sreg[i][j] = p;
                lt += p;
            }
#pragma unroll
            for (int off = 8; off > 0; off >>= 1)
                lt += __shfl_xor_sync(0xffffffffu, lt, off, 16);
            l[i] = l[i] * alpha + lt;
            m[i] = mnew;
#pragma unroll
            for (int c = 0; c < 8; c++) acc[i][c] *= alpha;
#pragma unroll
            for (int j = 0; j < 4; j++)
                Ps[(tx * 4 + j) * QK_PAD + ty * 4 + i] = sreg[i][j];
        }
        __syncthreads();

        for (int j = 0; j < BN; j++) {
            float pv[4];
#pragma unroll
            for (int i = 0; i < 4; i++) pv[i] = Ps[j * QK_PAD + ty * 4 + i];
            const float4 v0 = *(const float4*)&Vs[j * D_V + tx * 8];
            const float4 v1 = *(const float4*)&Vs[j * D_V + tx * 8 + 4];
            float vv[8] = {v0.x, v0.y, v0.z, v0.w, v1.x, v1.y, v1.z, v1.w};
#pragma unroll
            for (int c = 0; c < 8; c++)
#pragma unroll
                for (int i = 0; i < 4; i++) acc[i][c] += pv[i] * vv[c];
        }
    }

#pragma unroll
    for (int i = 0; i < 4; i++) {
        int r = q0 + ty * 4 + i;
        float invl = 1.f / l[i];
#pragma unroll
        for (int c = 0; c < 8; c++)
            out[(size_t)r * (H_HEADS * D_V) + h * D_V + tx * 8 + c] = acc[i][c] * invl;
    }
}

// ---------------- launch ---------------------------------------------------
static inline void split(const float* x, __nv_bfloat16* h, __nv_bfloat16* l, int n) {
    split_kernel<<<(n + 255) / 256, 256>>>(x, h, l, n);
}

extern "C" void kernel_launch(void* const* d_in, const int* in_sizes, int n_in,
                              void* d_out, int out_size)
{
    const int*   positions = (const int*)d_in[0];
    const float* hidden    = (const float*)d_in[1];
    const float* Wq        = (const float*)d_in[2];
    const float* Wkva      = (const float*)d_in[3];
    const float* lnw       = (const float*)d_in[4];
    const float* Wkvb      = (const float*)d_in[5];
    const float* Wo        = (const float*)d_in[6];
    float* out = (float*)d_out;

    float *q, *latent, *kva, *kpe, *kv, *attn, *tcos, *tsin;
    cudaGetSymbolAddress((void**)&q,      g_q);
    cudaGetSymbolAddress((void**)&latent, g_latent);
    cudaGetSymbolAddress((void**)&kva,    g_kva);
    cudaGetSymbolAddress((void**)&kpe,    g_kpe);
    cudaGetSymbolAddress((void**)&kv,     g_kv);
    cudaGetSymbolAddress((void**)&attn,   g_attn);
    cudaGetSymbolAddress((void**)&tcos,   g_cos);
    cudaGetSymbolAddress((void**)&tsin,   g_sin);

    __nv_bfloat16 *hid_h, *hid_l, *Wq_h, *Wq_l, *Wkva_h, *Wkva_l;
    __nv_bfloat16 *kva_h, *kva_l, *Wkvb_h, *Wkvb_l, *attn_h, *attn_l, *Wo_h, *Wo_l;
    cudaGetSymbolAddress((void**)&hid_h,  g_hid_h);
    cudaGetSymbolAddress((void**)&hid_l,  g_hid_l);
    cudaGetSymbolAddress((void**)&Wq_h,   g_Wq_h);
    cudaGetSymbolAddress((void**)&Wq_l,   g_Wq_l);
    cudaGetSymbolAddress((void**)&Wkva_h, g_Wkva_h);
    cudaGetSymbolAddress((void**)&Wkva_l, g_Wkva_l);
    cudaGetSymbolAddress((void**)&kva_h,  g_kva_h);
    cudaGetSymbolAddress((void**)&kva_l,  g_kva_l);
    cudaGetSymbolAddress((void**)&Wkvb_h, g_Wkvb_h);
    cudaGetSymbolAddress((void**)&Wkvb_l, g_Wkvb_l);
    cudaGetSymbolAddress((void**)&attn_h, g_attn_h);
    cudaGetSymbolAddress((void**)&attn_l, g_attn_l);
    cudaGetSymbolAddress((void**)&Wo_h,   g_Wo_h);
    cudaGetSymbolAddress((void**)&Wo_l,   g_Wo_l);

    // rope table
    rope_table_kernel<<<T_TOK, 32>>>(positions, tcos, tsin);

    // splits for GEMM 1 & 2
    split(hidden, hid_h, hid_l, T_TOK * HID);
    split(Wq,     Wq_h,  Wq_l,  HID * 3072);
    split(Wkva,   Wkva_h, Wkva_l, HID * 576);

    // 1. q = hidden @ Wq
    mma_gemm_kernel<<<dim3(3072 / XBN, T_TOK / XBM), 256>>>(
        hid_h, hid_l, Wq_h, Wq_l, q, T_TOK, 3072, HID);
    // 2. latent = hidden @ Wkva
    mma_gemm_kernel<<<dim3((576 + XBN - 1) / XBN, T_TOK / XBM), 256>>>(
        hid_h, hid_l, Wkva_h, Wkva_l, latent, T_TOK, 576, HID);
    // 3. rmsnorm + k_pe rope
    rmsnorm_ropek_kernel<<<T_TOK, 256>>>(latent, lnw, tcos, tsin, kva, kpe);
    // 4. q_pe rope
    rope_q_kernel<<<T_TOK, 512>>>(q, tcos, tsin);
    // 5. kv = kv_a @ Wkvb
    split(kva,  kva_h,  kva_l,  T_TOK * L_KV);
    split(Wkvb, Wkvb_h, Wkvb_l, L_KV * 4096);
    mma_gemm_kernel<<<dim3(4096 / XBN, T_TOK / XBM), 256>>>(
        kva_h, kva_l, Wkvb_h, Wkvb_l, kv, T_TOK, 4096, L_KV);
    // 6. causal attention
    cudaFuncSetAttribute(attn_kernel, cudaFuncAttributeMaxDynamicSharedMemorySize, ATTN_SMEM);
    attn_kernel<<<dim3(T_TOK / BM, H_HEADS), 256, ATTN_SMEM>>>(q, kv, kpe, attn);
    // 7. out = attn @ Wo
    split(attn, attn_h, attn_l, T_TOK * 2048);
    split(Wo,   Wo_h,   Wo_l,   2048 * 2048);
    mma_gemm_kernel<<<dim3(2048 / XBN, T_TOK / XBM), 256>>>(
        attn_h, attn_l, Wo_h, Wo_l, out, T_TOK, 2048, 2048);
}

// round 5
// speedup vs baseline: 4.4512x; 3.1873x over previous
#include <cuda_runtime.h>
#include <cuda_bf16.h>
#include <cuda_fp16.h>
#include <math.h>

#define T_TOK   4096
#define HID     2048
#define H_HEADS 16
#define D_NOPE  128
#define D_ROPE  64
#define D_V     128
#define L_KV    512
#define D_QK    192
#define KV_W    256

// ---------------- scratch (device globals) ---------------------------------
__device__ float g_q[(size_t)T_TOK * H_HEADS * D_QK];
__device__ float g_latent[(size_t)T_TOK * (L_KV + D_ROPE)];
__device__ float g_kva[(size_t)T_TOK * L_KV];
__device__ float g_kpe[(size_t)T_TOK * D_ROPE];
__device__ float g_kv[(size_t)T_TOK * H_HEADS * KV_W];
__device__ float g_attn[(size_t)T_TOK * H_HEADS * D_V];

__device__ float g_cos[(size_t)T_TOK * 32];
__device__ float g_sin[(size_t)T_TOK * 32];

// bf16 hi/lo split buffers (GEMMs)
__device__ __nv_bfloat16 g_hid_h [(size_t)T_TOK * HID];
__device__ __nv_bfloat16 g_hid_l [(size_t)T_TOK * HID];
__device__ __nv_bfloat16 g_Wq_h  [(size_t)HID * 3072];
__device__ __nv_bfloat16 g_Wq_l  [(size_t)HID * 3072];
__device__ __nv_bfloat16 g_Wkva_h[(size_t)HID * 576];
__device__ __nv_bfloat16 g_Wkva_l[(size_t)HID * 576];
__device__ __nv_bfloat16 g_kva_h [(size_t)T_TOK * L_KV];
__device__ __nv_bfloat16 g_kva_l [(size_t)T_TOK * L_KV];
__device__ __nv_bfloat16 g_Wkvb_h[(size_t)L_KV * 4096];
__device__ __nv_bfloat16 g_Wkvb_l[(size_t)L_KV * 4096];
__device__ __nv_bfloat16 g_attn_h[(size_t)T_TOK * 2048];
__device__ __nv_bfloat16 g_attn_l[(size_t)T_TOK * 2048];
__device__ __nv_bfloat16 g_Wo_h  [(size_t)2048 * 2048];
__device__ __nv_bfloat16 g_Wo_l  [(size_t)2048 * 2048];

// attention operand buffers
__device__ __nv_bfloat16 g_qah[(size_t)T_TOK * H_HEADS * D_QK];
__device__ __nv_bfloat16 g_qal[(size_t)T_TOK * H_HEADS * D_QK];
__device__ __nv_bfloat16 g_kah[(size_t)T_TOK * H_HEADS * D_QK];
__device__ __nv_bfloat16 g_kal[(size_t)T_TOK * H_HEADS * D_QK];
__device__ __half        g_vaf[(size_t)T_TOK * H_HEADS * D_V];

static __device__ __forceinline__ unsigned smem_u32(const void* p) {
    return (unsigned)__cvta_generic_to_shared(p);
}
static __device__ __forceinline__ void cp_async16(void* dst, const void* src) {
    asm volatile("cp.async.cg.shared.global [%0], [%1], 16;\n"
                 :: "r"(smem_u32(dst)), "l"(src));
}
static __device__ __forceinline__ void cp_commit() {
    asm volatile("cp.async.commit_group;\n");
}
static __device__ __forceinline__ unsigned pack_h2(float a, float b) {
    __half2 h = __floats2half2_rn(a, b);
    return *(unsigned*)&h;
}
static __device__ __forceinline__ float ex2f(float x) {   // MUFU EX2 (2^x)
    float r;
    asm("ex2.approx.ftz.f32 %0, %1;" : "=f"(r) : "f"(x));
    return r;
}

#define MMA_BF16(D, A, B)                                                    \
    asm volatile(                                                            \
        "mma.sync.aligned.m16n8k16.row.col.f32.bf16.bf16.f32 "               \
        "{%0,%1,%2,%3}, {%4,%5,%6,%7}, {%8,%9}, {%0,%1,%2,%3};"              \
        : "+f"(D[0]), "+f"(D[1]), "+f"(D[2]), "+f"(D[3])                     \
        : "r"(A[0]), "r"(A[1]), "r"(A[2]), "r"(A[3]), "r"(B[0]), "r"(B[1]))
#define MMA_F16(D, A, B)                                                     \
    asm volatile(                                                            \
        "mma.sync.aligned.m16n8k16.row.col.f32.f16.f16.f32 "                 \
        "{%0,%1,%2,%3}, {%4,%5,%6,%7}, {%8,%9}, {%0,%1,%2,%3};"              \
        : "+f"(D[0]), "+f"(D[1]), "+f"(D[2]), "+f"(D[3])                     \
        : "r"(A[0]), "r"(A[1]), "r"(A[2]), "r"(A[3]), "r"(B[0]), "r"(B[1]))

// ---------------- rope table ------------------------------------------------
__global__ __launch_bounds__(32) void rope_table_kernel(
    const int* __restrict__ positions, float* __restrict__ ct, float* __restrict__ st)
{
    int t = blockIdx.x, i = threadIdx.x;
    double pos  = (double)positions[t];
    double freq = pow(10000.0, -(double)i / 32.0);
    double ang  = pos * freq;
    ct[t * 32 + i] = (float)cos(ang);
    st[t * 32 + i] = (float)sin(ang);
}

// ---------------- fp32 -> bf16 hi/lo split ----------------------------------
__global__ __launch_bounds__(256) void split_kernel(
    const float* __restrict__ x, __nv_bfloat16* __restrict__ hi,
    __nv_bfloat16* __restrict__ lo, int n)
{
    int i = blockIdx.x * 256 + threadIdx.x;
    if (i < n) {
        float v = x[i];
        __nv_bfloat16 h = __float2bfloat16(v);
        hi[i] = h;
        lo[i] = __float2bfloat16(v - __bfloat162float(h));
    }
}

// ---------------- split-bf16 tensor-core GEMM (as R3) -----------------------
#define XBM 128
#define XBN 128
#define XBK 32
#define SA  40
#define SB  136

__global__ __launch_bounds__(256) void mma_gemm_kernel(
    const __nv_bfloat16* __restrict__ Ah, const __nv_bfloat16* __restrict__ Al,
    const __nv_bfloat16* __restrict__ Bh, const __nv_bfloat16* __restrict__ Bl,
    float* __restrict__ C, int M, int N, int K)
{
    __shared__ __nv_bfloat16 sAh[XBM * SA], sAl[XBM * SA];
    __shared__ __nv_bfloat16 sBh[XBK * SB], sBl[XBK * SB];

    const int tid  = threadIdx.x;
    const int lane = tid & 31, wid = tid >> 5;
    const int row0 = blockIdx.y * XBM;
    const int col0 = blockIdx.x * XBN;
    const int wm0  = (wid & 1) * 64;
    const int wn0  = (wid >> 1) * 32;
    const bool fullN = (col0 + XBN <= N);

    float acc[4][4][4];
#pragma unroll
    for (int a = 0; a < 4; a++)
#pragma unroll
        for (int b = 0; b < 4; b++)
#pragma unroll
            for (int c = 0; c < 4; c++) acc[a][b][c] = 0.f;

    for (int kb = 0; kb < K; kb += XBK) {
#pragma unroll
        for (int j = 0; j < 2; j++) {
            int idx = tid + j * 256;
            int r = idx >> 2, c8 = idx & 3;
            size_t g = (size_t)(row0 + r) * K + kb + c8 * 8;
            *(uint4*)&sAh[r * SA + c8 * 8] = *(const uint4*)&Ah[g];
            *(uint4*)&sAl[r * SA + c8 * 8] = *(const uint4*)&Al[g];
        }
        if (fullN) {
#pragma unroll
            for (int j = 0; j < 2; j++) {
                int idx = tid + j * 256;
                int r = idx >> 4, c8 = idx & 15;
                size_t g = (size_t)(kb + r) * N + col0 + c8 * 8;
                *(uint4*)&sBh[r * SB + c8 * 8] = *(const uint4*)&Bh[g];
                *(uint4*)&sBl[r * SB + c8 * 8] = *(const uint4*)&Bl[g];
            }
        } else {
            for (int idx = tid; idx < XBK * XBN; idx += 256) {
                int r = idx >> 7, c = idx & 127;
                int gc = col0 + c;
                __nv_bfloat16 vh = __float2bfloat16(0.f), vl = vh;
                if (gc < N) {
                    size_t g = (size_t)(kb + r) * N + gc;
                    vh = Bh[g]; vl = Bl[g];
                }
                sBh[r * SB + c] = vh;
                sBl[r * SB + c] = vl;
            }
        }
        __syncthreads();

#pragma unroll
        for (int ks = 0; ks < XBK; ks += 16) {
            unsigned fah[4][4], fal[4][4];
            {
                int r = lane & 15, seg = lane >> 4;
#pragma unroll
                for (int mt = 0; mt < 4; mt++) {
                    unsigned ah = smem_u32(&sAh[(wm0 + mt * 16 + r) * SA + ks + seg * 8]);
                    unsigned al = smem_u32(&sAl[(wm0 + mt * 16 + r) * SA + ks + seg * 8]);
                    asm volatile("ldmatrix.sync.aligned.m8n8.x4.shared.b16 {%0,%1,%2,%3}, [%4];"
                        : "=r"(fah[mt][0]), "=r"(fah[mt][1]), "=r"(fah[mt][2]), "=r"(fah[mt][3]) : "r"(ah));
                    asm volatile("ldmatrix.sync.aligned.m8n8.x4.shared.b16 {%0,%1,%2,%3}, [%4];"
                        : "=r"(fal[mt][0]), "=r"(fal[mt][1]), "=r"(fal[mt][2]), "=r"(fal[mt][3]) : "r"(al));
                }
            }
            unsigned fbh[4][2], fbl[4][2];
            {
                int l = lane & 15;
#pragma unroll
                for (int nt = 0; nt < 4; nt++) {
                    unsigned bh = smem_u32(&sBh[(ks + l) * SB + wn0 + nt * 8]);
                    unsigned bl = smem_u32(&sBl[(ks + l) * SB + wn0 + nt * 8]);
                    asm volatile("ldmatrix.sync.aligned.m8n8.x2.trans.shared.b16 {%0,%1}, [%2];"
                        : "=r"(fbh[nt][0]), "=r"(fbh[nt][1]) : "r"(bh));
                    asm volatile("ldmatrix.sync.aligned.m8n8.x2.trans.shared.b16 {%0,%1}, [%2];"
                        : "=r"(fbl[nt][0]), "=r"(fbl[nt][1]) : "r"(bl));
                }
            }
#pragma unroll
            for (int mt = 0; mt < 4; mt++) {
#pragma unroll
                for (int nt = 0; nt < 4; nt++) {
                    float* d = acc[mt][nt];
                    MMA_BF16(d, fah[mt], fbh[nt]);
                    MMA_BF16(d, fah[mt], fbl[nt]);
                    MMA_BF16(d, fal[mt], fbh[nt]);
                }
            }
        }
        __syncthreads();
    }

#pragma unroll
    for (int mt = 0; mt < 4; mt++) {
        int gr = row0 + wm0 + mt * 16 + (lane >> 2);
#pragma unroll
        for (int nt = 0; nt < 4; nt++) {
            int gc = col0 + wn0 + nt * 8 + (lane & 3) * 2;
            if (gc < N) {
                *(float2*)&C[(size_t)gr * N + gc]       = make_float2(acc[mt][nt][0], acc[mt][nt][1]);
                *(float2*)&C[(size_t)(gr + 8) * N + gc] = make_float2(acc[mt][nt][2], acc[mt][nt][3]);
            }
        }
    }
}

// ---------------- rmsnorm + k_pe rope ---------------------------------------
__global__ __launch_bounds__(256) void rmsnorm_ropek_kernel(
    const float* __restrict__ latent, const float* __restrict__ w,
    const float* __restrict__ ct, const float* __restrict__ st,
    float* __restrict__ kva, float* __restrict__ kpe)
{
    int t = blockIdx.x;
    const float* x = latent + (size_t)t * (L_KV + D_ROPE);
    __shared__ float red[256];
    float ss = 0.f;
    for (int i = threadIdx.x; i < L_KV; i += 256) { float v = x[i]; ss += v * v; }
    red[threadIdx.x] = ss;
    __syncthreads();
    for (int s = 128; s > 0; s >>= 1) {
        if (threadIdx.x < s) red[threadIdx.x] += red[threadIdx.x + s];
        __syncthreads();
    }
    float inv = rsqrtf(red[0] / (float)L_KV + 1e-6f);
    for (int i = threadIdx.x; i < L_KV; i += 256)
        kva[(size_t)t * L_KV + i] = x[i] * inv * w[i];

    if (threadIdx.x < 32) {
        int i = threadIdx.x;
        float c = ct[t * 32 + i], s = st[t * 32 + i];
        float x1 = x[L_KV + i], x2 = x[L_KV + 32 + i];
        kpe[(size_t)t * D_ROPE + i]      = x1 * c - x2 * s;
        kpe[(size_t)t * D_ROPE + 32 + i] = x2 * c + x1 * s;
    }
}

// ---------------- q prep: rope + scale + bf16 split -------------------------
__global__ __launch_bounds__(256) void qprep_kernel(
    const float* __restrict__ q, const float* __restrict__ ct, const float* __restrict__ st,
    __nv_bfloat16* __restrict__ qh, __nv_bfloat16* __restrict__ ql)
{
    int t = blockIdx.x;
    const float SC = 0.07216878364870323f * 1.4426950408889634f; // 1/sqrt(192)*log2e
    for (int idx = threadIdx.x; idx < H_HEADS * D_QK; idx += 256) {
        int c = idx % D_QK;
        const float* qr = q + (size_t)t * 3072 + (idx - c);
        float v;
        if (c < D_NOPE) v = qr[c];
        else {
            int i = c - D_NOPE;
            if (i < 32) v = qr[c] * ct[t * 32 + i] - qr[c + 32] * st[t * 32 + i];
            else { int j = i - 32; v = qr[c] * ct[t * 32 + j] + qr[c - 32] * st[t * 32 + j]; }
        }
        v *= SC;
        __nv_bfloat16 hv = __float2bfloat16(v);
        qh[(size_t)t * 3072 + idx] = hv;
        ql[(size_t)t * 3072 + idx] = __float2bfloat16(v - __bfloat162float(hv));
    }
}

// ---------------- k/v prep: per-head K(hi/lo) + V fp16 ----------------------
__global__ __launch_bounds__(256) void kprep_kernel(
    const float* __restrict__ kv, const float* __restrict__ kpe,
    __nv_bfloat16* __restrict__ kh, __nv_bfloat16* __restrict__ kl,
    __half* __restrict__ vf)
{
    int t = blockIdx.x;
    for (int idx = threadIdx.x; idx < H_HEADS * D_QK; idx += 256) {
        int hh = idx / D_QK, c = idx % D_QK;
        float v = (c < D_NOPE) ? kv[((size_t)t * H_HEADS + hh) * KV_W + c]
                               : kpe[(size_t)t * D_ROPE + (c - D_NOPE)];
        __nv_bfloat16 hv = __float2bfloat16(v);
        kh[(size_t)t * 3072 + idx] = hv;
        kl[(size_t)t * 3072 + idx] = __float2bfloat16(v - __bfloat162float(hv));
    }
    for (int idx = threadIdx.x; idx < H_HEADS * D_V; idx += 256) {
        int hh = idx / D_V, d = idx % D_V;
        vf[(size_t)t * 2048 + idx] =
            __float2half(kv[((size_t)t * H_HEADS + hh) * KV_W + D_NOPE + d]);
    }
}

// ---------------- tensor-core causal flash attention ------------------------
// BM=128 q rows, BN=64 kv cols, 256 threads (8 warps x 16 rows).
// smem: Qh(49152) Ql(49152) + 2 stages of [Kh 24576 | Kl 24576 | V 16384]
#define ATT_SMEM (98304 + 2 * 65536)

__global__ __launch_bounds__(256, 1) void attn_mma_kernel(
    const __nv_bfloat16* __restrict__ qh, const __nv_bfloat16* __restrict__ ql,
    const __nv_bfloat16* __restrict__ kh, const __nv_bfloat16* __restrict__ kl,
    const __half* __restrict__ vf, float* __restrict__ out)
{
    extern __shared__ char smr[];
    char* sQh = smr;
    char* sQl = smr + 49152;

    const int tid = threadIdx.x, lane = tid & 31, w = tid >> 5;
    const int b  = gridDim.x - 1 - blockIdx.x;   // heavy blocks first
    const int q0 = b * 128;
    const int h  = blockIdx.y;
    const int niter = (q0 + 128) >> 6;

    // Q tile load: 128 rows x 24 chunks (hi & lo)
    for (int idx = tid; idx < 128 * 24; idx += 256) {
        int r = idx / 24, c = idx % 24;
        int sw = ((c ^ (r & 7)) << 4);
        size_t g = ((size_t)(q0 + r) * H_HEADS + h) * D_QK + c * 8;
        cp_async16(sQh + r * 384 + sw, qh + g);
        cp_async16(sQl + r * 384 + sw, ql + g);
    }

    auto load_stage = [&](int st, int s0) {
        char* base = smr + 98304 + st * 65536;
        char* sKh = base, *sKl = base + 24576, *sV = base + 49152;
        for (int idx = tid; idx < 64 * 24; idx += 256) {
            int r = idx / 24, c = idx % 24;
            int sw = ((c ^ (r & 7)) << 4);
            size_t g = ((size_t)(s0 + r) * H_HEADS + h) * D_QK + c * 8;
            cp_async16(sKh + r * 384 + sw, kh + g);
            cp_async16(sKl + r * 384 + sw, kl + g);
        }
        for (int idx = tid; idx < 64 * 16; idx += 256) {
            int r = idx / 16, c = idx % 16;
            int sw = ((c ^ (r & 7)) << 4);
            cp_async16(sV + r * 256 + sw,
                       vf + ((size_t)(s0 + r) * H_HEADS + h) * D_V + c * 8);
        }
    };

    load_stage(0, 0);
    cp_commit();

    float m0 = -1e30f, m1 = -1e30f, l0 = 0.f, l1 = 0.f;
    float oacc[16][4];
#pragma unroll
    for (int i = 0; i < 16; i++)
#pragma unroll
        for (int j = 0; j < 4; j++) oacc[i][j] = 0.f;

    for (int it = 0; it < niter; it++) {
        const int s0 = it * 64;
        if (it + 1 < niter) { load_stage((it + 1) & 1, s0 + 64); cp_commit(); }
        if (it + 1 < niter) asm volatile("cp.async.wait_group 1;\n");
        else                asm volatile("cp.async.wait_group 0;\n");
        __syncthreads();

        char* base = smr + 98304 + (it & 1) * 65536;
        char* sKh = base, *sKl = base + 24576, *sV = base + 49152;

        // ---- S = Q K^T (split bf16, 3 mma) ----
        float sacc[8][4];
#pragma unroll
        for (int i = 0; i < 8; i++)
#pragma unroll
            for (int j = 0; j < 4; j++) sacc[i][j] = 0.f;

#pragma unroll
        for (int kk = 0; kk < 12; kk++) {
            unsigned ah[4], al[4];
            {
                int r = 16 * w + (lane & 15);
                int cc = 2 * kk + (lane >> 4);
                unsigned qa = smem_u32(sQh + r * 384 + (((cc ^ (r & 7)) << 4)));
                unsigned qb = smem_u32(sQl + r * 384 + (((cc ^ (r & 7)) << 4)));
                asm volatile("ldmatrix.sync.aligned.m8n8.x4.shared.b16 {%0,%1,%2,%3}, [%4];"
                    : "=r"(ah[0]), "=r"(ah[1]), "=r"(ah[2]), "=r"(ah[3]) : "r"(qa));
                asm volatile("ldmatrix.sync.aligned.m8n8.x4.shared.b16 {%0,%1,%2,%3}, [%4];"
                    : "=r"(al[0]), "=r"(al[1]), "=r"(al[2]), "=r"(al[3]) : "r"(qb));
            }
#pragma unroll
            for (int nt = 0; nt < 8; nt++) {
                unsigned bh[2], bl[2];
                int rK = nt * 8 + (lane & 7);
                int cc = 2 * kk + ((lane & 15) >> 3);
                unsigned ka = smem_u32(sKh + rK * 384 + (((cc ^ (rK & 7)) << 4)));
                unsigned kb = smem_u32(sKl + rK * 384 + (((cc ^ (rK & 7)) << 4)));
                asm volatile("ldmatrix.sync.aligned.m8n8.x2.shared.b16 {%0,%1}, [%2];"
                    : "=r"(bh[0]), "=r"(bh[1]) : "r"(ka));
                asm volatile("ldmatrix.sync.aligned.m8n8.x2.shared.b16 {%0,%1}, [%2];"
                    : "=r"(bl[0]), "=r"(bl[1]) : "r"(kb));
                float* d = sacc[nt];
                MMA_BF16(d, ah, bh);
                MMA_BF16(d, ah, bl);
                MMA_BF16(d, al, bh);
            }
        }

        // ---- causal mask (last two tiles only) ----
        if (s0 + 64 > q0) {
            int row0 = q0 + 16 * w + (lane >> 2);
#pragma unroll
            for (int nt = 0; nt < 8; nt++) {
                int c = s0 + nt * 8 + (lane & 3) * 2;
                if (c     > row0)     sacc[nt][0] = -1e30f;
                if (c + 1 > row0)     sacc[nt][1] = -1e30f;
                if (c     > row0 + 8) sacc[nt][2] = -1e30f;
                if (c + 1 > row0 + 8) sacc[nt][3] = -1e30f;
            }
        }

        // ---- online softmax (exp2 domain) ----
        float mx0 = -1e30f, mx1 = -1e30f;
#pragma unroll
        for (int nt = 0; nt < 8; nt++) {
            mx0 = fmaxf(mx0, fmaxf(sacc[nt][0], sacc[nt][1]));
            mx1 = fmaxf(mx1, fmaxf(sacc[nt][2], sacc[nt][3]));
        }
        mx0 = fmaxf(mx0, __shfl_xor_sync(0xffffffffu, mx0, 1));
        mx0 = fmaxf(mx0, __shfl_xor_sync(0xffffffffu, mx0, 2));
        mx1 = fmaxf(mx1, __shfl_xor_sync(0xffffffffu, mx1, 1));
        mx1 = fmaxf(mx1, __shfl_xor_sync(0xffffffffu, mx1, 2));
        float mn0 = fmaxf(m0, mx0), mn1 = fmaxf(m1, mx1);
        float a0 = ex2f(m0 - mn0), a1 = ex2f(m1 - mn1);
        m0 = mn0; m1 = mn1;
        float ps0 = 0.f, ps1 = 0.f;
#pragma unroll
        for (int nt = 0; nt < 8; nt++) {
            float p0 = ex2f(sacc[nt][0] - mn0);
            float p1 = ex2f(sacc[nt][1] - mn0);
            float p2 = ex2f(sacc[nt][2] - mn1);
            float p3 = ex2f(sacc[nt][3] - mn1);
            sacc[nt][0] = p0; sacc[nt][1] = p1; sacc[nt][2] = p2; sacc[nt][3] = p3;
            ps0 += p0 + p1; ps1 += p2 + p3;
        }
        ps0 += __shfl_xor_sync(0xffffffffu, ps0, 1);
        ps0 += __shfl_xor_sync(0xffffffffu, ps0, 2);
        ps1 += __shfl_xor_sync(0xffffffffu, ps1, 1);
        ps1 += __shfl_xor_sync(0xffffffffu, ps1, 2);
        l0 = l0 * a0 + ps0;
        l1 = l1 * a1 + ps1;
#pragma unroll
        for (int nd = 0; nd < 16; nd++) {
            oacc[nd][0] *= a0; oacc[nd][1] *= a0;
            oacc[nd][2] *= a1; oacc[nd][3] *= a1;
        }

        // ---- P fragments (fp16) ----
        unsigned pa[4][4];
#pragma unroll
        for (int k2 = 0; k2 < 4; k2++) {
            pa[k2][0] = pack_h2(sacc[2 * k2][0],     sacc[2 * k2][1]);
            pa[k2][1] = pack_h2(sacc[2 * k2][2],     sacc[2 * k2][3]);
            pa[k2][2] = pack_h2(sacc[2 * k2 + 1][0], sacc[2 * k2 + 1][1]);
            pa[k2][3] = pack_h2(sacc[2 * k2 + 1][2], sacc[2 * k2 + 1][3]);
        }

        // ---- O += P V ----
#pragma unroll
        for (int k2 = 0; k2 < 4; k2++) {
            int rV = k2 * 16 + (lane & 15);
#pragma unroll
            for (int nd = 0; nd < 16; nd++) {
                unsigned vb[2];
                unsigned va = smem_u32(sV + rV * 256 + (((nd ^ (rV & 7)) << 4)));
                asm volatile("ldmatrix.sync.aligned.m8n8.x2.trans.shared.b16 {%0,%1}, [%2];"
                    : "=r"(vb[0]), "=r"(vb[1]) : "r"(va));
                float* d = oacc[nd];
                MMA_F16(d, pa[k2], vb);
            }
        }
        __syncthreads();
    }

    // ---- epilogue ----
    float il0 = 1.f / l0, il1 = 1.f / l1;
    int r0 = q0 + 16 * w + (lane >> 2);
    int cb = h * D_V + (lane & 3) * 2;
#pragma unroll
    for (int nd = 0; nd < 16; nd++) {
        *(float2*)&out[(size_t)r0 * 2048 + cb + nd * 8] =
            make_float2(oacc[nd][0] * il0, oacc[nd][1] * il0);
        *(float2*)&out[(size_t)(r0 + 8) * 2048 + cb + nd * 8] =
            make_float2(oacc[nd][2] * il1, oacc[nd][3] * il1);
    }
}

// ---------------- launch ---------------------------------------------------
static inline void split(const float* x, __nv_bfloat16* h, __nv_bfloat16* l, int n) {
    split_kernel<<<(n + 255) / 256, 256>>>(x, h, l, n);
}

extern "C" void kernel_launch(void* const* d_in, const int* in_sizes, int n_in,
                              void* d_out, int out_size)
{
    const int*   positions = (const int*)d_in[0];
    const float* hidden    = (const float*)d_in[1];
    const float* Wq        = (const float*)d_in[2];
    const float* Wkva      = (const float*)d_in[3];
    const float* lnw       = (const float*)d_in[4];
    const float* Wkvb      = (const float*)d_in[5];
    const float* Wo        = (const float*)d_in[6];
    float* out = (float*)d_out;

    float *q, *latent, *kva, *kpe, *kv, *attn, *tcos, *tsin;
    cudaGetSymbolAddress((void**)&q,      g_q);
    cudaGetSymbolAddress((void**)&latent, g_latent);
    cudaGetSymbolAddress((void**)&kva,    g_kva);
    cudaGetSymbolAddress((void**)&kpe,    g_kpe);
    cudaGetSymbolAddress((void**)&kv,     g_kv);
    cudaGetSymbolAddress((void**)&attn,   g_attn);
    cudaGetSymbolAddress((void**)&tcos,   g_cos);
    cudaGetSymbolAddress((void**)&tsin,   g_sin);

    __nv_bfloat16 *hid_h, *hid_l, *Wq_h, *Wq_l, *Wkva_h, *Wkva_l;
    __nv_bfloat16 *kva_h, *kva_l, *Wkvb_h, *Wkvb_l, *attn_h, *attn_l, *Wo_h, *Wo_l;
    __nv_bfloat16 *qah, *qal, *kah, *kal;
    __half *vaf;
    cudaGetSymbolAddress((void**)&hid_h,  g_hid_h);
    cudaGetSymbolAddress((void**)&hid_l,  g_hid_l);
    cudaGetSymbolAddress((void**)&Wq_h,   g_Wq_h);
    cudaGetSymbolAddress((void**)&Wq_l,   g_Wq_l);
    cudaGetSymbolAddress((void**)&Wkva_h, g_Wkva_h);
    cudaGetSymbolAddress((void**)&Wkva_l, g_Wkva_l);
    cudaGetSymbolAddress((void**)&kva_h,  g_kva_h);
    cudaGetSymbolAddress((void**)&kva_l,  g_kva_l);
    cudaGetSymbolAddress((void**)&Wkvb_h, g_Wkvb_h);
    cudaGetSymbolAddress((void**)&Wkvb_l, g_Wkvb_l);
    cudaGetSymbolAddress((void**)&attn_h, g_attn_h);
    cudaGetSymbolAddress((void**)&attn_l, g_attn_l);
    cudaGetSymbolAddress((void**)&Wo_h,   g_Wo_h);
    cudaGetSymbolAddress((void**)&Wo_l,   g_Wo_l);
    cudaGetSymbolAddress((void**)&qah,    g_qah);
    cudaGetSymbolAddress((void**)&qal,    g_qal);
    cudaGetSymbolAddress((void**)&kah,    g_kah);
    cudaGetSymbolAddress((void**)&kal,    g_kal);
    cudaGetSymbolAddress((void**)&vaf,    g_vaf);

    rope_table_kernel<<<T_TOK, 32>>>(positions, tcos, tsin);

    split(hidden, hid_h, hid_l, T_TOK * HID);
    split(Wq,     Wq_h,  Wq_l,  HID * 3072);
    split(Wkva,   Wkva_h, Wkva_l, HID * 576);

    // 1. q = hidden @ Wq
    mma_gemm_kernel<<<dim3(3072 / XBN, T_TOK / XBM), 256>>>(
        hid_h, hid_l, Wq_h, Wq_l, q, T_TOK, 3072, HID);
    // 2. latent = hidden @ Wkva
    mma_gemm_kernel<<<dim3((576 + XBN - 1) / XBN, T_TOK / XBM), 256>>>(
        hid_h, hid_l, Wkva_h, Wkva_l, latent, T_TOK, 576, HID);
    // 3. rmsnorm + k_pe rope
    rmsnorm_ropek_kernel<<<T_TOK, 256>>>(latent, lnw, tcos, tsin, kva, kpe);
    // 4. kv = kv_a @ Wkvb
    split(kva,  kva_h,  kva_l,  T_TOK * L_KV);
    split(Wkvb, Wkvb_h, Wkvb_l, L_KV * 4096);
    mma_gemm_kernel<<<dim3(4096 / XBN, T_TOK / XBM), 256>>>(
        kva_h, kva_l, Wkvb_h, Wkvb_l, kv, T_TOK, 4096, L_KV);
    // 5. attention operand prep
    qprep_kernel<<<T_TOK, 256>>>(q, tcos, tsin, qah, qal);
    kprep_kernel<<<T_TOK, 256>>>(kv, kpe, kah, kal, vaf);
    // 6. tensor-core causal attention
    cudaFuncSetAttribute(attn_mma_kernel, cudaFuncAttributeMaxDynamicSharedMemorySize, ATT_SMEM);
    attn_mma_kernel<<<dim3(T_TOK / 128, H_HEADS), 256, ATT_SMEM>>>(
        qah, qal, kah, kal, vaf, attn);
    // 7. out = attn @ Wo
    split(attn, attn_h, attn_l, T_TOK * 2048);
    split(Wo,   Wo_h,   Wo_l,   2048 * 2048);
    mma_gemm_kernel<<<dim3(2048 / XBN, T_TOK / XBM), 256>>>(
        attn_h, attn_l, Wo_h, Wo_l, out, T_TOK, 2048, 2048);
}

// round 9
// speedup vs baseline: 5.4968x; 1.2349x over previous
#include <cuda_runtime.h>
#include <cuda_bf16.h>
#include <cuda_fp16.h>
#include <math.h>
#include <stdint.h>
#include <cstdint>

#define T_TOK   4096
#define HID     2048
#define H_HEADS 16
#define D_NOPE  128
#define D_ROPE  64
#define D_V     128
#define L_KV    512
#define D_QK    192
#define KV_W    256

// ---------------- scratch (device globals) ---------------------------------
__device__ float g_q[(size_t)T_TOK * H_HEADS * D_QK];
__device__ float g_latent[(size_t)T_TOK * (L_KV + D_ROPE)];
__device__ float g_kpe[(size_t)T_TOK * D_ROPE];
__device__ float g_kv[(size_t)T_TOK * H_HEADS * KV_W];

__device__ float g_cos[(size_t)T_TOK * 32];
__device__ float g_sin[(size_t)T_TOK * 32];

// A-side activations: fp16 hi/lo (exact 2-term representation)
__device__ __half g_hid_h [(size_t)T_TOK * HID];
__device__ __half g_hid_l [(size_t)T_TOK * HID];
__device__ __half g_kva_h [(size_t)T_TOK * L_KV];
__device__ __half g_kva_l [(size_t)T_TOK * L_KV];
__device__ __half g_attn_h[(size_t)T_TOK * 2048];
__device__ __half g_attn_l[(size_t)T_TOK * 2048];

// B-side weights: single fp16 plane (rounding error ~2^-11, the only GEMM error)
__device__ __half g_Wq_f  [(size_t)2048 * 3072];
__device__ __half g_Wkva_f[(size_t)2048 * 640];   // N=576 padded to 640
__device__ __half g_Wkvb_f[(size_t)512 * 4096];
__device__ __half g_Wo_f  [(size_t)2048 * 2048];

// attention operand buffers
__device__ __nv_bfloat16 g_qah[(size_t)T_TOK * H_HEADS * D_QK];
__device__ __nv_bfloat16 g_qal[(size_t)T_TOK * H_HEADS * D_QK];
__device__ __nv_bfloat16 g_kah[(size_t)T_TOK * H_HEADS * D_QK];
__device__ __nv_bfloat16 g_kal[(size_t)T_TOK * H_HEADS * D_QK];
__device__ __half        g_vaf[(size_t)T_TOK * H_HEADS * D_V];

static __device__ __forceinline__ unsigned smem_u32(const void* p) {
    return (unsigned)__cvta_generic_to_shared(p);
}
static __device__ __forceinline__ void cp_async16(void* dst, const void* src) {
    asm volatile("cp.async.cg.shared.global [%0], [%1], 16;\n"
                 :: "r"(smem_u32(dst)), "l"(src));
}
static __device__ __forceinline__ void cp_commit() {
    asm volatile("cp.async.commit_group;\n");
}
static __device__ __forceinline__ unsigned pack_h2(float a, float b) {
    __half2 h = __floats2half2_rn(a, b);
    return *(unsigned*)&h;
}
static __device__ __forceinline__ float ex2f(float x) {
    float r;
    asm("ex2.approx.ftz.f32 %0, %1;" : "=f"(r) : "f"(x));
    return r;
}

#define MMA_BF16(D, A, B)                                                    \
    asm volatile(                                                            \
        "mma.sync.aligned.m16n8k16.row.col.f32.bf16.bf16.f32 "               \
        "{%0,%1,%2,%3}, {%4,%5,%6,%7}, {%8,%9}, {%0,%1,%2,%3};"              \
        : "+f"(D[0]), "+f"(D[1]), "+f"(D[2]), "+f"(D[3])                     \
        : "r"(A[0]), "r"(A[1]), "r"(A[2]), "r"(A[3]), "r"(B[0]), "r"(B[1]))
#define MMA_F16(D, A, B)                                                     \
    asm volatile(                                                            \
        "mma.sync.aligned.m16n8k16.row.col.f32.f16.f16.f32 "                 \
        "{%0,%1,%2,%3}, {%4,%5,%6,%7}, {%8,%9}, {%0,%1,%2,%3};"              \
        : "+f"(D[0]), "+f"(D[1]), "+f"(D[2]), "+f"(D[3])                     \
        : "r"(A[0]), "r"(A[1]), "r"(A[2]), "r"(A[3]), "r"(B[0]), "r"(B[1]))

// ---------------- rope table ------------------------------------------------
__global__ __launch_bounds__(32) void rope_table_kernel(
    const int* __restrict__ positions, float* __restrict__ ct, float* __restrict__ st)
{
    int t = blockIdx.x, i = threadIdx.x;
    double pos  = (double)positions[t];
    double freq = pow(10000.0, -(double)i / 32.0);
    double ang  = pos * freq;
    ct[t * 32 + i] = (float)cos(ang);
    st[t * 32 + i] = (float)sin(ang);
}

// ---------------- fp32 -> fp16 hi/lo split ----------------------------------
__global__ __launch_bounds__(256) void hsplit_kernel(
    const float* __restrict__ x, __half* __restrict__ hi,
    __half* __restrict__ lo, int n)
{
    int i = blockIdx.x * 256 + threadIdx.x;
    if (i < n) {
        float v = x[i];
        __half h = __float2half(v);
        hi[i] = h;
        lo[i] = __float2half(v - __half2float(h));
    }
}

// ---------------- fp32 weight [K,N] -> fp16 [K,Npad] (zero pad) -------------
__global__ __launch_bounds__(256) void wconv_kernel(
    const float* __restrict__ X, __half* __restrict__ Y,
    int N, int Npad, int total)
{
    int i = blockIdx.x * 256 + threadIdx.x;
    if (i < total) {
        int r = i / Npad, c = i % Npad;
        Y[i] = __float2half(c < N ? X[(size_t)r * N + c] : 0.f);
    }
}

// ---------------- fp16 2-term tensor-core GEMM ------------------------------
// C[M,Nc] = (Ah+Al)[M,K] @ Bf[K,Nb(cols col0..)]; exact in A, fp16-rounded B.
// 128x128x32 tile, 256 threads (8 warps, 64x32 warp tiles), 3-stage cp.async.
// stage layout: Ah(128x40 fp16 =10240B) | Al(10240B) | B(32x136 fp16 =8704B)
#define STG       29184
#define GEMM_SMEM (3 * STG)

__global__ __launch_bounds__(256) void hgemm_kernel(
    const __half* __restrict__ Ah, const __half* __restrict__ Al,
    const __half* __restrict__ Bf, float* __restrict__ C,
    int M, int Nc, int Nb, int K)
{
    extern __shared__ char smr[];
    const int tid = threadIdx.x, lane = tid & 31, wid = tid >> 5;
    const int row0 = blockIdx.y * 128;
    const int col0 = blockIdx.x * 128;
    const int wm0  = (wid & 1) * 64;
    const int wn0  = (wid >> 1) * 32;
    const int nkc  = K >> 5;

    float acc[4][4][4];
#pragma unroll
    for (int a = 0; a < 4; a++)
#pragma unroll
        for (int b = 0; b < 4; b++)
#pragma unroll
            for (int c = 0; c < 4; c++) acc[a][b][c] = 0.f;

    auto load_stage = [&](int st, int kb) {
        char* base = smr + st * STG;
#pragma unroll
        for (int j = 0; j < 2; j++) {
            int idx = tid + j * 256;          // 0..511: r=idx>>2 (128 rows), c=idx&3
            int r = idx >> 2, c = idx & 3;
            size_t g = (size_t)(row0 + r) * K + kb + c * 8;
            cp_async16(base + r * 80 + c * 16,         Ah + g);
            cp_async16(base + 10240 + r * 80 + c * 16, Al + g);
        }
#pragma unroll
        for (int j = 0; j < 2; j++) {
            int idx = tid + j * 256;          // 0..511: r=idx>>4 (32 rows), c=idx&15
            int r = idx >> 4, c = idx & 15;
            size_t g = (size_t)(kb + r) * Nb + col0 + c * 8;
            cp_async16(base + 20480 + r * 272 + c * 16, Bf + g);
        }
        cp_commit();
    };

    load_stage(0, 0);
    if (nkc > 1) load_stage(1, 32);
    if (nkc > 2) load_stage(2, 64);

    for (int i = 0; i < nkc; i++) {
        int pend = nkc - 1 - i;
        if (pend >= 2)      asm volatile("cp.async.wait_group 2;\n" ::: "memory");
        else if (pend == 1) asm volatile("cp.async.wait_group 1;\n" ::: "memory");
        else                asm volatile("cp.async.wait_group 0;\n" ::: "memory");
        __syncthreads();

        char* base = smr + (i % 3) * STG;
#pragma unroll
        for (int ks = 0; ks < 32; ks += 16) {
            unsigned fah[4][4], fal[4][4], fb[4][2];
            {
                int r = lane & 15, seg = lane >> 4;
#pragma unroll
                for (int mt = 0; mt < 4; mt++) {
                    unsigned a0 = smem_u32(base + (wm0 + mt * 16 + r) * 80 + (ks + seg * 8) * 2);
                    unsigned a1 = smem_u32(base + 10240 + (wm0 + mt * 16 + r) * 80 + (ks + seg * 8) * 2);
                    asm volatile("ldmatrix.sync.aligned.m8n8.x4.shared.b16 {%0,%1,%2,%3}, [%4];"
                        : "=r"(fah[mt][0]), "=r"(fah[mt][1]), "=r"(fah[mt][2]), "=r"(fah[mt][3]) : "r"(a0));
                    asm volatile("ldmatrix.sync.aligned.m8n8.x4.shared.b16 {%0,%1,%2,%3}, [%4];"
                        : "=r"(fal[mt][0]), "=r"(fal[mt][1]), "=r"(fal[mt][2]), "=r"(fal[mt][3]) : "r"(a1));
                }
            }
            {
                int l = lane & 15;
#pragma unroll
                for (int nt = 0; nt < 4; nt++) {
                    unsigned b0 = smem_u32(base + 20480 + (ks + l) * 272 + (wn0 + nt * 8) * 2);
                    asm volatile("ldmatrix.sync.aligned.m8n8.x2.trans.shared.b16 {%0,%1}, [%2];"
                        : "=r"(fb[nt][0]), "=r"(fb[nt][1]) : "r"(b0));
                }
            }
            // pass 1: Ah*B; pass 2: Al*B — no back-to-back same-acc dependencies
#pragma unroll
            for (int mt = 0; mt < 4; mt++)
#pragma unroll
                for (int nt = 0; nt < 4; nt++) { float* d = acc[mt][nt]; MMA_F16(d, fah[mt], fb[nt]); }
#pragma unroll
            for (int mt = 0; mt < 4; mt++)
#pragma unroll
                for (int nt = 0; nt < 4; nt++) { float* d = acc[mt][nt]; MMA_F16(d, fal[mt], fb[nt]); }
        }
        __syncthreads();
        if (i + 3 < nkc) load_stage(i % 3, (i + 3) * 32);
    }

#pragma unroll
    for (int mt = 0; mt < 4; mt++) {
        int gr = row0 + wm0 + mt * 16 + (lane >> 2);
#pragma unroll
        for (int nt = 0; nt < 4; nt++) {
            int gc = col0 + wn0 + nt * 8 + (lane & 3) * 2;
            if (gc < Nc) {
                *(float2*)&C[(size_t)gr * Nc + gc]       = make_float2(acc[mt][nt][0], acc[mt][nt][1]);
                *(float2*)&C[(size_t)(gr + 8) * Nc + gc] = make_float2(acc[mt][nt][2], acc[mt][nt][3]);
            }
        }
    }
}

// ---------------- rmsnorm + k_pe rope (writes fp16 hi/lo kva) ---------------
__global__ __launch_bounds__(256) void rmsnorm_ropek_kernel(
    const float* __restrict__ latent, const float* __restrict__ w,
    const float* __restrict__ ct, const float* __restrict__ st,
    __half* __restrict__ kvah, __half* __restrict__ kval, float* __restrict__ kpe)
{
    int t = blockIdx.x;
    const float* x = latent + (size_t)t * (L_KV + D_ROPE);
    __shared__ float red[256];
    float ss = 0.f;
    for (int i = threadIdx.x; i < L_KV; i += 256) { float v = x[i]; ss += v * v; }
    red[threadIdx.x] = ss;
    __syncthreads();
    for (int s = 128; s > 0; s >>= 1) {
        if (threadIdx.x < s) red[threadIdx.x] += red[threadIdx.x + s];
        __syncthreads();
    }
    float inv = rsqrtf(red[0] / (float)L_KV + 1e-6f);
    for (int i = threadIdx.x; i < L_KV; i += 256) {
        float y = x[i] * inv * w[i];
        __half hh = __float2half(y);
        kvah[(size_t)t * L_KV + i] = hh;
        kval[(size_t)t * L_KV + i] = __float2half(y - __half2float(hh));
    }
    if (threadIdx.x < 32) {
        int i = threadIdx.x;
        float c = ct[t * 32 + i], s = st[t * 32 + i];
        float x1 = x[L_KV + i], x2 = x[L_KV + 32 + i];
        kpe[(size_t)t * D_ROPE + i]      = x1 * c - x2 * s;
        kpe[(size_t)t * D_ROPE + 32 + i] = x2 * c + x1 * s;
    }
}

// ---------------- q prep: rope + scale + bf16 split -------------------------
__global__ __launch_bounds__(256) void qprep_kernel(
    const float* __restrict__ q, const float* __restrict__ ct, const float* __restrict__ st,
    __nv_bfloat16* __restrict__ qh, __nv_bfloat16* __restrict__ ql)
{
    int t = blockIdx.x;
    const float SC = 0.07216878364870323f * 1.4426950408889634f;
    for (int idx = threadIdx.x; idx < H_HEADS * D_QK; idx += 256) {
        int c = idx % D_QK;
        const float* qr = q + (size_t)t * 3072 + (idx - c);
        float v;
        if (c < D_NOPE) v = qr[c];
        else {
            int i = c - D_NOPE;
            if (i < 32) v = qr[c] * ct[t * 32 + i] - qr[c + 32] * st[t * 32 + i];
            else { int j = i - 32; v = qr[c] * ct[t * 32 + j] + qr[c - 32] * st[t * 32 + j]; }
        }
        v *= SC;
        __nv_bfloat16 hv = __float2bfloat16(v);
        qh[(size_t)t * 3072 + idx] = hv;
        ql[(size_t)t * 3072 + idx] = __float2bfloat16(v - __bfloat162float(hv));
    }
}

// ---------------- k/v prep --------------------------------------------------
__global__ __launch_bounds__(256) void kprep_kernel(
    const float* __restrict__ kv, const float* __restrict__ kpe,
    __nv_bfloat16* __restrict__ kh, __nv_bfloat16* __restrict__ kl,
    __half* __restrict__ vf)
{
    int t = blockIdx.x;
    for (int idx = threadIdx.x; idx < H_HEADS * D_QK; idx += 256) {
        int hh = idx / D_QK, c = idx % D_QK;
        float v = (c < D_NOPE) ? kv[((size_t)t * H_HEADS + hh) * KV_W + c]
                               : kpe[(size_t)t * D_ROPE + (c - D_NOPE)];
        __nv_bfloat16 hv = __float2bfloat16(v);
        kh[(size_t)t * 3072 + idx] = hv;
        kl[(size_t)t * 3072 + idx] = __float2bfloat16(v - __bfloat162float(hv));
    }
    for (int idx = threadIdx.x; idx < H_HEADS * D_V; idx += 256) {
        int hh = idx / D_V, d = idx % D_V;
        vf[(size_t)t * 2048 + idx] =
            __float2half(kv[((size_t)t * H_HEADS + hh) * KV_W + D_NOPE + d]);
    }
}

// ---------------- tensor-core causal flash attention ------------------------
// R5 structure; epilogue now writes fp16 hi/lo directly (Wo GEMM A operand).
#define ATT_SMEM (98304 + 2 * 65536)

__global__ __launch_bounds__(256, 1) void attn_mma_kernel(
    const __nv_bfloat16* __restrict__ qh, const __nv_bfloat16* __restrict__ ql,
    const __nv_bfloat16* __restrict__ kh, const __nv_bfloat16* __restrict__ kl,
    const __half* __restrict__ vf,
    __half* __restrict__ oh, __half* __restrict__ ol)
{
    extern __shared__ char smr[];
    char* sQh = smr;
    char* sQl = smr + 49152;

    const int tid = threadIdx.x, lane = tid & 31, w = tid >> 5;
    const int b  = gridDim.x - 1 - blockIdx.x;
    const int q0 = b * 128;
    const int h  = blockIdx.y;
    const int niter = (q0 + 128) >> 6;

    for (int idx = tid; idx < 128 * 24; idx += 256) {
        int r = idx / 24, c = idx % 24;
        int sw = ((c ^ (r & 7)) << 4);
        size_t g = ((size_t)(q0 + r) * H_HEADS + h) * D_QK + c * 8;
        cp_async16(sQh + r * 384 + sw, qh + g);
        cp_async16(sQl + r * 384 + sw, ql + g);
    }

    auto load_stage = [&](int st, int s0) {
        char* base = smr + 98304 + st * 65536;
        char* sKh = base, *sKl = base + 24576, *sV = base + 49152;
        for (int idx = tid; idx < 64 * 24; idx += 256) {
            int r = idx / 24, c = idx % 24;
            int sw = ((c ^ (r & 7)) << 4);
            size_t g = ((size_t)(s0 + r) * H_HEADS + h) * D_QK + c * 8;
            cp_async16(sKh + r * 384 + sw, kh + g);
            cp_async16(sKl + r * 384 + sw, kl + g);
        }
        for (int idx = tid; idx < 64 * 16; idx += 256) {
            int r = idx / 16, c = idx % 16;
            int sw = ((c ^ (r & 7)) << 4);
            cp_async16(sV + r * 256 + sw,
                       vf + ((size_t)(s0 + r) * H_HEADS + h) * D_V + c * 8);
        }
    };

    load_stage(0, 0);
    cp_commit();

    float m0 = -1e30f, m1 = -1e30f, l0 = 0.f, l1 = 0.f;
    float oacc[16][4];
#pragma unroll
    for (int i = 0; i < 16; i++)
#pragma unroll
        for (int j = 0; j < 4; j++) oacc[i][j] = 0.f;

    for (int it = 0; it < niter; it++) {
        const int s0 = it * 64;
        if (it + 1 < niter) { load_stage((it + 1) & 1, s0 + 64); cp_commit(); }
        if (it + 1 < niter) asm volatile("cp.async.wait_group 1;\n");
        else                asm volatile("cp.async.wait_group 0;\n");
        __syncthreads();

        char* base = smr + 98304 + (it & 1) * 65536;
        char* sKh = base, *sKl = base + 24576, *sV = base + 49152;

        float sacc[8][4];
#pragma unroll
        for (int i = 0; i < 8; i++)
#pragma unroll
            for (int j = 0; j < 4; j++) sacc[i][j] = 0.f;

#pragma unroll
        for (int kk = 0; kk < 12; kk++) {
            unsigned ah[4], al[4];
            {
                int r = 16 * w + (lane & 15);
                int cc = 2 * kk + (lane >> 4);
                unsigned qa = smem_u32(sQh + r * 384 + (((cc ^ (r & 7)) << 4)));
                unsigned qb = smem_u32(sQl + r * 384 + (((cc ^ (r & 7)) << 4)));
                asm volatile("ldmatrix.sync.aligned.m8n8.x4.shared.b16 {%0,%1,%2,%3}, [%4];"
                    : "=r"(ah[0]), "=r"(ah[1]), "=r"(ah[2]), "=r"(ah[3]) : "r"(qa));
                asm volatile("ldmatrix.sync.aligned.m8n8.x4.shared.b16 {%0,%1,%2,%3}, [%4];"
                    : "=r"(al[0]), "=r"(al[1]), "=r"(al[2]), "=r"(al[3]) : "r"(qb));
            }
#pragma unroll
            for (int nt = 0; nt < 8; nt++) {
                unsigned bh[2], bl[2];
                int rK = nt * 8 + (lane & 7);
                int cc = 2 * kk + ((lane & 15) >> 3);
                unsigned ka = smem_u32(sKh + rK * 384 + (((cc ^ (rK & 7)) << 4)));
                unsigned kb = smem_u32(sKl + rK * 384 + (((cc ^ (rK & 7)) << 4)));
                asm volatile("ldmatrix.sync.aligned.m8n8.x2.shared.b16 {%0,%1}, [%2];"
                    : "=r"(bh[0]), "=r"(bh[1]) : "r"(ka));
                asm volatile("ldmatrix.sync.aligned.m8n8.x2.shared.b16 {%0,%1}, [%2];"
                    : "=r"(bl[0]), "=r"(bl[1]) : "r"(kb));
                float* d = sacc[nt];
                MMA_BF16(d, ah, bh);
                MMA_BF16(d, ah, bl);
                MMA_BF16(d, al, bh);
            }
        }

        if (s0 + 64 > q0) {
            int row0 = q0 + 16 * w + (lane >> 2);
#pragma unroll
            for (int nt = 0; nt < 8; nt++) {
                int c = s0 + nt * 8 + (lane & 3) * 2;
                if (c     > row0)     sacc[nt][0] = -1e30f;
                if (c + 1 > row0)     sacc[nt][1] = -1e30f;
                if (c     > row0 + 8) sacc[nt][2] = -1e30f;
                if (c + 1 > row0 + 8) sacc[nt][3] = -1e30f;
            }
        }

        float mx0 = -1e30f, mx1 = -1e30f;
#pragma unroll
        for (int nt = 0; nt < 8; nt++) {
            mx0 = fmaxf(mx0, fmaxf(sacc[nt][0], sacc[nt][1]));
            mx1 = fmaxf(mx1, fmaxf(sacc[nt][2], sacc[nt][3]));
        }
        mx0 = fmaxf(mx0, __shfl_xor_sync(0xffffffffu, mx0, 1));
        mx0 = fmaxf(mx0, __shfl_xor_sync(0xffffffffu, mx0, 2));
        mx1 = fmaxf(mx1, __shfl_xor_sync(0xffffffffu, mx1, 1));
        mx1 = fmaxf(mx1, __shfl_xor_sync(0xffffffffu, mx1, 2));
        float mn0 = fmaxf(m0, mx0), mn1 = fmaxf(m1, mx1);
        float a0 = ex2f(m0 - mn0), a1 = ex2f(m1 - mn1);
        m0 = mn0; m1 = mn1;
        float ps0 = 0.f, ps1 = 0.f;
#pragma unroll
        for (int nt = 0; nt < 8; nt++) {
            float p0 = ex2f(sacc[nt][0] - mn0);
            float p1 = ex2f(sacc[nt][1] - mn0);
            float p2 = ex2f(sacc[nt][2] - mn1);
            float p3 = ex2f(sacc[nt][3] - mn1);
            sacc[nt][0] = p0; sacc[nt][1] = p1; sacc[nt][2] = p2; sacc[nt][3] = p3;
            ps0 += p0 + p1; ps1 += p2 + p3;
        }
        ps0 += __shfl_xor_sync(0xffffffffu, ps0, 1);
        ps0 += __shfl_xor_sync(0xffffffffu, ps0, 2);
        ps1 += __shfl_xor_sync(0xffffffffu, ps1, 1);
        ps1 += __shfl_xor_sync(0xffffffffu, ps1, 2);
        l0 = l0 * a0 + ps0;
        l1 = l1 * a1 + ps1;
#pragma unroll
        for (int nd = 0; nd < 16; nd++) {
            oacc[nd][0] *= a0; oacc[nd][1] *= a0;
            oacc[nd][2] *= a1; oacc[nd][3] *= a1;
        }

        unsigned pa[4][4];
#pragma unroll
        for (int k2 = 0; k2 < 4; k2++) {
            pa[k2][0] = pack_h2(sacc[2 * k2][0],     sacc[2 * k2][1]);
            pa[k2][1] = pack_h2(sacc[2 * k2][2],     sacc[2 * k2][3]);
            pa[k2][2] = pack_h2(sacc[2 * k2 + 1][0], sacc[2 * k2 + 1][1]);
            pa[k2][3] = pack_h2(sacc[2 * k2 + 1][2], sacc[2 * k2 + 1][3]);
        }

#pragma unroll
        for (int k2 = 0; k2 < 4; k2++) {
            int rV = k2 * 16 + (lane & 15);
#pragma unroll
            for (int nd = 0; nd < 16; nd++) {
                unsigned vb[2];
                unsigned va = smem_u32(sV + rV * 256 + (((nd ^ (rV & 7)) << 4)));
                asm volatile("ldmatrix.sync.aligned.m8n8.x2.trans.shared.b16 {%0,%1}, [%2];"
                    : "=r"(vb[0]), "=r"(vb[1]) : "r"(va));
                float* d = oacc[nd];
                MMA_F16(d, pa[k2], vb);
            }
        }
        __syncthreads();
    }

    // epilogue: normalize + write fp16 hi/lo (exact 2-term) for the Wo GEMM
    float il0 = 1.f / l0, il1 = 1.f / l1;
    int r0 = q0 + 16 * w + (lane >> 2);
    int cb = h * D_V + (lane & 3) * 2;
#pragma unroll
    for (int nd = 0; nd < 16; nd++) {
        size_t p0 = (size_t)r0 * 2048 + cb + nd * 8;
        size_t p1 = (size_t)(r0 + 8) * 2048 + cb + nd * 8;
        float v0 = oacc[nd][0] * il0, v1 = oacc[nd][1] * il0;
        float v2 = oacc[nd][2] * il1, v3 = oacc[nd][3] * il1;
        __half h0 = __float2half(v0), h1 = __float2half(v1);
        __half h2 = __float2half(v2), h3 = __float2half(v3);
        *(__half2*)&oh[p0] = __halves2half2(h0, h1);
        *(__half2*)&ol[p0] = __halves2half2(__float2half(v0 - __half2float(h0)),
                                            __float2half(v1 - __half2float(h1)));
        *(__half2*)&oh[p1] = __halves2half2(h2, h3);
        *(__half2*)&ol[p1] = __halves2half2(__float2half(v2 - __half2float(h2)),
                                            __float2half(v3 - __half2float(h3)));
    }
}

// ---------------- launch ---------------------------------------------------
static inline void hgemm(const __half* Ah, const __half* Al, const __half* Bf,
                         float* C, int M, int Nc, int Nb, int K) {
    cudaFuncSetAttribute(hgemm_kernel, cudaFuncAttributeMaxDynamicSharedMemorySize, GEMM_SMEM);
    hgemm_kernel<<<dim3(Nb / 128, M / 128), 256, GEMM_SMEM>>>(Ah, Al, Bf, C, M, Nc, Nb, K);
}

extern "C" void kernel_launch(void* const* d_in, const int* in_sizes, int n_in,
                              void* d_out, int out_size)
{
    const int*   positions = (const int*)d_in[0];
    const float* hidden    = (const float*)d_in[1];
    const float* Wq        = (const float*)d_in[2];
    const float* Wkva      = (const float*)d_in[3];
    const float* lnw       = (const float*)d_in[4];
    const float* Wkvb      = (const float*)d_in[5];
    const float* Wo        = (const float*)d_in[6];
    float* out = (float*)d_out;

    float *q, *latent, *kpe, *kv, *tcos, *tsin;
    cudaGetSymbolAddress((void**)&q,      g_q);
    cudaGetSymbolAddress((void**)&latent, g_latent);
    cudaGetSymbolAddress((void**)&kpe,    g_kpe);
    cudaGetSymbolAddress((void**)&kv,     g_kv);
    cudaGetSymbolAddress((void**)&tcos,   g_cos);
    cudaGetSymbolAddress((void**)&tsin,   g_sin);

    __half *hid_h, *hid_l, *kva_h, *kva_l, *attn_h, *attn_l;
    __half *Wq_f, *Wkva_f, *Wkvb_f, *Wo_f, *vaf;
    __nv_bfloat16 *qah, *qal, *kah, *kal;
    cudaGetSymbolAddress((void**)&hid_h,  g_hid_h);
    cudaGetSymbolAddress((void**)&hid_l,  g_hid_l);
    cudaGetSymbolAddress((void**)&kva_h,  g_kva_h);
    cudaGetSymbolAddress((void**)&kva_l,  g_kva_l);
    cudaGetSymbolAddress((void**)&attn_h, g_attn_h);
    cudaGetSymbolAddress((void**)&attn_l, g_attn_l);
    cudaGetSymbolAddress((void**)&Wq_f,   g_Wq_f);
    cudaGetSymbolAddress((void**)&Wkva_f, g_Wkva_f);
    cudaGetSymbolAddress((void**)&Wkvb_f, g_Wkvb_f);
    cudaGetSymbolAddress((void**)&Wo_f,   g_Wo_f);
    cudaGetSymbolAddress((void**)&qah,    g_qah);
    cudaGetSymbolAddress((void**)&qal,    g_qal);
    cudaGetSymbolAddress((void**)&kah,    g_kah);
    cudaGetSymbolAddress((void**)&kal,    g_kal);
    cudaGetSymbolAddress((void**)&vaf,    g_vaf);

    rope_table_kernel<<<T_TOK, 32>>>(positions, tcos, tsin);

    hsplit_kernel<<<(T_TOK * HID + 255) / 256, 256>>>(hidden, hid_h, hid_l, T_TOK * HID);
    wconv_kernel<<<(2048 * 3072 + 255) / 256, 256>>>(Wq,   Wq_f,   3072, 3072, 2048 * 3072);
    wconv_kernel<<<(2048 * 640  + 255) / 256, 256>>>(Wkva, Wkva_f, 576,  640,  2048 * 640);

    // 1. q = hidden @ Wq
    hgemm(hid_h, hid_l, Wq_f, q, T_TOK, 3072, 3072, HID);
    // 2. latent = hidden @ Wkva (N padded 640, stride/guard 576)
    hgemm(hid_h, hid_l, Wkva_f, latent, T_TOK, 576, 640, HID);
    // 3. rmsnorm (fp16 hi/lo out) + k_pe rope
    rmsnorm_ropek_kernel<<<T_TOK, 256>>>(latent, lnw, tcos, tsin, kva_h, kva_l, kpe);
    // 4. kv = kv_a @ Wkvb
    wconv_kernel<<<(512 * 4096 + 255) / 256, 256>>>(Wkvb, Wkvb_f, 4096, 4096, 512 * 4096);
    hgemm(kva_h, kva_l, Wkvb_f, kv, T_TOK, 4096, 4096, L_KV);
    // 5. attention operand prep
    qprep_kernel<<<T_TOK, 256>>>(q, tcos, tsin, qah, qal);
    kprep_kernel<<<T_TOK, 256>>>(kv, kpe, kah, kal, vaf);
    // 6. tensor-core causal attention (fp16 hi/lo epilogue)
    cudaFuncSetAttribute(attn_mma_kernel, cudaFuncAttributeMaxDynamicSharedMemorySize, ATT_SMEM);
    attn_mma_kernel<<<dim3(T_TOK / 128, H_HEADS), 256, ATT_SMEM>>>(
        qah, qal, kah, kal, vaf, attn_h, attn_l);
    // 7. out = attn @ Wo
    wconv_kernel<<<(2048 * 2048 + 255) / 256, 256>>>(Wo, Wo_f, 2048, 2048, 2048 * 2048);
    hgemm(attn_h, attn_l, Wo_f, out, T_TOK, 2048, 2048, 2048);
}

// round 10
// speedup vs baseline: 6.5350x; 1.1889x over previous
#include <cuda_runtime.h>
#include <cuda_bf16.h>
#include <cuda_fp16.h>
#include <math.h>
#include <stdint.h>
#include <cstdint>

#define T_TOK   4096
#define HID     2048
#define H_HEADS 16
#define D_NOPE  128
#define D_ROPE  64
#define D_V     128
#define L_KV    512
#define D_QK    192
#define KV_W    256

// ---------------- scratch (device globals) ---------------------------------
__device__ float g_q[(size_t)T_TOK * H_HEADS * D_QK];
__device__ float g_latent[(size_t)T_TOK * (L_KV + D_ROPE)];
__device__ float g_kpe[(size_t)T_TOK * D_ROPE];
__device__ float g_kv[(size_t)T_TOK * H_HEADS * KV_W];

__device__ float g_cos[(size_t)T_TOK * 32];
__device__ float g_sin[(size_t)T_TOK * 32];

// A-side activations: fp16 hi/lo (exact 2-term representation)
__device__ __half g_hid_h [(size_t)T_TOK * HID];
__device__ __half g_hid_l [(size_t)T_TOK * HID];
__device__ __half g_kva_h [(size_t)T_TOK * L_KV];
__device__ __half g_kva_l [(size_t)T_TOK * L_KV];
__device__ __half g_attn_f[(size_t)T_TOK * 2048];   // single plane (Wo GEMM A)

// B-side weights: single fp16 plane
__device__ __half g_Wq_f  [(size_t)2048 * 3072];
__device__ __half g_Wkva_f[(size_t)2048 * 640];   // N=576 padded to 640
__device__ __half g_Wkvb_f[(size_t)512 * 4096];
__device__ __half g_Wo_f  [(size_t)2048 * 2048];

// attention operand buffers (fp16)
__device__ __half g_qah[(size_t)T_TOK * H_HEADS * D_QK];
__device__ __half g_qal[(size_t)T_TOK * H_HEADS * D_QK];
__device__ __half g_kaf[(size_t)T_TOK * H_HEADS * D_QK];
__device__ __half g_vaf[(size_t)T_TOK * H_HEADS * D_V];

static __device__ __forceinline__ unsigned smem_u32(const void* p) {
    return (unsigned)__cvta_generic_to_shared(p);
}
static __device__ __forceinline__ void cp_async16(void* dst, const void* src) {
    asm volatile("cp.async.cg.shared.global [%0], [%1], 16;\n"
                 :: "r"(smem_u32(dst)), "l"(src));
}
static __device__ __forceinline__ void cp_commit() {
    asm volatile("cp.async.commit_group;\n");
}
static __device__ __forceinline__ unsigned pack_h2(float a, float b) {
    __half2 h = __floats2half2_rn(a, b);
    return *(unsigned*)&h;
}
static __device__ __forceinline__ float ex2f(float x) {
    float r;
    asm("ex2.approx.ftz.f32 %0, %1;" : "=f"(r) : "f"(x));
    return r;
}

#define MMA_F16(D, A, B)                                                     \
    asm volatile(                                                            \
        "mma.sync.aligned.m16n8k16.row.col.f32.f16.f16.f32 "                 \
        "{%0,%1,%2,%3}, {%4,%5,%6,%7}, {%8,%9}, {%0,%1,%2,%3};"              \
        : "+f"(D[0]), "+f"(D[1]), "+f"(D[2]), "+f"(D[3])                     \
        : "r"(A[0]), "r"(A[1]), "r"(A[2]), "r"(A[3]), "r"(B[0]), "r"(B[1]))

// ---------------- rope table ------------------------------------------------
__global__ __launch_bounds__(32) void rope_table_kernel(
    const int* __restrict__ positions, float* __restrict__ ct, float* __restrict__ st)
{
    int t = blockIdx.x, i = threadIdx.x;
    double pos  = (double)positions[t];
    double freq = pow(10000.0, -(double)i / 32.0);
    double ang  = pos * freq;
    ct[t * 32 + i] = (float)cos(ang);
    st[t * 32 + i] = (float)sin(ang);
}

// ---------------- fp32 -> fp16 hi/lo split ----------------------------------
__global__ __launch_bounds__(256) void hsplit_kernel(
    const float* __restrict__ x, __half* __restrict__ hi,
    __half* __restrict__ lo, int n)
{
    int i = blockIdx.x * 256 + threadIdx.x;
    if (i < n) {
        float v = x[i];
        __half h = __float2half(v);
        hi[i] = h;
        lo[i] = __float2half(v - __half2float(h));
    }
}

// ---------------- fp32 weight [K,N] -> fp16 [K,Npad] (zero pad) -------------
__global__ __launch_bounds__(256) void wconv_kernel(
    const float* __restrict__ X, __half* __restrict__ Y,
    int N, int Npad, int total)
{
    int i = blockIdx.x * 256 + threadIdx.x;
    if (i < total) {
        int r = i / Npad, c = i % Npad;
        Y[i] = __float2half(c < N ? X[(size_t)r * N + c] : 0.f);
    }
}

// ---------------- fp16 tensor-core GEMM (TERMS = 1 or 2 A planes) -----------
// C[M,Nc] = A[M,K] @ Bf[K,Nb]; 128x128x32 tile, 256 threads, 3-stage cp.async.
// stage: Ah(10240B) [| Al(10240B)] | B(8704B)
template <int TERMS>
__global__ __launch_bounds__(256) void hgemm_kernel(
    const __half* __restrict__ Ah, const __half* __restrict__ Al,
    const __half* __restrict__ Bf, float* __restrict__ C,
    int M, int Nc, int Nb, int K)
{
    constexpr int BOFF = TERMS * 10240;
    constexpr int STG  = BOFF + 8704;
    extern __shared__ char smr[];
    const int tid = threadIdx.x, lane = tid & 31, wid = tid >> 5;
    const int row0 = blockIdx.y * 128;
    const int col0 = blockIdx.x * 128;
    const int wm0  = (wid & 1) * 64;
    const int wn0  = (wid >> 1) * 32;
    const int nkc  = K >> 5;

    float acc[4][4][4];
#pragma unroll
    for (int a = 0; a < 4; a++)
#pragma unroll
        for (int b = 0; b < 4; b++)
#pragma unroll
            for (int c = 0; c < 4; c++) acc[a][b][c] = 0.f;

    auto load_stage = [&](int st, int kb) {
        char* base = smr + st * STG;
#pragma unroll
        for (int j = 0; j < 2; j++) {
            int idx = tid + j * 256;
            int r = idx >> 2, c = idx & 3;
            size_t g = (size_t)(row0 + r) * K + kb + c * 8;
            cp_async16(base + r * 80 + c * 16, Ah + g);
            if (TERMS == 2)
                cp_async16(base + 10240 + r * 80 + c * 16, Al + g);
        }
#pragma unroll
        for (int j = 0; j < 2; j++) {
            int idx = tid + j * 256;
            int r = idx >> 4, c = idx & 15;
            size_t g = (size_t)(kb + r) * Nb + col0 + c * 8;
            cp_async16(base + BOFF + r * 272 + c * 16, Bf + g);
        }
        cp_commit();
    };

    load_stage(0, 0);
    if (nkc > 1) load_stage(1, 32);
    if (nkc > 2) load_stage(2, 64);

    for (int i = 0; i < nkc; i++) {
        int pend = nkc - 1 - i;
        if (pend >= 2)      asm volatile("cp.async.wait_group 2;\n" ::: "memory");
        else if (pend == 1) asm volatile("cp.async.wait_group 1;\n" ::: "memory");
        else                asm volatile("cp.async.wait_group 0;\n" ::: "memory");
        __syncthreads();

        char* base = smr + (i % 3) * STG;
#pragma unroll
        for (int ks = 0; ks < 32; ks += 16) {
            unsigned fah[4][4], fal[4][4], fb[4][2];
            {
                int r = lane & 15, seg = lane >> 4;
#pragma unroll
                for (int mt = 0; mt < 4; mt++) {
                    unsigned a0 = smem_u32(base + (wm0 + mt * 16 + r) * 80 + (ks + seg * 8) * 2);
                    asm volatile("ldmatrix.sync.aligned.m8n8.x4.shared.b16 {%0,%1,%2,%3}, [%4];"
                        : "=r"(fah[mt][0]), "=r"(fah[mt][1]), "=r"(fah[mt][2]), "=r"(fah[mt][3]) : "r"(a0));
                    if (TERMS == 2) {
                        unsigned a1 = smem_u32(base + 10240 + (wm0 + mt * 16 + r) * 80 + (ks + seg * 8) * 2);
                        asm volatile("ldmatrix.sync.aligned.m8n8.x4.shared.b16 {%0,%1,%2,%3}, [%4];"
                            : "=r"(fal[mt][0]), "=r"(fal[mt][1]), "=r"(fal[mt][2]), "=r"(fal[mt][3]) : "r"(a1));
                    }
                }
            }
            {
                int l = lane & 15;
#pragma unroll
                for (int nt = 0; nt < 4; nt++) {
                    unsigned b0 = smem_u32(base + BOFF + (ks + l) * 272 + (wn0 + nt * 8) * 2);
                    asm volatile("ldmatrix.sync.aligned.m8n8.x2.trans.shared.b16 {%0,%1}, [%2];"
                        : "=r"(fb[nt][0]), "=r"(fb[nt][1]) : "r"(b0));
                }
            }
#pragma unroll
            for (int mt = 0; mt < 4; mt++)
#pragma unroll
                for (int nt = 0; nt < 4; nt++) { float* d = acc[mt][nt]; MMA_F16(d, fah[mt], fb[nt]); }
            if (TERMS == 2) {
#pragma unroll
                for (int mt = 0; mt < 4; mt++)
#pragma unroll
                    for (int nt = 0; nt < 4; nt++) { float* d = acc[mt][nt]; MMA_F16(d, fal[mt], fb[nt]); }
            }
        }
        __syncthreads();
        if (i + 3 < nkc) load_stage(i % 3, (i + 3) * 32);
    }

#pragma unroll
    for (int mt = 0; mt < 4; mt++) {
        int gr = row0 + wm0 + mt * 16 + (lane >> 2);
#pragma unroll
        for (int nt = 0; nt < 4; nt++) {
            int gc = col0 + wn0 + nt * 8 + (lane & 3) * 2;
            if (gc < Nc) {
                *(float2*)&C[(size_t)gr * Nc + gc]       = make_float2(acc[mt][nt][0], acc[mt][nt][1]);
                *(float2*)&C[(size_t)(gr + 8) * Nc + gc] = make_float2(acc[mt][nt][2], acc[mt][nt][3]);
            }
        }
    }
}

// ---------------- rmsnorm + k_pe rope (writes fp16 hi/lo kva) ---------------
__global__ __launch_bounds__(256) void rmsnorm_ropek_kernel(
    const float* __restrict__ latent, const float* __restrict__ w,
    const float* __restrict__ ct, const float* __restrict__ st,
    __half* __restrict__ kvah, __half* __restrict__ kval, float* __restrict__ kpe)
{
    int t = blockIdx.x;
    const float* x = latent + (size_t)t * (L_KV + D_ROPE);
    __shared__ float red[256];
    float ss = 0.f;
    for (int i = threadIdx.x; i < L_KV; i += 256) { float v = x[i]; ss += v * v; }
    red[threadIdx.x] = ss;
    __syncthreads();
    for (int s = 128; s > 0; s >>= 1) {
        if (threadIdx.x < s) red[threadIdx.x] += red[threadIdx.x + s];
        __syncthreads();
    }
    float inv = rsqrtf(red[0] / (float)L_KV + 1e-6f);
    for (int i = threadIdx.x; i < L_KV; i += 256) {
        float y = x[i] * inv * w[i];
        __half hh = __float2half(y);
        kvah[(size_t)t * L_KV + i] = hh;
        kval[(size_t)t * L_KV + i] = __float2half(y - __half2float(hh));
    }
    if (threadIdx.x < 32) {
        int i = threadIdx.x;
        float c = ct[t * 32 + i], s = st[t * 32 + i];
        float x1 = x[L_KV + i], x2 = x[L_KV + 32 + i];
        kpe[(size_t)t * D_ROPE + i]      = x1 * c - x2 * s;
        kpe[(size_t)t * D_ROPE + 32 + i] = x2 * c + x1 * s;
    }
}

// ---------------- q prep: rope + scale + fp16 hi/lo split -------------------
__global__ __launch_bounds__(256) void qprep_kernel(
    const float* __restrict__ q, const float* __restrict__ ct, const float* __restrict__ st,
    __half* __restrict__ qh, __half* __restrict__ ql)
{
    int t = blockIdx.x;
    const float SC = 0.07216878364870323f * 1.4426950408889634f;
    for (int idx = threadIdx.x; idx < H_HEADS * D_QK; idx += 256) {
        int c = idx % D_QK;
        const float* qr = q + (size_t)t * 3072 + (idx - c);
        float v;
        if (c < D_NOPE) v = qr[c];
        else {
            int i = c - D_NOPE;
            if (i < 32) v = qr[c] * ct[t * 32 + i] - qr[c + 32] * st[t * 32 + i];
            else { int j = i - 32; v = qr[c] * ct[t * 32 + j] + qr[c - 32] * st[t * 32 + j]; }
        }
        v *= SC;
        __half hv = __float2half(v);
        qh[(size_t)t * 3072 + idx] = hv;
        ql[(size_t)t * 3072 + idx] = __float2half(v - __half2float(hv));
    }
}

// ---------------- k/v prep: K single fp16 plane + V fp16 --------------------
__global__ __launch_bounds__(256) void kprep_kernel(
    const float* __restrict__ kv, const float* __restrict__ kpe,
    __half* __restrict__ kf, __half* __restrict__ vf)
{
    int t = blockIdx.x;
    for (int idx = threadIdx.x; idx < H_HEADS * D_QK; idx += 256) {
        int hh = idx / D_QK, c = idx % D_QK;
        float v = (c < D_NOPE) ? kv[((size_t)t * H_HEADS + hh) * KV_W + c]
                               : kpe[(size_t)t * D_ROPE + (c - D_NOPE)];
        kf[(size_t)t * 3072 + idx] = __float2half(v);
    }
    for (int idx = threadIdx.x; idx < H_HEADS * D_V; idx += 256) {
        int hh = idx / D_V, d = idx % D_V;
        vf[(size_t)t * 2048 + idx] =
            __float2half(kv[((size_t)t * H_HEADS + hh) * KV_W + D_NOPE + d]);
    }
}

// ---------------- tensor-core causal flash attention ------------------------
// BM=128, BN=64, 256 threads. Q fp16 hi/lo (exact); K single fp16; V fp16.
// smem: Qh(49152) Ql(49152) + 2 stages of [Kf 24576 | V 16384] = 180224 B
#define ATT_SMEM (98304 + 2 * 40960)

__global__ __launch_bounds__(256, 1) void attn_mma_kernel(
    const __half* __restrict__ qh, const __half* __restrict__ ql,
    const __half* __restrict__ kf, const __half* __restrict__ vf,
    __half* __restrict__ of)
{
    extern __shared__ char smr[];
    char* sQh = smr;
    char* sQl = smr + 49152;

    const int tid = threadIdx.x, lane = tid & 31, w = tid >> 5;
    const int b  = gridDim.x - 1 - blockIdx.x;
    const int q0 = b * 128;
    const int h  = blockIdx.y;
    const int niter = (q0 + 128) >> 6;

    for (int idx = tid; idx < 128 * 24; idx += 256) {
        int r = idx / 24, c = idx % 24;
        int sw = ((c ^ (r & 7)) << 4);
        size_t g = ((size_t)(q0 + r) * H_HEADS + h) * D_QK + c * 8;
        cp_async16(sQh + r * 384 + sw, qh + g);
        cp_async16(sQl + r * 384 + sw, ql + g);
    }

    auto load_stage = [&](int st, int s0) {
        char* base = smr + 98304 + st * 40960;
        char* sKf = base, *sV = base + 24576;
        for (int idx = tid; idx < 64 * 24; idx += 256) {
            int r = idx / 24, c = idx % 24;
            int sw = ((c ^ (r & 7)) << 4);
            size_t g = ((size_t)(s0 + r) * H_HEADS + h) * D_QK + c * 8;
            cp_async16(sKf + r * 384 + sw, kf + g);
        }
        for (int idx = tid; idx < 64 * 16; idx += 256) {
            int r = idx / 16, c = idx % 16;
            int sw = ((c ^ (r & 7)) << 4);
            cp_async16(sV + r * 256 + sw,
                       vf + ((size_t)(s0 + r) * H_HEADS + h) * D_V + c * 8);
        }
    };

    load_stage(0, 0);
    cp_commit();

    float m0 = -1e30f, m1 = -1e30f, l0 = 0.f, l1 = 0.f;
    float oacc[16][4];
#pragma unroll
    for (int i = 0; i < 16; i++)
#pragma unroll
        for (int j = 0; j < 4; j++) oacc[i][j] = 0.f;

    for (int it = 0; it < niter; it++) {
        const int s0 = it * 64;
        if (it + 1 < niter) { load_stage((it + 1) & 1, s0 + 64); cp_commit(); }
        if (it + 1 < niter) asm volatile("cp.async.wait_group 1;\n");
        else                asm volatile("cp.async.wait_group 0;\n");
        __syncthreads();

        char* base = smr + 98304 + (it & 1) * 40960;
        char* sKf = base, *sV = base + 24576;

        // ---- S = Q K^T (Q exact 2-plane fp16, K single fp16: 2 mma) ----
        float sacc[8][4];
#pragma unroll
        for (int i = 0; i < 8; i++)
#pragma unroll
            for (int j = 0; j < 4; j++) sacc[i][j] = 0.f;

#pragma unroll
        for (int kk = 0; kk < 12; kk++) {
            unsigned ah[4], al[4];
            {
                int r = 16 * w + (lane & 15);
                int cc = 2 * kk + (lane >> 4);
                unsigned qa = smem_u32(sQh + r * 384 + (((cc ^ (r & 7)) << 4)));
                unsigned qb = smem_u32(sQl + r * 384 + (((cc ^ (r & 7)) << 4)));
                asm volatile("ldmatrix.sync.aligned.m8n8.x4.shared.b16 {%0,%1,%2,%3}, [%4];"
                    : "=r"(ah[0]), "=r"(ah[1]), "=r"(ah[2]), "=r"(ah[3]) : "r"(qa));
                asm volatile("ldmatrix.sync.aligned.m8n8.x4.shared.b16 {%0,%1,%2,%3}, [%4];"
                    : "=r"(al[0]), "=r"(al[1]), "=r"(al[2]), "=r"(al[3]) : "r"(qb));
            }
#pragma unroll
            for (int nt = 0; nt < 8; nt++) {
                unsigned bf[2];
                int rK = nt * 8 + (lane & 7);
                int cc = 2 * kk + ((lane & 15) >> 3);
                unsigned ka = smem_u32(sKf + rK * 384 + (((cc ^ (rK & 7)) << 4)));
                asm volatile("ldmatrix.sync.aligned.m8n8.x2.shared.b16 {%0,%1}, [%2];"
                    : "=r"(bf[0]), "=r"(bf[1]) : "r"(ka));
                float* d = sacc[nt];
                MMA_F16(d, ah, bf);
                MMA_F16(d, al, bf);
            }
        }

        if (s0 + 64 > q0) {
            int row0 = q0 + 16 * w + (lane >> 2);
#pragma unroll
            for (int nt = 0; nt < 8; nt++) {
                int c = s0 + nt * 8 + (lane & 3) * 2;
                if (c     > row0)     sacc[nt][0] = -1e30f;
                if (c + 1 > row0)     sacc[nt][1] = -1e30f;
                if (c     > row0 + 8) sacc[nt][2] = -1e30f;
                if (c + 1 > row0 + 8) sacc[nt][3] = -1e30f;
            }
        }

        float mx0 = -1e30f, mx1 = -1e30f;
#pragma unroll
        for (int nt = 0; nt < 8; nt++) {
            mx0 = fmaxf(mx0, fmaxf(sacc[nt][0], sacc[nt][1]));
            mx1 = fmaxf(mx1, fmaxf(sacc[nt][2], sacc[nt][3]));
        }
        mx0 = fmaxf(mx0, __shfl_xor_sync(0xffffffffu, mx0, 1));
        mx0 = fmaxf(mx0, __shfl_xor_sync(0xffffffffu, mx0, 2));
        mx1 = fmaxf(mx1, __shfl_xor_sync(0xffffffffu, mx1, 1));
        mx1 = fmaxf(mx1, __shfl_xor_sync(0xffffffffu, mx1, 2));
        float mn0 = fmaxf(m0, mx0), mn1 = fmaxf(m1, mx1);
        float a0 = ex2f(m0 - mn0), a1 = ex2f(m1 - mn1);
        m0 = mn0; m1 = mn1;
        float ps0 = 0.f, ps1 = 0.f;
#pragma unroll
        for (int nt = 0; nt < 8; nt++) {
            float p0 = ex2f(sacc[nt][0] - mn0);
            float p1 = ex2f(sacc[nt][1] - mn0);
            float p2 = ex2f(sacc[nt][2] - mn1);
            float p3 = ex2f(sacc[nt][3] - mn1);
            sacc[nt][0] = p0; sacc[nt][1] = p1; sacc[nt][2] = p2; sacc[nt][3] = p3;
            ps0 += p0 + p1; ps1 += p2 + p3;
        }
        ps0 += __shfl_xor_sync(0xffffffffu, ps0, 1);
        ps0 += __shfl_xor_sync(0xffffffffu, ps0, 2);
        ps1 += __shfl_xor_sync(0xffffffffu, ps1, 1);
        ps1 += __shfl_xor_sync(0xffffffffu, ps1, 2);
        l0 = l0 * a0 + ps0;
        l1 = l1 * a1 + ps1;
#pragma unroll
        for (int nd = 0; nd < 16; nd++) {
            oacc[nd][0] *= a0; oacc[nd][1] *= a0;
            oacc[nd][2] *= a1; oacc[nd][3] *= a1;
        }

        unsigned pa[4][4];
#pragma unroll
        for (int k2 = 0; k2 < 4; k2++) {
            pa[k2][0] = pack_h2(sacc[2 * k2][0],     sacc[2 * k2][1]);
            pa[k2][1] = pack_h2(sacc[2 * k2][2],     sacc[2 * k2][3]);
            pa[k2][2] = pack_h2(sacc[2 * k2 + 1][0], sacc[2 * k2 + 1][1]);
            pa[k2][3] = pack_h2(sacc[2 * k2 + 1][2], sacc[2 * k2 + 1][3]);
        }

#pragma unroll
        for (int k2 = 0; k2 < 4; k2++) {
            int rV = k2 * 16 + (lane & 15);
#pragma unroll
            for (int nd = 0; nd < 16; nd++) {
                unsigned vb[2];
                unsigned va = smem_u32(sV + rV * 256 + (((nd ^ (rV & 7)) << 4)));
                asm volatile("ldmatrix.sync.aligned.m8n8.x2.trans.shared.b16 {%0,%1}, [%2];"
                    : "=r"(vb[0]), "=r"(vb[1]) : "r"(va));
                float* d = oacc[nd];
                MMA_F16(d, pa[k2], vb);
            }
        }
        __syncthreads();
    }

    // epilogue: normalize + write single fp16 plane (Wo GEMM A operand)
    float il0 = 1.f / l0, il1 = 1.f / l1;
    int r0 = q0 + 16 * w + (lane >> 2);
    int cb = h * D_V + (lane & 3) * 2;
#pragma unroll
    for (int nd = 0; nd < 16; nd++) {
        size_t p0 = (size_t)r0 * 2048 + cb + nd * 8;
        size_t p1 = (size_t)(r0 + 8) * 2048 + cb + nd * 8;
        *(__half2*)&of[p0] = __floats2half2_rn(oacc[nd][0] * il0, oacc[nd][1] * il0);
        *(__half2*)&of[p1] = __floats2half2_rn(oacc[nd][2] * il1, oacc[nd][3] * il1);
    }
}

// ---------------- launch ---------------------------------------------------
static inline void hgemm2(const __half* Ah, const __half* Al, const __half* Bf,
                          float* C, int M, int Nc, int Nb, int K) {
    cudaFuncSetAttribute(hgemm_kernel<2>, cudaFuncAttributeMaxDynamicSharedMemorySize, 3 * 29184);
    hgemm_kernel<2><<<dim3(Nb / 128, M / 128), 256, 3 * 29184>>>(Ah, Al, Bf, C, M, Nc, Nb, K);
}
static inline void hgemm1(const __half* Af, const __half* Bf,
                          float* C, int M, int Nc, int Nb, int K) {
    cudaFuncSetAttribute(hgemm_kernel<1>, cudaFuncAttributeMaxDynamicSharedMemorySize, 3 * 18944);
    hgemm_kernel<1><<<dim3(Nb / 128, M / 128), 256, 3 * 18944>>>(Af, Af, Bf, C, M, Nc, Nb, K);
}

extern "C" void kernel_launch(void* const* d_in, const int* in_sizes, int n_in,
                              void* d_out, int out_size)
{
    const int*   positions = (const int*)d_in[0];
    const float* hidden    = (const float*)d_in[1];
    const float* Wq        = (const float*)d_in[2];
    const float* Wkva      = (const float*)d_in[3];
    const float* lnw       = (const float*)d_in[4];
    const float* Wkvb      = (const float*)d_in[5];
    const float* Wo        = (const float*)d_in[6];
    float* out = (float*)d_out;

    float *q, *latent, *kpe, *kv, *tcos, *tsin;
    cudaGetSymbolAddress((void**)&q,      g_q);
    cudaGetSymbolAddress((void**)&latent, g_latent);
    cudaGetSymbolAddress((void**)&kpe,    g_kpe);
    cudaGetSymbolAddress((void**)&kv,     g_kv);
    cudaGetSymbolAddress((void**)&tcos,   g_cos);
    cudaGetSymbolAddress((void**)&tsin,   g_sin);

    __half *hid_h, *hid_l, *kva_h, *kva_l, *attn_f;
    __half *Wq_f, *Wkva_f, *Wkvb_f, *Wo_f;
    __half *qah, *qal, *kaf, *vaf;
    cudaGetSymbolAddress((void**)&hid_h,  g_hid_h);
    cudaGetSymbolAddress((void**)&hid_l,  g_hid_l);
    cudaGetSymbolAddress((void**)&kva_h,  g_kva_h);
    cudaGetSymbolAddress((void**)&kva_l,  g_kva_l);
    cudaGetSymbolAddress((void**)&attn_f, g_attn_f);
    cudaGetSymbolAddress((void**)&Wq_f,   g_Wq_f);
    cudaGetSymbolAddress((void**)&Wkva_f, g_Wkva_f);
    cudaGetSymbolAddress((void**)&Wkvb_f, g_Wkvb_f);
    cudaGetSymbolAddress((void**)&Wo_f,   g_Wo_f);
    cudaGetSymbolAddress((void**)&qah,    g_qah);
    cudaGetSymbolAddress((void**)&qal,    g_qal);
    cudaGetSymbolAddress((void**)&kaf,    g_kaf);
    cudaGetSymbolAddress((void**)&vaf,    g_vaf);

    rope_table_kernel<<<T_TOK, 32>>>(positions, tcos, tsin);

    hsplit_kernel<<<(T_TOK * HID + 255) / 256, 256>>>(hidden, hid_h, hid_l, T_TOK * HID);
    wconv_kernel<<<(2048 * 3072 + 255) / 256, 256>>>(Wq,   Wq_f,   3072, 3072, 2048 * 3072);
    wconv_kernel<<<(2048 * 640  + 255) / 256, 256>>>(Wkva, Wkva_f, 576,  640,  2048 * 640);

    // 1. q = hidden @ Wq  (2-term A: exact)
    hgemm2(hid_h, hid_l, Wq_f, q, T_TOK, 3072, 3072, HID);
    // 2. latent = hidden @ Wkva
    hgemm2(hid_h, hid_l, Wkva_f, latent, T_TOK, 576, 640, HID);
    // 3. rmsnorm (fp16 hi/lo out) + k_pe rope
    rmsnorm_ropek_kernel<<<T_TOK, 256>>>(latent, lnw, tcos, tsin, kva_h, kva_l, kpe);
    // 4. kv = kv_a @ Wkvb
    wconv_kernel<<<(512 * 4096 + 255) / 256, 256>>>(Wkvb, Wkvb_f, 4096, 4096, 512 * 4096);
    hgemm2(kva_h, kva_l, Wkvb_f, kv, T_TOK, 4096, 4096, L_KV);
    // 5. attention operand prep
    qprep_kernel<<<T_TOK, 256>>>(q, tcos, tsin, qah, qal);
    kprep_kernel<<<T_TOK, 256>>>(kv, kpe, kaf, vaf);
    // 6. tensor-core causal attention (QK: 2 mma; single fp16 epilogue)
    cudaFuncSetAttribute(attn_mma_kernel, cudaFuncAttributeMaxDynamicSharedMemorySize, ATT_SMEM);
    attn_mma_kernel<<<dim3(T_TOK / 128, H_HEADS), 256, ATT_SMEM>>>(
        qah, qal, kaf, vaf, attn_f);
    // 7. out = attn @ Wo  (1-term A)
    wconv_kernel<<<(2048 * 2048 + 255) / 256, 256>>>(Wo, Wo_f, 2048, 2048, 2048 * 2048);
    hgemm1(attn_f, Wo_f, out, T_TOK, 2048, 2048, 2048);
}

// round 13
// speedup vs baseline: 6.9770x; 1.0676x over previous
#include <cuda_runtime.h>
#include <cuda_bf16.h>
#include <cuda_fp16.h>
#include <math.h>
#include <stdint.h>
#include <cstdint>

#define T_TOK   4096
#define HID     2048
#define H_HEADS 16
#define D_NOPE  128
#define D_ROPE  64
#define D_V     128
#define L_KV    512
#define D_QK    192
#define KV_W    256

// ---------------- scratch (device globals) ---------------------------------
__device__ float g_q[(size_t)T_TOK * H_HEADS * D_QK];
__device__ float g_latent[(size_t)T_TOK * (L_KV + D_ROPE)];
__device__ float g_kpe[(size_t)T_TOK * D_ROPE];
__device__ float g_kv[(size_t)T_TOK * H_HEADS * KV_W];

__device__ float g_cos[(size_t)T_TOK * 32];
__device__ float g_sin[(size_t)T_TOK * 32];

// A-side activations: fp16 hi/lo (exact 2-term representation)
__device__ __half g_hid_h [(size_t)T_TOK * HID];
__device__ __half g_hid_l [(size_t)T_TOK * HID];
__device__ __half g_kva_h [(size_t)T_TOK * L_KV];
__device__ __half g_kva_l [(size_t)T_TOK * L_KV];
__device__ __half g_attn_f[(size_t)T_TOK * 2048];   // single plane (Wo GEMM A)

// B-side weights: single fp16 plane
__device__ __half g_Wq_f  [(size_t)2048 * 3072];
__device__ __half g_Wkva_f[(size_t)2048 * 640];   // N=576 padded to 640
__device__ __half g_Wkvb_f[(size_t)512 * 4096];
__device__ __half g_Wo_f  [(size_t)2048 * 2048];

// attention operand buffers (fp16, single plane each)
__device__ __half g_qaf[(size_t)T_TOK * H_HEADS * D_QK];
__device__ __half g_kaf[(size_t)T_TOK * H_HEADS * D_QK];
__device__ __half g_vaf[(size_t)T_TOK * H_HEADS * D_V];

static __device__ __forceinline__ unsigned smem_u32(const void* p) {
    return (unsigned)__cvta_generic_to_shared(p);
}
static __device__ __forceinline__ void cp_async16(void* dst, const void* src) {
    asm volatile("cp.async.cg.shared.global [%0], [%1], 16;\n"
                 :: "r"(smem_u32(dst)), "l"(src));
}
static __device__ __forceinline__ void cp_commit() {
    asm volatile("cp.async.commit_group;\n");
}
static __device__ __forceinline__ unsigned pack_h2(float a, float b) {
    __half2 h = __floats2half2_rn(a, b);
    return *(unsigned*)&h;
}
static __device__ __forceinline__ float ex2f(float x) {
    float r;
    asm("ex2.approx.ftz.f32 %0, %1;" : "=f"(r) : "f"(x));
    return r;
}

#define MMA_F16(D, A, B)                                                     \
    asm volatile(                                                            \
        "mma.sync.aligned.m16n8k16.row.col.f32.f16.f16.f32 "                 \
        "{%0,%1,%2,%3}, {%4,%5,%6,%7}, {%8,%9}, {%0,%1,%2,%3};"              \
        : "+f"(D[0]), "+f"(D[1]), "+f"(D[2]), "+f"(D[3])                     \
        : "r"(A[0]), "r"(A[1]), "r"(A[2]), "r"(A[3]), "r"(B[0]), "r"(B[1]))

// ---------------- rope table ------------------------------------------------
__global__ __launch_bounds__(32) void rope_table_kernel(
    const int* __restrict__ positions, float* __restrict__ ct, float* __restrict__ st)
{
    int t = blockIdx.x, i = threadIdx.x;
    double pos  = (double)positions[t];
    double freq = pow(10000.0, -(double)i / 32.0);
    double ang  = pos * freq;
    ct[t * 32 + i] = (float)cos(ang);
    st[t * 32 + i] = (float)sin(ang);
}

// ---------------- fp32 -> fp16 hi/lo split ----------------------------------
__global__ __launch_bounds__(256) void hsplit_kernel(
    const float* __restrict__ x, __half* __restrict__ hi,
    __half* __restrict__ lo, int n)
{
    int i = blockIdx.x * 256 + threadIdx.x;
    if (i < n) {
        float v = x[i];
        __half h = __float2half(v);
        hi[i] = h;
        lo[i] = __float2half(v - __half2float(h));
    }
}

// ---------------- fp32 weight [K,N] -> fp16 [K,Npad] (zero pad) -------------
__global__ __launch_bounds__(256) void wconv_kernel(
    const float* __restrict__ X, __half* __restrict__ Y,
    int N, int Npad, int total)
{
    int i = blockIdx.x * 256 + threadIdx.x;
    if (i < total) {
        int r = i / Npad, c = i % Npad;
        Y[i] = __float2half(c < N ? X[(size_t)r * N + c] : 0.f);
    }
}

// ---------------- fp16 tensor-core GEMM (TERMS = 1 or 2 A planes) -----------
// C[M,Nc] = A[M,K] @ Bf[K,Nb]; 128x128x32 tile, 256 threads, 3-stage cp.async.
// stage: Ah(10240B) [| Al(10240B)] | B(8704B)
template <int TERMS>
__global__ __launch_bounds__(256) void hgemm_kernel(
    const __half* __restrict__ Ah, const __half* __restrict__ Al,
    const __half* __restrict__ Bf, float* __restrict__ C,
    int M, int Nc, int Nb, int K)
{
    constexpr int BOFF = TERMS * 10240;
    constexpr int STG  = BOFF + 8704;
    extern __shared__ char smr[];
    const int tid = threadIdx.x, lane = tid & 31, wid = tid >> 5;
    const int row0 = blockIdx.y * 128;
    const int col0 = blockIdx.x * 128;
    const int wm0  = (wid & 1) * 64;
    const int wn0  = (wid >> 1) * 32;
    const int nkc  = K >> 5;

    float acc[4][4][4];
#pragma unroll
    for (int a = 0; a < 4; a++)
#pragma unroll
        for (int b = 0; b < 4; b++)
#pragma unroll
            for (int c = 0; c < 4; c++) acc[a][b][c] = 0.f;

    auto load_stage = [&](int st, int kb) {
        char* base = smr + st * STG;
#pragma unroll
        for (int j = 0; j < 2; j++) {
            int idx = tid + j * 256;
            int r = idx >> 2, c = idx & 3;
            size_t g = (size_t)(row0 + r) * K + kb + c * 8;
            cp_async16(base + r * 80 + c * 16, Ah + g);
            if (TERMS == 2)
                cp_async16(base + 10240 + r * 80 + c * 16, Al + g);
        }
#pragma unroll
        for (int j = 0; j < 2; j++) {
            int idx = tid + j * 256;
            int r = idx >> 4, c = idx & 15;
            size_t g = (size_t)(kb + r) * Nb + col0 + c * 8;
            cp_async16(base + BOFF + r * 272 + c * 16, Bf + g);
        }
        cp_commit();
    };

    load_stage(0, 0);
    if (nkc > 1) load_stage(1, 32);
    if (nkc > 2) load_stage(2, 64);

    for (int i = 0; i < nkc; i++) {
        int pend = nkc - 1 - i;
        if (pend >= 2)      asm volatile("cp.async.wait_group 2;\n" ::: "memory");
        else if (pend == 1) asm volatile("cp.async.wait_group 1;\n" ::: "memory");
        else                asm volatile("cp.async.wait_group 0;\n" ::: "memory");
        __syncthreads();

        char* base = smr + (i % 3) * STG;
#pragma unroll
        for (int ks = 0; ks < 32; ks += 16) {
            unsigned fah[4][4], fal[4][4], fb[4][2];
            {
                int r = lane & 15, seg = lane >> 4;
#pragma unroll
                for (int mt = 0; mt < 4; mt++) {
                    unsigned a0 = smem_u32(base + (wm0 + mt * 16 + r) * 80 + (ks + seg * 8) * 2);
                    asm volatile("ldmatrix.sync.aligned.m8n8.x4.shared.b16 {%0,%1,%2,%3}, [%4];"
                        : "=r"(fah[mt][0]), "=r"(fah[mt][1]), "=r"(fah[mt][2]), "=r"(fah[mt][3]) : "r"(a0));
                    if (TERMS == 2) {
                        unsigned a1 = smem_u32(base + 10240 + (wm0 + mt * 16 + r) * 80 + (ks + seg * 8) * 2);
                        asm volatile("ldmatrix.sync.aligned.m8n8.x4.shared.b16 {%0,%1,%2,%3}, [%4];"
                            : "=r"(fal[mt][0]), "=r"(fal[mt][1]), "=r"(fal[mt][2]), "=r"(fal[mt][3]) : "r"(a1));
                    }
                }
            }
            {
                int l = lane & 15;
#pragma unroll
                for (int nt = 0; nt < 4; nt++) {
                    unsigned b0 = smem_u32(base + BOFF + (ks + l) * 272 + (wn0 + nt * 8) * 2);
                    asm volatile("ldmatrix.sync.aligned.m8n8.x2.trans.shared.b16 {%0,%1}, [%2];"
                        : "=r"(fb[nt][0]), "=r"(fb[nt][1]) : "r"(b0));
                }
            }
#pragma unroll
            for (int mt = 0; mt < 4; mt++)
#pragma unroll
                for (int nt = 0; nt < 4; nt++) { float* d = acc[mt][nt]; MMA_F16(d, fah[mt], fb[nt]); }
            if (TERMS == 2) {
#pragma unroll
                for (int mt = 0; mt < 4; mt++)
#pragma unroll
                    for (int nt = 0; nt < 4; nt++) { float* d = acc[mt][nt]; MMA_F16(d, fal[mt], fb[nt]); }
            }
        }
        __syncthreads();
        if (i + 3 < nkc) load_stage(i % 3, (i + 3) * 32);
    }

#pragma unroll
    for (int mt = 0; mt < 4; mt++) {
        int gr = row0 + wm0 + mt * 16 + (lane >> 2);
#pragma unroll
        for (int nt = 0; nt < 4; nt++) {
            int gc = col0 + wn0 + nt * 8 + (lane & 3) * 2;
            if (gc < Nc) {
                *(float2*)&C[(size_t)gr * Nc + gc]       = make_float2(acc[mt][nt][0], acc[mt][nt][1]);
                *(float2*)&C[(size_t)(gr + 8) * Nc + gc] = make_float2(acc[mt][nt][2], acc[mt][nt][3]);
            }
        }
    }
}

// ---------------- rmsnorm + k_pe rope (writes fp16 hi/lo kva) ---------------
__global__ __launch_bounds__(256) void rmsnorm_ropek_kernel(
    const float* __restrict__ latent, const float* __restrict__ w,
    const float* __restrict__ ct, const float* __restrict__ st,
    __half* __restrict__ kvah, __half* __restrict__ kval, float* __restrict__ kpe)
{
    int t = blockIdx.x;
    const float* x = latent + (size_t)t * (L_KV + D_ROPE);
    __shared__ float red[256];
    float ss = 0.f;
    for (int i = threadIdx.x; i < L_KV; i += 256) { float v = x[i]; ss += v * v; }
    red[threadIdx.x] = ss;
    __syncthreads();
    for (int s = 128; s > 0; s >>= 1) {
        if (threadIdx.x < s) red[threadIdx.x] += red[threadIdx.x + s];
        __syncthreads();
    }
    float inv = rsqrtf(red[0] / (float)L_KV + 1e-6f);
    for (int i = threadIdx.x; i < L_KV; i += 256) {
        float y = x[i] * inv * w[i];
        __half hh = __float2half(y);
        kvah[(size_t)t * L_KV + i] = hh;
        kval[(size_t)t * L_KV + i] = __float2half(y - __half2float(hh));
    }
    if (threadIdx.x < 32) {
        int i = threadIdx.x;
        float c = ct[t * 32 + i], s = st[t * 32 + i];
        float x1 = x[L_KV + i], x2 = x[L_KV + 32 + i];
        kpe[(size_t)t * D_ROPE + i]      = x1 * c - x2 * s;
        kpe[(size_t)t * D_ROPE + 32 + i] = x2 * c + x1 * s;
    }
}

// ---------------- q prep: rope + scale -> single fp16 plane -----------------
__global__ __launch_bounds__(256) void qprep_kernel(
    const float* __restrict__ q, const float* __restrict__ ct, const float* __restrict__ st,
    __half* __restrict__ qf)
{
    int t = blockIdx.x;
    const float SC = 0.07216878364870323f * 1.4426950408889634f;
    for (int idx = threadIdx.x; idx < H_HEADS * D_QK; idx += 256) {
        int c = idx % D_QK;
        const float* qr = q + (size_t)t * 3072 + (idx - c);
        float v;
        if (c < D_NOPE) v = qr[c];
        else {
            int i = c - D_NOPE;
            if (i < 32) v = qr[c] * ct[t * 32 + i] - qr[c + 32] * st[t * 32 + i];
            else { int j = i - 32; v = qr[c] * ct[t * 32 + j] + qr[c - 32] * st[t * 32 + j]; }
        }
        qf[(size_t)t * 3072 + idx] = __float2half(v * SC);
    }
}

// ---------------- k/v prep: K single fp16 plane + V fp16 --------------------
__global__ __launch_bounds__(256) void kprep_kernel(
    const float* __restrict__ kv, const float* __restrict__ kpe,
    __half* __restrict__ kf, __half* __restrict__ vf)
{
    int t = blockIdx.x;
    for (int idx = threadIdx.x; idx < H_HEADS * D_QK; idx += 256) {
        int hh = idx / D_QK, c = idx % D_QK;
        float v = (c < D_NOPE) ? kv[((size_t)t * H_HEADS + hh) * KV_W + c]
                               : kpe[(size_t)t * D_ROPE + (c - D_NOPE)];
        kf[(size_t)t * 3072 + idx] = __float2half(v);
    }
    for (int idx = threadIdx.x; idx < H_HEADS * D_V; idx += 256) {
        int hh = idx / D_V, d = idx % D_V;
        vf[(size_t)t * 2048 + idx] =
            __float2half(kv[((size_t)t * H_HEADS + hh) * KV_W + D_NOPE + d]);
    }
}

// ---------------- tensor-core causal flash attention ------------------------
// BM=128, BN=64, 256 threads. Q, K, V all single fp16 planes.
// smem: Qf(49152) + 2 stages of [Kf 24576 | V 16384] = 131072 B
#define ATT_SMEM (49152 + 2 * 40960)

__global__ __launch_bounds__(256, 1) void attn_mma_kernel(
    const __half* __restrict__ qf, const __half* __restrict__ kf,
    const __half* __restrict__ vf, __half* __restrict__ of)
{
    extern __shared__ char smr[];
    char* sQf = smr;

    const int tid = threadIdx.x, lane = tid & 31, w = tid >> 5;
    const int b  = gridDim.x - 1 - blockIdx.x;
    const int q0 = b * 128;
    const int h  = blockIdx.y;
    const int niter = (q0 + 128) >> 6;

    for (int idx = tid; idx < 128 * 24; idx += 256) {
        int r = idx / 24, c = idx % 24;
        int sw = ((c ^ (r & 7)) << 4);
        size_t g = ((size_t)(q0 + r) * H_HEADS + h) * D_QK + c * 8;
        cp_async16(sQf + r * 384 + sw, qf + g);
    }

    auto load_stage = [&](int st, int s0) {
        char* base = smr + 49152 + st * 40960;
        char* sKf = base, *sV = base + 24576;
        for (int idx = tid; idx < 64 * 24; idx += 256) {
            int r = idx / 24, c = idx % 24;
            int sw = ((c ^ (r & 7)) << 4);
            size_t g = ((size_t)(s0 + r) * H_HEADS + h) * D_QK + c * 8;
            cp_async16(sKf + r * 384 + sw, kf + g);
        }
        for (int idx = tid; idx < 64 * 16; idx += 256) {
            int r = idx / 16, c = idx % 16;
            int sw = ((c ^ (r & 7)) << 4);
            cp_async16(sV + r * 256 + sw,
                       vf + ((size_t)(s0 + r) * H_HEADS + h) * D_V + c * 8);
        }
    };

    load_stage(0, 0);
    cp_commit();

    float m0 = -1e30f, m1 = -1e30f, l0 = 0.f, l1 = 0.f;
    float oacc[16][4];
#pragma unroll
    for (int i = 0; i < 16; i++)
#pragma unroll
        for (int j = 0; j < 4; j++) oacc[i][j] = 0.f;

    for (int it = 0; it < niter; it++) {
        const int s0 = it * 64;
        if (it + 1 < niter) { load_stage((it + 1) & 1, s0 + 64); cp_commit(); }
        if (it + 1 < niter) asm volatile("cp.async.wait_group 1;\n");
        else                asm volatile("cp.async.wait_group 0;\n");
        __syncthreads();

        char* base = smr + 49152 + (it & 1) * 40960;
        char* sKf = base, *sV = base + 24576;

        // ---- S = Q K^T (single fp16 planes: 1 mma) ----
        float sacc[8][4];
#pragma unroll
        for (int i = 0; i < 8; i++)
#pragma unroll
            for (int j = 0; j < 4; j++) sacc[i][j] = 0.f;

#pragma unroll
        for (int kk = 0; kk < 12; kk++) {
            unsigned ah[4];
            {
                int r = 16 * w + (lane & 15);
                int cc = 2 * kk + (lane >> 4);
                unsigned qa = smem_u32(sQf + r * 384 + (((cc ^ (r & 7)) << 4)));
                asm volatile("ldmatrix.sync.aligned.m8n8.x4.shared.b16 {%0,%1,%2,%3}, [%4];"
                    : "=r"(ah[0]), "=r"(ah[1]), "=r"(ah[2]), "=r"(ah[3]) : "r"(qa));
            }
#pragma unroll
            for (int nt = 0; nt < 8; nt++) {
                unsigned bf[2];
                int rK = nt * 8 + (lane & 7);
                int cc = 2 * kk + ((lane & 15) >> 3);
                unsigned ka = smem_u32(sKf + rK * 384 + (((cc ^ (rK & 7)) << 4)));
                asm volatile("ldmatrix.sync.aligned.m8n8.x2.shared.b16 {%0,%1}, [%2];"
                    : "=r"(bf[0]), "=r"(bf[1]) : "r"(ka));
                float* d = sacc[nt];
                MMA_F16(d, ah, bf);
            }
        }

        if (s0 + 64 > q0) {
            int row0 = q0 + 16 * w + (lane >> 2);
#pragma unroll
            for (int nt = 0; nt < 8; nt++) {
                int c = s0 + nt * 8 + (lane & 3) * 2;
                if (c     > row0)     sacc[nt][0] = -1e30f;
                if (c + 1 > row0)     sacc[nt][1] = -1e30f;
                if (c     > row0 + 8) sacc[nt][2] = -1e30f;
                if (c + 1 > row0 + 8) sacc[nt][3] = -1e30f;
            }
        }

        float mx0 = -1e30f, mx1 = -1e30f;
#pragma unroll
        for (int nt = 0; nt < 8; nt++) {
            mx0 = fmaxf(mx0, fmaxf(sacc[nt][0], sacc[nt][1]));
            mx1 = fmaxf(mx1, fmaxf(sacc[nt][2], sacc[nt][3]));
        }
        mx0 = fmaxf(mx0, __shfl_xor_sync(0xffffffffu, mx0, 1));
        mx0 = fmaxf(mx0, __shfl_xor_sync(0xffffffffu, mx0, 2));
        mx1 = fmaxf(mx1, __shfl_xor_sync(0xffffffffu, mx1, 1));
        mx1 = fmaxf(mx1, __shfl_xor_sync(0xffffffffu, mx1, 2));
        float mn0 = fmaxf(m0, mx0), mn1 = fmaxf(m1, mx1);
        float a0 = ex2f(m0 - mn0), a1 = ex2f(m1 - mn1);
        m0 = mn0; m1 = mn1;
        float ps0 = 0.f, ps1 = 0.f;
#pragma unroll
        for (int nt = 0; nt < 8; nt++) {
            float p0 = ex2f(sacc[nt][0] - mn0);
            float p1 = ex2f(sacc[nt][1] - mn0);
            float p2 = ex2f(sacc[nt][2] - mn1);
            float p3 = ex2f(sacc[nt][3] - mn1);
            sacc[nt][0] = p0; sacc[nt][1] = p1; sacc[nt][2] = p2; sacc[nt][3] = p3;
            ps0 += p0 + p1; ps1 += p2 + p3;
        }
        ps0 += __shfl_xor_sync(0xffffffffu, ps0, 1);
        ps0 += __shfl_xor_sync(0xffffffffu, ps0, 2);
        ps1 += __shfl_xor_sync(0xffffffffu, ps1, 1);
        ps1 += __shfl_xor_sync(0xffffffffu, ps1, 2);
        l0 = l0 * a0 + ps0;
        l1 = l1 * a1 + ps1;
#pragma unroll
        for (int nd = 0; nd < 16; nd++) {
            oacc[nd][0] *= a0; oacc[nd][1] *= a0;
            oacc[nd][2] *= a1; oacc[nd][3] *= a1;
        }

        unsigned pa[4][4];
#pragma unroll
        for (int k2 = 0; k2 < 4; k2++) {
            pa[k2][0] = pack_h2(sacc[2 * k2][0],     sacc[2 * k2][1]);
            pa[k2][1] = pack_h2(sacc[2 * k2][2],     sacc[2 * k2][3]);
            pa[k2][2] = pack_h2(sacc[2 * k2 + 1][0], sacc[2 * k2 + 1][1]);
            pa[k2][3] = pack_h2(sacc[2 * k2 + 1][2], sacc[2 * k2 + 1][3]);
        }

#pragma unroll
        for (int k2 = 0; k2 < 4; k2++) {
            int rV = k2 * 16 + (lane & 15);
#pragma unroll
            for (int nd = 0; nd < 16; nd++) {
                unsigned vb[2];
                unsigned va = smem_u32(sV + rV * 256 + (((nd ^ (rV & 7)) << 4)));
                asm volatile("ldmatrix.sync.aligned.m8n8.x2.trans.shared.b16 {%0,%1}, [%2];"
                    : "=r"(vb[0]), "=r"(vb[1]) : "r"(va));
                float* d = oacc[nd];
                MMA_F16(d, pa[k2], vb);
            }
        }
        __syncthreads();
    }

    // epilogue: normalize + write single fp16 plane (Wo GEMM A operand)
    float il0 = 1.f / l0, il1 = 1.f / l1;
    int r0 = q0 + 16 * w + (lane >> 2);
    int cb = h * D_V + (lane & 3) * 2;
#pragma unroll
    for (int nd = 0; nd < 16; nd++) {
        size_t p0 = (size_t)r0 * 2048 + cb + nd * 8;
        size_t p1 = (size_t)(r0 + 8) * 2048 + cb + nd * 8;
        *(__half2*)&of[p0] = __floats2half2_rn(oacc[nd][0] * il0, oacc[nd][1] * il0);
        *(__half2*)&of[p1] = __floats2half2_rn(oacc[nd][2] * il1, oacc[nd][3] * il1);
    }
}

// ---------------- launch ---------------------------------------------------
static inline void hgemm2(const __half* Ah, const __half* Al, const __half* Bf,
                          float* C, int M, int Nc, int Nb, int K) {
    cudaFuncSetAttribute(hgemm_kernel<2>, cudaFuncAttributeMaxDynamicSharedMemorySize, 3 * 29184);
    hgemm_kernel<2><<<dim3(Nb / 128, M / 128), 256, 3 * 29184>>>(Ah, Al, Bf, C, M, Nc, Nb, K);
}
static inline void hgemm1(const __half* Af, const __half* Bf,
                          float* C, int M, int Nc, int Nb, int K) {
    cudaFuncSetAttribute(hgemm_kernel<1>, cudaFuncAttributeMaxDynamicSharedMemorySize, 3 * 18944);
    hgemm_kernel<1><<<dim3(Nb / 128, M / 128), 256, 3 * 18944>>>(Af, Af, Bf, C, M, Nc, Nb, K);
}

extern "C" void kernel_launch(void* const* d_in, const int* in_sizes, int n_in,
                              void* d_out, int out_size)
{
    const int*   positions = (const int*)d_in[0];
    const float* hidden    = (const float*)d_in[1];
    const float* Wq        = (const float*)d_in[2];
    const float* Wkva      = (const float*)d_in[3];
    const float* lnw       = (const float*)d_in[4];
    const float* Wkvb      = (const float*)d_in[5];
    const float* Wo        = (const float*)d_in[6];
    float* out = (float*)d_out;

    float *q, *latent, *kpe, *kv, *tcos, *tsin;
    cudaGetSymbolAddress((void**)&q,      g_q);
    cudaGetSymbolAddress((void**)&latent, g_latent);
    cudaGetSymbolAddress((void**)&kpe,    g_kpe);
    cudaGetSymbolAddress((void**)&kv,     g_kv);
    cudaGetSymbolAddress((void**)&tcos,   g_cos);
    cudaGetSymbolAddress((void**)&tsin,   g_sin);

    __half *hid_h, *hid_l, *kva_h, *kva_l, *attn_f;
    __half *Wq_f, *Wkva_f, *Wkvb_f, *Wo_f;
    __half *qaf, *kaf, *vaf;
    cudaGetSymbolAddress((void**)&hid_h,  g_hid_h);
    cudaGetSymbolAddress((void**)&hid_l,  g_hid_l);
    cudaGetSymbolAddress((void**)&kva_h,  g_kva_h);
    cudaGetSymbolAddress((void**)&kva_l,  g_kva_l);
    cudaGetSymbolAddress((void**)&attn_f, g_attn_f);
    cudaGetSymbolAddress((void**)&Wq_f,   g_Wq_f);
    cudaGetSymbolAddress((void**)&Wkva_f, g_Wkva_f);
    cudaGetSymbolAddress((void**)&Wkvb_f, g_Wkvb_f);
    cudaGetSymbolAddress((void**)&Wo_f,   g_Wo_f);
    cudaGetSymbolAddress((void**)&qaf,    g_qaf);
    cudaGetSymbolAddress((void**)&kaf,    g_kaf);
    cudaGetSymbolAddress((void**)&vaf,    g_vaf);

    rope_table_kernel<<<T_TOK, 32>>>(positions, tcos, tsin);

    hsplit_kernel<<<(T_TOK * HID + 255) / 256, 256>>>(hidden, hid_h, hid_l, T_TOK * HID);
    wconv_kernel<<<(2048 * 3072 + 255) / 256, 256>>>(Wq,   Wq_f,   3072, 3072, 2048 * 3072);
    wconv_kernel<<<(2048 * 640  + 255) / 256, 256>>>(Wkva, Wkva_f, 576,  640,  2048 * 640);

    // 1. q = hidden @ Wq  (2-term A: exact)
    hgemm2(hid_h, hid_l, Wq_f, q, T_TOK, 3072, 3072, HID);
    // 2. latent = hidden @ Wkva
    hgemm2(hid_h, hid_l, Wkva_f, latent, T_TOK, 576, 640, HID);
    // 3. rmsnorm (fp16 hi/lo out) + k_pe rope
    rmsnorm_ropek_kernel<<<T_TOK, 256>>>(latent, lnw, tcos, tsin, kva_h, kva_l, kpe);
    // 4. kv = kv_a @ Wkvb
    wconv_kernel<<<(512 * 4096 + 255) / 256, 256>>>(Wkvb, Wkvb_f, 4096, 4096, 512 * 4096);
    hgemm2(kva_h, kva_l, Wkvb_f, kv, T_TOK, 4096, 4096, L_KV);
    // 5. attention operand prep (single planes)
    qprep_kernel<<<T_TOK, 256>>>(q, tcos, tsin, qaf);
    kprep_kernel<<<T_TOK, 256>>>(kv, kpe, kaf, vaf);
    // 6. tensor-core causal attention (QK: 1 mma; fp16 epilogue)
    cudaFuncSetAttribute(attn_mma_kernel, cudaFuncAttributeMaxDynamicSharedMemorySize, ATT_SMEM);
    attn_mma_kernel<<<dim3(T_TOK / 128, H_HEADS), 256, ATT_SMEM>>>(
        qaf, kaf, vaf, attn_f);
    // 7. out = attn @ Wo  (1-term A)
    wconv_kernel<<<(2048 * 2048 + 255) / 256, 256>>>(Wo, Wo_f, 2048, 2048, 2048 * 2048);
    hgemm1(attn_f, Wo_f, out, T_TOK, 2048, 2048, 2048);
}

// round 14
// speedup vs baseline: 8.6514x; 1.2400x over previous
#include <cuda_runtime.h>
#include <cuda_bf16.h>
#include <cuda_fp16.h>
#include <math.h>
#include <stdint.h>
#include <cstdint>

#define T_TOK   4096
#define HID     2048
#define H_HEADS 16
#define D_NOPE  128
#define D_ROPE  64
#define D_V     128
#define L_KV    512
#define D_QK    192
#define KV_W    256

// ---------------- scratch (device globals) ---------------------------------
__device__ float g_q[(size_t)T_TOK * H_HEADS * D_QK];
__device__ float g_latent[(size_t)T_TOK * (L_KV + D_ROPE)];
__device__ float g_kpe[(size_t)T_TOK * D_ROPE];
__device__ float g_kv[(size_t)T_TOK * H_HEADS * KV_W];

__device__ float g_cos[(size_t)T_TOK * 32];
__device__ float g_sin[(size_t)T_TOK * 32];

// activations (fp16). hidden keeps hi/lo (lo used only by Wkva 2-term GEMM).
__device__ __half g_hid_h [(size_t)T_TOK * HID];
__device__ __half g_hid_l [(size_t)T_TOK * HID];
__device__ __half g_kva_f [(size_t)T_TOK * L_KV];    // single plane
__device__ __half g_attn_f[(size_t)T_TOK * 2048];    // single plane

// B-side weights: single fp16 plane
__device__ __half g_Wq_f  [(size_t)2048 * 3072];
__device__ __half g_Wkva_f[(size_t)2048 * 640];   // N=576 padded to 640
__device__ __half g_Wkvb_f[(size_t)512 * 4096];
__device__ __half g_Wo_f  [(size_t)2048 * 2048];

// attention operand buffers (fp16, single plane each)
__device__ __half g_qaf[(size_t)T_TOK * H_HEADS * D_QK];
__device__ __half g_kaf[(size_t)T_TOK * H_HEADS * D_QK];
__device__ __half g_vaf[(size_t)T_TOK * H_HEADS * D_V];

static __device__ __forceinline__ unsigned smem_u32(const void* p) {
    return (unsigned)__cvta_generic_to_shared(p);
}
static __device__ __forceinline__ void cp_async16(void* dst, const void* src) {
    asm volatile("cp.async.cg.shared.global [%0], [%1], 16;\n"
                 :: "r"(smem_u32(dst)), "l"(src));
}
static __device__ __forceinline__ void cp_commit() {
    asm volatile("cp.async.commit_group;\n");
}
static __device__ __forceinline__ unsigned pack_h2(float a, float b) {
    __half2 h = __floats2half2_rn(a, b);
    return *(unsigned*)&h;
}
static __device__ __forceinline__ float ex2f(float x) {
    float r;
    asm("ex2.approx.ftz.f32 %0, %1;" : "=f"(r) : "f"(x));
    return r;
}

#define MMA_F16(D, A, B)                                                     \
    asm volatile(                                                            \
        "mma.sync.aligned.m16n8k16.row.col.f32.f16.f16.f32 "                 \
        "{%0,%1,%2,%3}, {%4,%5,%6,%7}, {%8,%9}, {%0,%1,%2,%3};"              \
        : "+f"(D[0]), "+f"(D[1]), "+f"(D[2]), "+f"(D[3])                     \
        : "r"(A[0]), "r"(A[1]), "r"(A[2]), "r"(A[3]), "r"(B[0]), "r"(B[1]))

// ---------------- rope table ------------------------------------------------
__global__ __launch_bounds__(32) void rope_table_kernel(
    const int* __restrict__ positions, float* __restrict__ ct, float* __restrict__ st)
{
    int t = blockIdx.x, i = threadIdx.x;
    double pos  = (double)positions[t];
    double freq = pow(10000.0, -(double)i / 32.0);
    double ang  = pos * freq;
    ct[t * 32 + i] = (float)cos(ang);
    st[t * 32 + i] = (float)sin(ang);
}

// ---------------- fp32 -> fp16 hi/lo split ----------------------------------
__global__ __launch_bounds__(256) void hsplit_kernel(
    const float* __restrict__ x, __half* __restrict__ hi,
    __half* __restrict__ lo, int n)
{
    int i = blockIdx.x * 256 + threadIdx.x;
    if (i < n) {
        float v = x[i];
        __half h = __float2half(v);
        hi[i] = h;
        lo[i] = __float2half(v - __half2float(h));
    }
}

// ---------------- fp32 weight [K,N] -> fp16 [K,Npad] (zero pad) -------------
__global__ __launch_bounds__(256) void wconv_kernel(
    const float* __restrict__ X, __half* __restrict__ Y,
    int N, int Npad, int total)
{
    int i = blockIdx.x * 256 + threadIdx.x;
    if (i < total) {
        int r = i / Npad, c = i % Npad;
        Y[i] = __float2half(c < N ? X[(size_t)r * N + c] : 0.f);
    }
}

// ---------------- fp16 tensor-core GEMM (TERMS = 1 or 2 A planes) -----------
// C[M,Nc] = A[M,K] @ Bf[K,Nb]; 128x128x32 tile, 256 threads, 3-stage cp.async.
// stage: Ah(10240B) [| Al(10240B)] | B(8704B)
template <int TERMS>
__global__ __launch_bounds__(256) void hgemm_kernel(
    const __half* __restrict__ Ah, const __half* __restrict__ Al,
    const __half* __restrict__ Bf, float* __restrict__ C,
    int M, int Nc, int Nb, int K)
{
    constexpr int BOFF = TERMS * 10240;
    constexpr int STG  = BOFF + 8704;
    extern __shared__ char smr[];
    const int tid = threadIdx.x, lane = tid & 31, wid = tid >> 5;
    const int row0 = blockIdx.y * 128;
    const int col0 = blockIdx.x * 128;
    const int wm0  = (wid & 1) * 64;
    const int wn0  = (wid >> 1) * 32;
    const int nkc  = K >> 5;

    float acc[4][4][4];
#pragma unroll
    for (int a = 0; a < 4; a++)
#pragma unroll
        for (int b = 0; b < 4; b++)
#pragma unroll
            for (int c = 0; c < 4; c++) acc[a][b][c] = 0.f;

    auto load_stage = [&](int st, int kb) {
        char* base = smr + st * STG;
#pragma unroll
        for (int j = 0; j < 2; j++) {
            int idx = tid + j * 256;
            int r = idx >> 2, c = idx & 3;
            size_t g = (size_t)(row0 + r) * K + kb + c * 8;
            cp_async16(base + r * 80 + c * 16, Ah + g);
            if (TERMS == 2)
                cp_async16(base + 10240 + r * 80 + c * 16, Al + g);
        }
#pragma unroll
        for (int j = 0; j < 2; j++) {
            int idx = tid + j * 256;
            int r = idx >> 4, c = idx & 15;
            size_t g = (size_t)(kb + r) * Nb + col0 + c * 8;
            cp_async16(base + BOFF + r * 272 + c * 16, Bf + g);
        }
        cp_commit();
    };

    load_stage(0, 0);
    if (nkc > 1) load_stage(1, 32);
    if (nkc > 2) load_stage(2, 64);

    for (int i = 0; i < nkc; i++) {
        int pend = nkc - 1 - i;
        if (pend >= 2)      asm volatile("cp.async.wait_group 2;\n" ::: "memory");
        else if (pend == 1) asm volatile("cp.async.wait_group 1;\n" ::: "memory");
        else                asm volatile("cp.async.wait_group 0;\n" ::: "memory");
        __syncthreads();

        char* base = smr + (i % 3) * STG;
#pragma unroll
        for (int ks = 0; ks < 32; ks += 16) {
            unsigned fah[4][4], fal[4][4], fb[4][2];
            {
                int r = lane & 15, seg = lane >> 4;
#pragma unroll
                for (int mt = 0; mt < 4; mt++) {
                    unsigned a0 = smem_u32(base + (wm0 + mt * 16 + r) * 80 + (ks + seg * 8) * 2);
                    asm volatile("ldmatrix.sync.aligned.m8n8.x4.shared.b16 {%0,%1,%2,%3}, [%4];"
                        : "=r"(fah[mt][0]), "=r"(fah[mt][1]), "=r"(fah[mt][2]), "=r"(fah[mt][3]) : "r"(a0));
                    if (TERMS == 2) {
                        unsigned a1 = smem_u32(base + 10240 + (wm0 + mt * 16 + r) * 80 + (ks + seg * 8) * 2);
                        asm volatile("ldmatrix.sync.aligned.m8n8.x4.shared.b16 {%0,%1,%2,%3}, [%4];"
                            : "=r"(fal[mt][0]), "=r"(fal[mt][1]), "=r"(fal[mt][2]), "=r"(fal[mt][3]) : "r"(a1));
                    }
                }
            }
            {
                int l = lane & 15;
#pragma unroll
                for (int nt = 0; nt < 4; nt++) {
                    unsigned b0 = smem_u32(base + BOFF + (ks + l) * 272 + (wn0 + nt * 8) * 2);
                    asm volatile("ldmatrix.sync.aligned.m8n8.x2.trans.shared.b16 {%0,%1}, [%2];"
                        : "=r"(fb[nt][0]), "=r"(fb[nt][1]) : "r"(b0));
                }
            }
#pragma unroll
            for (int mt = 0; mt < 4; mt++)
#pragma unroll
                for (int nt = 0; nt < 4; nt++) { float* d = acc[mt][nt]; MMA_F16(d, fah[mt], fb[nt]); }
            if (TERMS == 2) {
#pragma unroll
                for (int mt = 0; mt < 4; mt++)
#pragma unroll
                    for (int nt = 0; nt < 4; nt++) { float* d = acc[mt][nt]; MMA_F16(d, fal[mt], fb[nt]); }
            }
        }
        __syncthreads();
        if (i + 3 < nkc) load_stage(i % 3, (i + 3) * 32);
    }

#pragma unroll
    for (int mt = 0; mt < 4; mt++) {
        int gr = row0 + wm0 + mt * 16 + (lane >> 2);
#pragma unroll
        for (int nt = 0; nt < 4; nt++) {
            int gc = col0 + wn0 + nt * 8 + (lane & 3) * 2;
            if (gc < Nc) {
                *(float2*)&C[(size_t)gr * Nc + gc]       = make_float2(acc[mt][nt][0], acc[mt][nt][1]);
                *(float2*)&C[(size_t)(gr + 8) * Nc + gc] = make_float2(acc[mt][nt][2], acc[mt][nt][3]);
            }
        }
    }
}

// ---------------- rmsnorm + k_pe rope (writes single-plane fp16 kva) --------
__global__ __launch_bounds__(256) void rmsnorm_ropek_kernel(
    const float* __restrict__ latent, const float* __restrict__ w,
    const float* __restrict__ ct, const float* __restrict__ st,
    __half* __restrict__ kvaf, float* __restrict__ kpe)
{
    int t = blockIdx.x;
    const float* x = latent + (size_t)t * (L_KV + D_ROPE);
    __shared__ float red[256];
    float ss = 0.f;
    for (int i = threadIdx.x; i < L_KV; i += 256) { float v = x[i]; ss += v * v; }
    red[threadIdx.x] = ss;
    __syncthreads();
    for (int s = 128; s > 0; s >>= 1) {
        if (threadIdx.x < s) red[threadIdx.x] += red[threadIdx.x + s];
        __syncthreads();
    }
    float inv = rsqrtf(red[0] / (float)L_KV + 1e-6f);
    for (int i = threadIdx.x; i < L_KV; i += 256)
        kvaf[(size_t)t * L_KV + i] = __float2half(x[i] * inv * w[i]);
    if (threadIdx.x < 32) {
        int i = threadIdx.x;
        float c = ct[t * 32 + i], s = st[t * 32 + i];
        float x1 = x[L_KV + i], x2 = x[L_KV + 32 + i];
        kpe[(size_t)t * D_ROPE + i]      = x1 * c - x2 * s;
        kpe[(size_t)t * D_ROPE + 32 + i] = x2 * c + x1 * s;
    }
}

// ---------------- q prep: rope + scale -> single fp16 plane -----------------
__global__ __launch_bounds__(256) void qprep_kernel(
    const float* __restrict__ q, const float* __restrict__ ct, const float* __restrict__ st,
    __half* __restrict__ qf)
{
    int t = blockIdx.x;
    const float SC = 0.07216878364870323f * 1.4426950408889634f;
    for (int idx = threadIdx.x; idx < H_HEADS * D_QK; idx += 256) {
        int c = idx % D_QK;
        const float* qr = q + (size_t)t * 3072 + (idx - c);
        float v;
        if (c < D_NOPE) v = qr[c];
        else {
            int i = c - D_NOPE;
            if (i < 32) v = qr[c] * ct[t * 32 + i] - qr[c + 32] * st[t * 32 + i];
            else { int j = i - 32; v = qr[c] * ct[t * 32 + j] + qr[c - 32] * st[t * 32 + j]; }
        }
        qf[(size_t)t * 3072 + idx] = __float2half(v * SC);
    }
}

// ---------------- k/v prep: K single fp16 plane + V fp16 --------------------
__global__ __launch_bounds__(256) void kprep_kernel(
    const float* __restrict__ kv, const float* __restrict__ kpe,
    __half* __restrict__ kf, __half* __restrict__ vf)
{
    int t = blockIdx.x;
    for (int idx = threadIdx.x; idx < H_HEADS * D_QK; idx += 256) {
        int hh = idx / D_QK, c = idx % D_QK;
        float v = (c < D_NOPE) ? kv[((size_t)t * H_HEADS + hh) * KV_W + c]
                               : kpe[(size_t)t * D_ROPE + (c - D_NOPE)];
        kf[(size_t)t * 3072 + idx] = __float2half(v);
    }
    for (int idx = threadIdx.x; idx < H_HEADS * D_V; idx += 256) {
        int hh = idx / D_V, d = idx % D_V;
        vf[(size_t)t * 2048 + idx] =
            __float2half(kv[((size_t)t * H_HEADS + hh) * KV_W + D_NOPE + d]);
    }
}

// ---------------- tensor-core causal flash attention ------------------------
// BM=128, BN=64, 256 threads. Q, K, V all single fp16 planes.
// smem: Qf(49152) + 2 stages of [Kf 24576 | V 16384] = 131072 B
#define ATT_SMEM (49152 + 2 * 40960)

__global__ __launch_bounds__(256, 1) void attn_mma_kernel(
    const __half* __restrict__ qf, const __half* __restrict__ kf,
    const __half* __restrict__ vf, __half* __restrict__ of)
{
    extern __shared__ char smr[];
    char* sQf = smr;

    const int tid = threadIdx.x, lane = tid & 31, w = tid >> 5;
    const int b  = gridDim.x - 1 - blockIdx.x;
    const int q0 = b * 128;
    const int h  = blockIdx.y;
    const int niter = (q0 + 128) >> 6;

    for (int idx = tid; idx < 128 * 24; idx += 256) {
        int r = idx / 24, c = idx % 24;
        int sw = ((c ^ (r & 7)) << 4);
        size_t g = ((size_t)(q0 + r) * H_HEADS + h) * D_QK + c * 8;
        cp_async16(sQf + r * 384 + sw, qf + g);
    }

    auto load_stage = [&](int st, int s0) {
        char* base = smr + 49152 + st * 40960;
        char* sKf = base, *sV = base + 24576;
        for (int idx = tid; idx < 64 * 24; idx += 256) {
            int r = idx / 24, c = idx % 24;
            int sw = ((c ^ (r & 7)) << 4);
            size_t g = ((size_t)(s0 + r) * H_HEADS + h) * D_QK + c * 8;
            cp_async16(sKf + r * 384 + sw, kf + g);
        }
        for (int idx = tid; idx < 64 * 16; idx += 256) {
            int r = idx / 16, c = idx % 16;
            int sw = ((c ^ (r & 7)) << 4);
            cp_async16(sV + r * 256 + sw,
                       vf + ((size_t)(s0 + r) * H_HEADS + h) * D_V + c * 8);
        }
    };

    load_stage(0, 0);
    cp_commit();

    float m0 = -1e30f, m1 = -1e30f, l0 = 0.f, l1 = 0.f;
    float oacc[16][4];
#pragma unroll
    for (int i = 0; i < 16; i++)
#pragma unroll
        for (int j = 0; j < 4; j++) oacc[i][j] = 0.f;

    for (int it = 0; it < niter; it++) {
        const int s0 = it * 64;
        if (it + 1 < niter) { load_stage((it + 1) & 1, s0 + 64); cp_commit(); }
        if (it + 1 < niter) asm volatile("cp.async.wait_group 1;\n");
        else                asm volatile("cp.async.wait_group 0;\n");
        __syncthreads();

        char* base = smr + 49152 + (it & 1) * 40960;
        char* sKf = base, *sV = base + 24576;

        // ---- S = Q K^T (single fp16 planes: 1 mma) ----
        float sacc[8][4];
#pragma unroll
        for (int i = 0; i < 8; i++)
#pragma unroll
            for (int j = 0; j < 4; j++) sacc[i][j] = 0.f;

#pragma unroll
        for (int kk = 0; kk < 12; kk++) {
            unsigned ah[4];
            {
                int r = 16 * w + (lane & 15);
                int cc = 2 * kk + (lane >> 4);
                unsigned qa = smem_u32(sQf + r * 384 + (((cc ^ (r & 7)) << 4)));
                asm volatile("ldmatrix.sync.aligned.m8n8.x4.shared.b16 {%0,%1,%2,%3}, [%4];"
                    : "=r"(ah[0]), "=r"(ah[1]), "=r"(ah[2]), "=r"(ah[3]) : "r"(qa));
            }
#pragma unroll
            for (int nt = 0; nt < 8; nt++) {
                unsigned bf[2];
                int rK = nt * 8 + (lane & 7);
                int cc = 2 * kk + ((lane & 15) >> 3);
                unsigned ka = smem_u32(sKf + rK * 384 + (((cc ^ (rK & 7)) << 4)));
                asm volatile("ldmatrix.sync.aligned.m8n8.x2.shared.b16 {%0,%1}, [%2];"
                    : "=r"(bf[0]), "=r"(bf[1]) : "r"(ka));
                float* d = sacc[nt];
                MMA_F16(d, ah, bf);
            }
        }

        if (s0 + 64 > q0) {
            int row0 = q0 + 16 * w + (lane >> 2);
#pragma unroll
            for (int nt = 0; nt < 8; nt++) {
                int c = s0 + nt * 8 + (lane & 3) * 2;
                if (c     > row0)     sacc[nt][0] = -1e30f;
                if (c + 1 > row0)     sacc[nt][1] = -1e30f;
                if (c     > row0 + 8) sacc[nt][2] = -1e30f;
                if (c + 1 > row0 + 8) sacc[nt][3] = -1e30f;
            }
        }

        float mx0 = -1e30f, mx1 = -1e30f;
#pragma unroll
        for (int nt = 0; nt < 8; nt++) {
            mx0 = fmaxf(mx0, fmaxf(sacc[nt][0], sacc[nt][1]));
            mx1 = fmaxf(mx1, fmaxf(sacc[nt][2], sacc[nt][3]));
        }
        mx0 = fmaxf(mx0, __shfl_xor_sync(0xffffffffu, mx0, 1));
        mx0 = fmaxf(mx0, __shfl_xor_sync(0xffffffffu, mx0, 2));
        mx1 = fmaxf(mx1, __shfl_xor_sync(0xffffffffu, mx1, 1));
        mx1 = fmaxf(mx1, __shfl_xor_sync(0xffffffffu, mx1, 2));
        float mn0 = fmaxf(m0, mx0), mn1 = fmaxf(m1, mx1);
        float a0 = ex2f(m0 - mn0), a1 = ex2f(m1 - mn1);
        m0 = mn0; m1 = mn1;
        float ps0 = 0.f, ps1 = 0.f;
#pragma unroll
        for (int nt = 0; nt < 8; nt++) {
            float p0 = ex2f(sacc[nt][0] - mn0);
            float p1 = ex2f(sacc[nt][1] - mn0);
            float p2 = ex2f(sacc[nt][2] - mn1);
            float p3 = ex2f(sacc[nt][3] - mn1);
            sacc[nt][0] = p0; sacc[nt][1] = p1; sacc[nt][2] = p2; sacc[nt][3] = p3;
            ps0 += p0 + p1; ps1 += p2 + p3;
        }
        ps0 += __shfl_xor_sync(0xffffffffu, ps0, 1);
        ps0 += __shfl_xor_sync(0xffffffffu, ps0, 2);
        ps1 += __shfl_xor_sync(0xffffffffu, ps1, 1);
        ps1 += __shfl_xor_sync(0xffffffffu, ps1, 2);
        l0 = l0 * a0 + ps0;
        l1 = l1 * a1 + ps1;
#pragma unroll
        for (int nd = 0; nd < 16; nd++) {
            oacc[nd][0] *= a0; oacc[nd][1] *= a0;
            oacc[nd][2] *= a1; oacc[nd][3] *= a1;
        }

        unsigned pa[4][4];
#pragma unroll
        for (int k2 = 0; k2 < 4; k2++) {
            pa[k2][0] = pack_h2(sacc[2 * k2][0],     sacc[2 * k2][1]);
            pa[k2][1] = pack_h2(sacc[2 * k2][2],     sacc[2 * k2][3]);
            pa[k2][2] = pack_h2(sacc[2 * k2 + 1][0], sacc[2 * k2 + 1][1]);
            pa[k2][3] = pack_h2(sacc[2 * k2 + 1][2], sacc[2 * k2 + 1][3]);
        }

#pragma unroll
        for (int k2 = 0; k2 < 4; k2++) {
            int rV = k2 * 16 + (lane & 15);
#pragma unroll
            for (int nd = 0; nd < 16; nd++) {
                unsigned vb[2];
                unsigned va = smem_u32(sV + rV * 256 + (((nd ^ (rV & 7)) << 4)));
                asm volatile("ldmatrix.sync.aligned.m8n8.x2.trans.shared.b16 {%0,%1}, [%2];"
                    : "=r"(vb[0]), "=r"(vb[1]) : "r"(va));
                float* d = oacc[nd];
                MMA_F16(d, pa[k2], vb);
            }
        }
        __syncthreads();
    }

    // epilogue: normalize + write single fp16 plane (Wo GEMM A operand)
    float il0 = 1.f / l0, il1 = 1.f / l1;
    int r0 = q0 + 16 * w + (lane >> 2);
    int cb = h * D_V + (lane & 3) * 2;
#pragma unroll
    for (int nd = 0; nd < 16; nd++) {
        size_t p0 = (size_t)r0 * 2048 + cb + nd * 8;
        size_t p1 = (size_t)(r0 + 8) * 2048 + cb + nd * 8;
        *(__half2*)&of[p0] = __floats2half2_rn(oacc[nd][0] * il0, oacc[nd][1] * il0);
        *(__half2*)&of[p1] = __floats2half2_rn(oacc[nd][2] * il1, oacc[nd][3] * il1);
    }
}

// ---------------- launch ---------------------------------------------------
static inline void hgemm2(const __half* Ah, const __half* Al, const __half* Bf,
                          float* C, int M, int Nc, int Nb, int K) {
    cudaFuncSetAttribute(hgemm_kernel<2>, cudaFuncAttributeMaxDynamicSharedMemorySize, 3 * 29184);
    hgemm_kernel<2><<<dim3(Nb / 128, M / 128), 256, 3 * 29184>>>(Ah, Al, Bf, C, M, Nc, Nb, K);
}
static inline void hgemm1(const __half* Af, const __half* Bf,
                          float* C, int M, int Nc, int Nb, int K) {
    cudaFuncSetAttribute(hgemm_kernel<1>, cudaFuncAttributeMaxDynamicSharedMemorySize, 3 * 18944);
    hgemm_kernel<1><<<dim3(Nb / 128, M / 128), 256, 3 * 18944>>>(Af, Af, Bf, C, M, Nc, Nb, K);
}

extern "C" void kernel_launch(void* const* d_in, const int* in_sizes, int n_in,
                              void* d_out, int out_size)
{
    const int*   positions = (const int*)d_in[0];
    const float* hidden    = (const float*)d_in[1];
    const float* Wq        = (const float*)d_in[2];
    const float* Wkva      = (const float*)d_in[3];
    const float* lnw       = (const float*)d_in[4];
    const float* Wkvb      = (const float*)d_in[5];
    const float* Wo        = (const float*)d_in[6];
    float* out = (float*)d_out;

    float *q, *latent, *kpe, *kv, *tcos, *tsin;
    cudaGetSymbolAddress((void**)&q,      g_q);
    cudaGetSymbolAddress((void**)&latent, g_latent);
    cudaGetSymbolAddress((void**)&kpe,    g_kpe);
    cudaGetSymbolAddress((void**)&kv,     g_kv);
    cudaGetSymbolAddress((void**)&tcos,   g_cos);
    cudaGetSymbolAddress((void**)&tsin,   g_sin);

    __half *hid_h, *hid_l, *kva_f, *attn_f;
    __half *Wq_f, *Wkva_f, *Wkvb_f, *Wo_f;
    __half *qaf, *kaf, *vaf;
    cudaGetSymbolAddress((void**)&hid_h,  g_hid_h);
    cudaGetSymbolAddress((void**)&hid_l,  g_hid_l);
    cudaGetSymbolAddress((void**)&kva_f,  g_kva_f);
    cudaGetSymbolAddress((void**)&attn_f, g_attn_f);
    cudaGetSymbolAddress((void**)&Wq_f,   g_Wq_f);
    cudaGetSymbolAddress((void**)&Wkva_f, g_Wkva_f);
    cudaGetSymbolAddress((void**)&Wkvb_f, g_Wkvb_f);
    cudaGetSymbolAddress((void**)&Wo_f,   g_Wo_f);
    cudaGetSymbolAddress((void**)&qaf,    g_qaf);
    cudaGetSymbolAddress((void**)&kaf,    g_kaf);
    cudaGetSymbolAddress((void**)&vaf,    g_vaf);

    rope_table_kernel<<<T_TOK, 32>>>(positions, tcos, tsin);

    hsplit_kernel<<<(T_TOK * HID + 255) / 256, 256>>>(hidden, hid_h, hid_l, T_TOK * HID);
    wconv_kernel<<<(2048 * 3072 + 255) / 256, 256>>>(Wq,   Wq_f,   3072, 3072, 2048 * 3072);
    wconv_kernel<<<(2048 * 640  + 255) / 256, 256>>>(Wkva, Wkva_f, 576,  640,  2048 * 640);

    // 1. q = hidden @ Wq  (1-term A: hidden fp16 plane)
    hgemm1(hid_h, Wq_f, q, T_TOK, 3072, 3072, HID);
    // 2. latent = hidden @ Wkva (2-term A: exact hidden — chained path insurance)
    hgemm2(hid_h, hid_l, Wkva_f, latent, T_TOK, 576, 640, HID);
    // 3. rmsnorm (fp16 single-plane out) + k_pe rope
    rmsnorm_ropek_kernel<<<T_TOK, 256>>>(latent, lnw, tcos, tsin, kva_f, kpe);
    // 4. kv = kv_a @ Wkvb  (1-term A)
    wconv_kernel<<<(512 * 4096 + 255) / 256, 256>>>(Wkvb, Wkvb_f, 4096, 4096, 512 * 4096);
    hgemm1(kva_f, Wkvb_f, kv, T_TOK, 4096, 4096, L_KV);
    // 5. attention operand prep (single planes)
    qprep_kernel<<<T_TOK, 256>>>(q, tcos, tsin, qaf);
    kprep_kernel<<<T_TOK, 256>>>(kv, kpe, kaf, vaf);
    // 6. tensor-core causal attention
    cudaFuncSetAttribute(attn_mma_kernel, cudaFuncAttributeMaxDynamicSharedMemorySize, ATT_SMEM);
    attn_mma_kernel<<<dim3(T_TOK / 128, H_HEADS), 256, ATT_SMEM>>>(
        qaf, kaf, vaf, attn_f);
    // 7. out = attn @ Wo  (1-term A)
    wconv_kernel<<<(2048 * 2048 + 255) / 256, 256>>>(Wo, Wo_f, 2048, 2048, 2048 * 2048);
    hgemm1(attn_f, Wo_f, out, T_TOK, 2048, 2048, 2048);
}

// round 15
// speedup vs baseline: 9.7591x; 1.1280x over previous
#include <cuda_runtime.h>
#include <cuda_bf16.h>
#include <cuda_fp16.h>
#include <math.h>
#include <stdint.h>
#include <cstdint>

#define T_TOK   4096
#define HID     2048
#define H_HEADS 16
#define D_NOPE  128
#define D_ROPE  64
#define D_V     128
#define L_KV    512
#define D_QK    192
#define KV_W    256

// ---------------- scratch (device globals) ---------------------------------
__device__ float g_q[(size_t)T_TOK * H_HEADS * D_QK];
__device__ float g_latent[(size_t)T_TOK * (L_KV + D_ROPE)];
__device__ float g_kpe[(size_t)T_TOK * D_ROPE];
__device__ float g_kv[(size_t)T_TOK * H_HEADS * KV_W];

__device__ float g_cos[(size_t)T_TOK * 32];
__device__ float g_sin[(size_t)T_TOK * 32];

// activations (fp16, single plane each)
__device__ __half g_hid_f [(size_t)T_TOK * HID];
__device__ __half g_kva_f [(size_t)T_TOK * L_KV];
__device__ __half g_attn_f[(size_t)T_TOK * 2048];

// B-side weights: single fp16 plane
__device__ __half g_Wq_f  [(size_t)2048 * 3072];
__device__ __half g_Wkva_f[(size_t)2048 * 640];   // N=576 padded to 640
__device__ __half g_Wkvb_f[(size_t)512 * 4096];
__device__ __half g_Wo_f  [(size_t)2048 * 2048];

// attention operand buffers (fp16, single plane each)
__device__ __half g_qaf[(size_t)T_TOK * H_HEADS * D_QK];
__device__ __half g_kaf[(size_t)T_TOK * H_HEADS * D_QK];
__device__ __half g_vaf[(size_t)T_TOK * H_HEADS * D_V];

static __device__ __forceinline__ unsigned smem_u32(const void* p) {
    return (unsigned)__cvta_generic_to_shared(p);
}
static __device__ __forceinline__ void cp_async16(void* dst, const void* src) {
    asm volatile("cp.async.cg.shared.global [%0], [%1], 16;\n"
                 :: "r"(smem_u32(dst)), "l"(src));
}
static __device__ __forceinline__ void cp_commit() {
    asm volatile("cp.async.commit_group;\n");
}
static __device__ __forceinline__ unsigned pack_h2(float a, float b) {
    __half2 h = __floats2half2_rn(a, b);
    return *(unsigned*)&h;
}
static __device__ __forceinline__ float ex2f(float x) {
    float r;
    asm("ex2.approx.ftz.f32 %0, %1;" : "=f"(r) : "f"(x));
    return r;
}

#define MMA_F16(D, A, B)                                                     \
    asm volatile(                                                            \
        "mma.sync.aligned.m16n8k16.row.col.f32.f16.f16.f32 "                 \
        "{%0,%1,%2,%3}, {%4,%5,%6,%7}, {%8,%9}, {%0,%1,%2,%3};"              \
        : "+f"(D[0]), "+f"(D[1]), "+f"(D[2]), "+f"(D[3])                     \
        : "r"(A[0]), "r"(A[1]), "r"(A[2]), "r"(A[3]), "r"(B[0]), "r"(B[1]))

// ---------------- rope table ------------------------------------------------
__global__ __launch_bounds__(32) void rope_table_kernel(
    const int* __restrict__ positions, float* __restrict__ ct, float* __restrict__ st)
{
    int t = blockIdx.x, i = threadIdx.x;
    double pos  = (double)positions[t];
    double freq = pow(10000.0, -(double)i / 32.0);
    double ang  = pos * freq;
    ct[t * 32 + i] = (float)cos(ang);
    st[t * 32 + i] = (float)sin(ang);
}

// ---------------- fp32 -> fp16 plain convert --------------------------------
__global__ __launch_bounds__(256) void hconv_kernel(
    const float* __restrict__ x, __half* __restrict__ y, int n)
{
    int i = blockIdx.x * 256 + threadIdx.x;
    if (i < n) y[i] = __float2half(x[i]);
}

// ---------------- fp32 weight [K,N] -> fp16 [K,Npad] (zero pad) -------------
__global__ __launch_bounds__(256) void wconv_kernel(
    const float* __restrict__ X, __half* __restrict__ Y,
    int N, int Npad, int total)
{
    int i = blockIdx.x * 256 + threadIdx.x;
    if (i < total) {
        int r = i / Npad, c = i % Npad;
        Y[i] = __float2half(c < N ? X[(size_t)r * N + c] : 0.f);
    }
}

// ---------------- fp16 1-term tensor-core GEMM ------------------------------
// C[M,Nc] = A[M,K] @ Bf[K,Nb]; 128x128x32 tile, 256 threads, 3-stage cp.async.
// stage: A(10240B) | B(8704B) = 18944 B
#define GSTG 18944
#define GEMM_SMEM (3 * GSTG)

__global__ __launch_bounds__(256) void hgemm_kernel(
    const __half* __restrict__ Af, const __half* __restrict__ Bf,
    float* __restrict__ C, int M, int Nc, int Nb, int K)
{
    extern __shared__ char smr[];
    const int tid = threadIdx.x, lane = tid & 31, wid = tid >> 5;
    const int row0 = blockIdx.y * 128;
    const int col0 = blockIdx.x * 128;
    const int wm0  = (wid & 1) * 64;
    const int wn0  = (wid >> 1) * 32;
    const int nkc  = K >> 5;

    float acc[4][4][4];
#pragma unroll
    for (int a = 0; a < 4; a++)
#pragma unroll
        for (int b = 0; b < 4; b++)
#pragma unroll
            for (int c = 0; c < 4; c++) acc[a][b][c] = 0.f;

    auto load_stage = [&](int st, int kb) {
        char* base = smr + st * GSTG;
#pragma unroll
        for (int j = 0; j < 2; j++) {
            int idx = tid + j * 256;
            int r = idx >> 2, c = idx & 3;
            size_t g = (size_t)(row0 + r) * K + kb + c * 8;
            cp_async16(base + r * 80 + c * 16, Af + g);
        }
#pragma unroll
        for (int j = 0; j < 2; j++) {
            int idx = tid + j * 256;
            int r = idx >> 4, c = idx & 15;
            size_t g = (size_t)(kb + r) * Nb + col0 + c * 8;
            cp_async16(base + 10240 + r * 272 + c * 16, Bf + g);
        }
        cp_commit();
    };

    load_stage(0, 0);
    if (nkc > 1) load_stage(1, 32);
    if (nkc > 2) load_stage(2, 64);

    for (int i = 0; i < nkc; i++) {
        int pend = nkc - 1 - i;
        if (pend >= 2)      asm volatile("cp.async.wait_group 2;\n" ::: "memory");
        else if (pend == 1) asm volatile("cp.async.wait_group 1;\n" ::: "memory");
        else                asm volatile("cp.async.wait_group 0;\n" ::: "memory");
        __syncthreads();

        char* base = smr + (i % 3) * GSTG;
#pragma unroll
        for (int ks = 0; ks < 32; ks += 16) {
            unsigned fa[4][4], fb[4][2];
            {
                int r = lane & 15, seg = lane >> 4;
#pragma unroll
                for (int mt = 0; mt < 4; mt++) {
                    unsigned a0 = smem_u32(base + (wm0 + mt * 16 + r) * 80 + (ks + seg * 8) * 2);
                    asm volatile("ldmatrix.sync.aligned.m8n8.x4.shared.b16 {%0,%1,%2,%3}, [%4];"
                        : "=r"(fa[mt][0]), "=r"(fa[mt][1]), "=r"(fa[mt][2]), "=r"(fa[mt][3]) : "r"(a0));
                }
            }
            {
                int l = lane & 15;
#pragma unroll
                for (int nt = 0; nt < 4; nt++) {
                    unsigned b0 = smem_u32(base + 10240 + (ks + l) * 272 + (wn0 + nt * 8) * 2);
                    asm volatile("ldmatrix.sync.aligned.m8n8.x2.trans.shared.b16 {%0,%1}, [%2];"
                        : "=r"(fb[nt][0]), "=r"(fb[nt][1]) : "r"(b0));
                }
            }
#pragma unroll
            for (int mt = 0; mt < 4; mt++)
#pragma unroll
                for (int nt = 0; nt < 4; nt++) { float* d = acc[mt][nt]; MMA_F16(d, fa[mt], fb[nt]); }
        }
        __syncthreads();
        if (i + 3 < nkc) load_stage(i % 3, (i + 3) * 32);
    }

#pragma unroll
    for (int mt = 0; mt < 4; mt++) {
        int gr = row0 + wm0 + mt * 16 + (lane >> 2);
#pragma unroll
        for (int nt = 0; nt < 4; nt++) {
            int gc = col0 + wn0 + nt * 8 + (lane & 3) * 2;
            if (gc < Nc) {
                *(float2*)&C[(size_t)gr * Nc + gc]       = make_float2(acc[mt][nt][0], acc[mt][nt][1]);
                *(float2*)&C[(size_t)(gr + 8) * Nc + gc] = make_float2(acc[mt][nt][2], acc[mt][nt][3]);
            }
        }
    }
}

// ---------------- rmsnorm + k_pe rope (single-plane fp16 kva) ---------------
__global__ __launch_bounds__(256) void rmsnorm_ropek_kernel(
    const float* __restrict__ latent, const float* __restrict__ w,
    const float* __restrict__ ct, const float* __restrict__ st,
    __half* __restrict__ kvaf, float* __restrict__ kpe)
{
    int t = blockIdx.x;
    const float* x = latent + (size_t)t * (L_KV + D_ROPE);
    __shared__ float red[256];
    float ss = 0.f;
    for (int i = threadIdx.x; i < L_KV; i += 256) { float v = x[i]; ss += v * v; }
    red[threadIdx.x] = ss;
    __syncthreads();
    for (int s = 128; s > 0; s >>= 1) {
        if (threadIdx.x < s) red[threadIdx.x] += red[threadIdx.x + s];
        __syncthreads();
    }
    float inv = rsqrtf(red[0] / (float)L_KV + 1e-6f);
    for (int i = threadIdx.x; i < L_KV; i += 256)
        kvaf[(size_t)t * L_KV + i] = __float2half(x[i] * inv * w[i]);
    if (threadIdx.x < 32) {
        int i = threadIdx.x;
        float c = ct[t * 32 + i], s = st[t * 32 + i];
        float x1 = x[L_KV + i], x2 = x[L_KV + 32 + i];
        kpe[(size_t)t * D_ROPE + i]      = x1 * c - x2 * s;
        kpe[(size_t)t * D_ROPE + 32 + i] = x2 * c + x1 * s;
    }
}

// ---------------- q prep: rope + scale -> single fp16 plane -----------------
__global__ __launch_bounds__(256) void qprep_kernel(
    const float* __restrict__ q, const float* __restrict__ ct, const float* __restrict__ st,
    __half* __restrict__ qf)
{
    int t = blockIdx.x;
    const float SC = 0.07216878364870323f * 1.4426950408889634f;
    for (int idx = threadIdx.x; idx < H_HEADS * D_QK; idx += 256) {
        int c = idx % D_QK;
        const float* qr = q + (size_t)t * 3072 + (idx - c);
        float v;
        if (c < D_NOPE) v = qr[c];
        else {
            int i = c - D_NOPE;
            if (i < 32) v = qr[c] * ct[t * 32 + i] - qr[c + 32] * st[t * 32 + i];
            else { int j = i - 32; v = qr[c] * ct[t * 32 + j] + qr[c - 32] * st[t * 32 + j]; }
        }
        qf[(size_t)t * 3072 + idx] = __float2half(v * SC);
    }
}

// ---------------- k/v prep: K single fp16 plane + V fp16 --------------------
__global__ __launch_bounds__(256) void kprep_kernel(
    const float* __restrict__ kv, const float* __restrict__ kpe,
    __half* __restrict__ kf, __half* __restrict__ vf)
{
    int t = blockIdx.x;
    for (int idx = threadIdx.x; idx < H_HEADS * D_QK; idx += 256) {
        int hh = idx / D_QK, c = idx % D_QK;
        float v = (c < D_NOPE) ? kv[((size_t)t * H_HEADS + hh) * KV_W + c]
                               : kpe[(size_t)t * D_ROPE + (c - D_NOPE)];
        kf[(size_t)t * 3072 + idx] = __float2half(v);
    }
    for (int idx = threadIdx.x; idx < H_HEADS * D_V; idx += 256) {
        int hh = idx / D_V, d = idx % D_V;
        vf[(size_t)t * 2048 + idx] =
            __float2half(kv[((size_t)t * H_HEADS + hh) * KV_W + D_NOPE + d]);
    }
}

// ---------------- tensor-core causal flash attention ------------------------
// BM=128, BN=128, 256 threads (8 warps x 16 q rows).
// smem: Qf(49152) + 2 stages of [Kf 49152 | V 32768] = 212992 B
#define ASTG 81920
#define ATT_SMEM (49152 + 2 * ASTG)

__global__ __launch_bounds__(256, 1) void attn_mma_kernel(
    const __half* __restrict__ qf, const __half* __restrict__ kf,
    const __half* __restrict__ vf, __half* __restrict__ of)
{
    extern __shared__ char smr[];
    char* sQf = smr;

    const int tid = threadIdx.x, lane = tid & 31, w = tid >> 5;
    const int b  = gridDim.x - 1 - blockIdx.x;   // heavy blocks first
    const int q0 = b * 128;
    const int h  = blockIdx.y;
    const int niter = b + 1;                     // 128-wide KV tiles

    for (int idx = tid; idx < 128 * 24; idx += 256) {
        int r = idx / 24, c = idx % 24;
        int sw = ((c ^ (r & 7)) << 4);
        size_t g = ((size_t)(q0 + r) * H_HEADS + h) * D_QK + c * 8;
        cp_async16(sQf + r * 384 + sw, qf + g);
    }

    auto load_stage = [&](int st, int s0) {
        char* base = smr + 49152 + st * ASTG;
        char* sKf = base, *sV = base + 49152;
        for (int idx = tid; idx < 128 * 24; idx += 256) {
            int r = idx / 24, c = idx % 24;
            int sw = ((c ^ (r & 7)) << 4);
            size_t g = ((size_t)(s0 + r) * H_HEADS + h) * D_QK + c * 8;
            cp_async16(sKf + r * 384 + sw, kf + g);
        }
        for (int idx = tid; idx < 128 * 16; idx += 256) {
            int r = idx / 16, c = idx % 16;
            int sw = ((c ^ (r & 7)) << 4);
            cp_async16(sV + r * 256 + sw,
                       vf + ((size_t)(s0 + r) * H_HEADS + h) * D_V + c * 8);
        }
    };

    load_stage(0, 0);
    cp_commit();

    float m0 = -1e30f, m1 = -1e30f, l0 = 0.f, l1 = 0.f;
    float oacc[16][4];
#pragma unroll
    for (int i = 0; i < 16; i++)
#pragma unroll
        for (int j = 0; j < 4; j++) oacc[i][j] = 0.f;

    for (int it = 0; it < niter; it++) {
        const int s0 = it * 128;
        if (it + 1 < niter) { load_stage((it + 1) & 1, s0 + 128); cp_commit(); }
        if (it + 1 < niter) asm volatile("cp.async.wait_group 1;\n");
        else                asm volatile("cp.async.wait_group 0;\n");
        __syncthreads();

        char* base = smr + 49152 + (it & 1) * ASTG;
        char* sKf = base, *sV = base + 49152;

        // ---- S = Q K^T (1 mma per fragment; 16 n-tiles) ----
        float sacc[16][4];
#pragma unroll
        for (int i = 0; i < 16; i++)
#pragma unroll
            for (int j = 0; j < 4; j++) sacc[i][j] = 0.f;

#pragma unroll
        for (int kk = 0; kk < 12; kk++) {
            unsigned ah[4];
            {
                int r = 16 * w + (lane & 15);
                int cc = 2 * kk + (lane >> 4);
                unsigned qa = smem_u32(sQf + r * 384 + (((cc ^ (r & 7)) << 4)));
                asm volatile("ldmatrix.sync.aligned.m8n8.x4.shared.b16 {%0,%1,%2,%3}, [%4];"
                    : "=r"(ah[0]), "=r"(ah[1]), "=r"(ah[2]), "=r"(ah[3]) : "r"(qa));
            }
#pragma unroll
            for (int nt = 0; nt < 16; nt++) {
                unsigned bf[2];
                int rK = nt * 8 + (lane & 7);
                int cc = 2 * kk + ((lane & 15) >> 3);
                unsigned ka = smem_u32(sKf + rK * 384 + (((cc ^ (rK & 7)) << 4)));
                asm volatile("ldmatrix.sync.aligned.m8n8.x2.shared.b16 {%0,%1}, [%2];"
                    : "=r"(bf[0]), "=r"(bf[1]) : "r"(ka));
                float* d = sacc[nt];
                MMA_F16(d, ah, bf);
            }
        }

        // ---- causal mask (diagonal tile = last iteration) ----
        if (s0 + 128 > q0) {
            int row0 = q0 + 16 * w + (lane >> 2);
#pragma unroll
            for (int nt = 0; nt < 16; nt++) {
                int c = s0 + nt * 8 + (lane & 3) * 2;
                if (c     > row0)     sacc[nt][0] = -1e30f;
                if (c + 1 > row0)     sacc[nt][1] = -1e30f;
                if (c     > row0 + 8) sacc[nt][2] = -1e30f;
                if (c + 1 > row0 + 8) sacc[nt][3] = -1e30f;
            }
        }

        // ---- online softmax (exp2 domain) ----
        float mx0 = -1e30f, mx1 = -1e30f;
#pragma unroll
        for (int nt = 0; nt < 16; nt++) {
            mx0 = fmaxf(mx0, fmaxf(sacc[nt][0], sacc[nt][1]));
            mx1 = fmaxf(mx1, fmaxf(sacc[nt][2], sacc[nt][3]));
        }
        mx0 = fmaxf(mx0, __shfl_xor_sync(0xffffffffu, mx0, 1));
        mx0 = fmaxf(mx0, __shfl_xor_sync(0xffffffffu, mx0, 2));
        mx1 = fmaxf(mx1, __shfl_xor_sync(0xffffffffu, mx1, 1));
        mx1 = fmaxf(mx1, __shfl_xor_sync(0xffffffffu, mx1, 2));
        float mn0 = fmaxf(m0, mx0), mn1 = fmaxf(m1, mx1);
        float a0 = ex2f(m0 - mn0), a1 = ex2f(m1 - mn1);
        m0 = mn0; m1 = mn1;
        float ps0 = 0.f, ps1 = 0.f;
#pragma unroll
        for (int nt = 0; nt < 16; nt++) {
            float p0 = ex2f(sacc[nt][0] - mn0);
            float p1 = ex2f(sacc[nt][1] - mn0);
            float p2 = ex2f(sacc[nt][2] - mn1);
            float p3 = ex2f(sacc[nt][3] - mn1);
            sacc[nt][0] = p0; sacc[nt][1] = p1; sacc[nt][2] = p2; sacc[nt][3] = p3;
            ps0 += p0 + p1; ps1 += p2 + p3;
        }
        ps0 += __shfl_xor_sync(0xffffffffu, ps0, 1);
        ps0 += __shfl_xor_sync(0xffffffffu, ps0, 2);
        ps1 += __shfl_xor_sync(0xffffffffu, ps1, 1);
        ps1 += __shfl_xor_sync(0xffffffffu, ps1, 2);
        l0 = l0 * a0 + ps0;
        l1 = l1 * a1 + ps1;
#pragma unroll
        for (int nd = 0; nd < 16; nd++) {
            oacc[nd][0] *= a0; oacc[nd][1] *= a0;
            oacc[nd][2] *= a1; oacc[nd][3] *= a1;
        }

        // ---- P fragments (fp16): 8 k-steps of 16 ----
        unsigned pa[8][4];
#pragma unroll
        for (int k2 = 0; k2 < 8; k2++) {
            pa[k2][0] = pack_h2(sacc[2 * k2][0],     sacc[2 * k2][1]);
            pa[k2][1] = pack_h2(sacc[2 * k2][2],     sacc[2 * k2][3]);
            pa[k2][2] = pack_h2(sacc[2 * k2 + 1][0], sacc[2 * k2 + 1][1]);
            pa[k2][3] = pack_h2(sacc[2 * k2 + 1][2], sacc[2 * k2 + 1][3]);
        }

        // ---- O += P V ----
#pragma unroll
        for (int k2 = 0; k2 < 8; k2++) {
            int rV = k2 * 16 + (lane & 15);
#pragma unroll
            for (int nd = 0; nd < 16; nd++) {
                unsigned vb[2];
                unsigned va = smem_u32(sV + rV * 256 + (((nd ^ (rV & 7)) << 4)));
                asm volatile("ldmatrix.sync.aligned.m8n8.x2.trans.shared.b16 {%0,%1}, [%2];"
                    : "=r"(vb[0]), "=r"(vb[1]) : "r"(va));
                float* d = oacc[nd];
                MMA_F16(d, pa[k2], vb);
            }
        }
        __syncthreads();
    }

    // epilogue: normalize + write single fp16 plane (Wo GEMM A operand)
    float il0 = 1.f / l0, il1 = 1.f / l1;
    int r0 = q0 + 16 * w + (lane >> 2);
    int cb = h * D_V + (lane & 3) * 2;
#pragma unroll
    for (int nd = 0; nd < 16; nd++) {
        size_t p0 = (size_t)r0 * 2048 + cb + nd * 8;
        size_t p1 = (size_t)(r0 + 8) * 2048 + cb + nd * 8;
        *(__half2*)&of[p0] = __floats2half2_rn(oacc[nd][0] * il0, oacc[nd][1] * il0);
        *(__half2*)&of[p1] = __floats2half2_rn(oacc[nd][2] * il1, oacc[nd][3] * il1);
    }
}

// ---------------- launch ---------------------------------------------------
static inline void hgemm(const __half* Af, const __half* Bf,
                         float* C, int M, int Nc, int Nb, int K) {
    cudaFuncSetAttribute(hgemm_kernel, cudaFuncAttributeMaxDynamicSharedMemorySize, GEMM_SMEM);
    hgemm_kernel<<<dim3(Nb / 128, M / 128), 256, GEMM_SMEM>>>(Af, Bf, C, M, Nc, Nb, K);
}

extern "C" void kernel_launch(void* const* d_in, const int* in_sizes, int n_in,
                              void* d_out, int out_size)
{
    const int*   positions = (const int*)d_in[0];
    const float* hidden    = (const float*)d_in[1];
    const float* Wq        = (const float*)d_in[2];
    const float* Wkva      = (const float*)d_in[3];
    const float* lnw       = (const float*)d_in[4];
    const float* Wkvb      = (const float*)d_in[5];
    const float* Wo        = (const float*)d_in[6];
    float* out = (float*)d_out;

    float *q, *latent, *kpe, *kv, *tcos, *tsin;
    cudaGetSymbolAddress((void**)&q,      g_q);
    cudaGetSymbolAddress((void**)&latent, g_latent);
    cudaGetSymbolAddress((void**)&kpe,    g_kpe);
    cudaGetSymbolAddress((void**)&kv,     g_kv);
    cudaGetSymbolAddress((void**)&tcos,   g_cos);
    cudaGetSymbolAddress((void**)&tsin,   g_sin);

    __half *hid_f, *kva_f, *attn_f;
    __half *Wq_f, *Wkva_f, *Wkvb_f, *Wo_f;
    __half *qaf, *kaf, *vaf;
    cudaGetSymbolAddress((void**)&hid_f,  g_hid_f);
    cudaGetSymbolAddress((void**)&kva_f,  g_kva_f);
    cudaGetSymbolAddress((void**)&attn_f, g_attn_f);
    cudaGetSymbolAddress((void**)&Wq_f,   g_Wq_f);
    cudaGetSymbolAddress((void**)&Wkva_f, g_Wkva_f);
    cudaGetSymbolAddress((void**)&Wkvb_f, g_Wkvb_f);
    cudaGetSymbolAddress((void**)&Wo_f,   g_Wo_f);
    cudaGetSymbolAddress((void**)&qaf,    g_qaf);
    cudaGetSymbolAddress((void**)&kaf,    g_kaf);
    cudaGetSymbolAddress((void**)&vaf,    g_vaf);

    rope_table_kernel<<<T_TOK, 32>>>(positions, tcos, tsin);

    hconv_kernel<<<(T_TOK * HID + 255) / 256, 256>>>(hidden, hid_f, T_TOK * HID);
    wconv_kernel<<<(2048 * 3072 + 255) / 256, 256>>>(Wq,   Wq_f,   3072, 3072, 2048 * 3072);
    wconv_kernel<<<(2048 * 640  + 255) / 256, 256>>>(Wkva, Wkva_f, 576,  640,  2048 * 640);

    // 1. q = hidden @ Wq
    hgemm(hid_f, Wq_f, q, T_TOK, 3072, 3072, HID);
    // 2. latent = hidden @ Wkva
    hgemm(hid_f, Wkva_f, latent, T_TOK, 576, 640, HID);
    // 3. rmsnorm (fp16 out) + k_pe rope
    rmsnorm_ropek_kernel<<<T_TOK, 256>>>(latent, lnw, tcos, tsin, kva_f, kpe);
    // 4. kv = kv_a @ Wkvb
    wconv_kernel<<<(512 * 4096 + 255) / 256, 256>>>(Wkvb, Wkvb_f, 4096, 4096, 512 * 4096);
    hgemm(kva_f, Wkvb_f, kv, T_TOK, 4096, 4096, L_KV);
    // 5. attention operand prep
    qprep_kernel<<<T_TOK, 256>>>(q, tcos, tsin, qaf);
    kprep_kernel<<<T_TOK, 256>>>(kv, kpe, kaf, vaf);
    // 6. tensor-core causal attention (BN=128)
    cudaFuncSetAttribute(attn_mma_kernel, cudaFuncAttributeMaxDynamicSharedMemorySize, ATT_SMEM);
    attn_mma_kernel<<<dim3(T_TOK / 128, H_HEADS), 256, ATT_SMEM>>>(
        qaf, kaf, vaf, attn_f);
    // 7. out = attn @ Wo
    wconv_kernel<<<(2048 * 2048 + 255) / 256, 256>>>(Wo, Wo_f, 2048, 2048, 2048 * 2048);
    hgemm(attn_f, Wo_f, out, T_TOK, 2048, 2048, 2048);
}

// round 16
// speedup vs baseline: 9.7666x; 1.0008x over previous
#include <cuda_runtime.h>
#include <cuda_bf16.h>
#include <cuda_fp16.h>
#include <math.h>
#include <stdint.h>
#include <cstdint>

#define T_TOK   4096
#define HID     2048
#define H_HEADS 16
#define D_NOPE  128
#define D_ROPE  64
#define D_V     128
#define L_KV    512
#define D_QK    192
#define KV_W    256

// ---------------- scratch (device globals) ---------------------------------
__device__ float g_q[(size_t)T_TOK * H_HEADS * D_QK];
__device__ float g_latent[(size_t)T_TOK * (L_KV + D_ROPE)];
__device__ float g_kpe[(size_t)T_TOK * D_ROPE];
__device__ float g_kv[(size_t)T_TOK * H_HEADS * KV_W];

__device__ float g_cos[(size_t)T_TOK * 32];
__device__ float g_sin[(size_t)T_TOK * 32];

// activations (fp16, single plane each)
__device__ __half g_hid_f [(size_t)T_TOK * HID];
__device__ __half g_kva_f [(size_t)T_TOK * L_KV];
__device__ __half g_attn_f[(size_t)T_TOK * 2048];

// B-side weights: single fp16 plane
__device__ __half g_Wq_f  [(size_t)2048 * 3072];
__device__ __half g_Wkva_f[(size_t)2048 * 640];   // N=576 padded to 640
__device__ __half g_Wkvb_f[(size_t)512 * 4096];
__device__ __half g_Wo_f  [(size_t)2048 * 2048];

// attention operand buffers (fp16, single plane each)
__device__ __half g_qaf[(size_t)T_TOK * H_HEADS * D_QK];
__device__ __half g_kaf[(size_t)T_TOK * H_HEADS * D_QK];
__device__ __half g_vaf[(size_t)T_TOK * H_HEADS * D_V];

static __device__ __forceinline__ unsigned smem_u32(const void* p) {
    return (unsigned)__cvta_generic_to_shared(p);
}
static __device__ __forceinline__ void cp_async16(void* dst, const void* src) {
    asm volatile("cp.async.cg.shared.global [%0], [%1], 16;\n"
                 :: "r"(smem_u32(dst)), "l"(src));
}
static __device__ __forceinline__ void cp_commit() {
    asm volatile("cp.async.commit_group;\n");
}
static __device__ __forceinline__ unsigned pack_h2(float a, float b) {
    __half2 h = __floats2half2_rn(a, b);
    return *(unsigned*)&h;
}
static __device__ __forceinline__ float ex2f(float x) {
    float r;
    asm("ex2.approx.ftz.f32 %0, %1;" : "=f"(r) : "f"(x));
    return r;
}

#define MMA_F16(D, A, B)                                                     \
    asm volatile(                                                            \
        "mma.sync.aligned.m16n8k16.row.col.f32.f16.f16.f32 "                 \
        "{%0,%1,%2,%3}, {%4,%5,%6,%7}, {%8,%9}, {%0,%1,%2,%3};"              \
        : "+f"(D[0]), "+f"(D[1]), "+f"(D[2]), "+f"(D[3])                     \
        : "r"(A[0]), "r"(A[1]), "r"(A[2]), "r"(A[3]), "r"(B[0]), "r"(B[1]))

// ---------------- rope table ------------------------------------------------
__global__ __launch_bounds__(32) void rope_table_kernel(
    const int* __restrict__ positions, float* __restrict__ ct, float* __restrict__ st)
{
    int t = blockIdx.x, i = threadIdx.x;
    double pos  = (double)positions[t];
    double freq = pow(10000.0, -(double)i / 32.0);
    double ang  = pos * freq;
    ct[t * 32 + i] = (float)cos(ang);
    st[t * 32 + i] = (float)sin(ang);
}

// ---------------- fp32 -> fp16 plain convert --------------------------------
__global__ __launch_bounds__(256) void hconv_kernel(
    const float* __restrict__ x, __half* __restrict__ y, int n)
{
    int i = blockIdx.x * 256 + threadIdx.x;
    if (i < n) y[i] = __float2half(x[i]);
}

// ---------------- fp32 weight [K,N] -> fp16 [K,Npad] (zero pad) -------------
__global__ __launch_bounds__(256) void wconv_kernel(
    const float* __restrict__ X, __half* __restrict__ Y,
    int N, int Npad, int total)
{
    int i = blockIdx.x * 256 + threadIdx.x;
    if (i < total) {
        int r = i / Npad, c = i % Npad;
        Y[i] = __float2half(c < N ? X[(size_t)r * N + c] : 0.f);
    }
}

// ---------------- fp16 1-term tensor-core GEMM ------------------------------
// C[M,Nc] = A[M,K] @ Bf[K,Nb]; 128x128x32 tile, 256 threads, 3-stage cp.async.
// stage: A(10240B) | B(8704B) = 18944 B
#define GSTG 18944
#define GEMM_SMEM (3 * GSTG)

__global__ __launch_bounds__(256) void hgemm_kernel(
    const __half* __restrict__ Af, const __half* __restrict__ Bf,
    float* __restrict__ C, int M, int Nc, int Nb, int K)
{
    extern __shared__ char smr[];
    const int tid = threadIdx.x, lane = tid & 31, wid = tid >> 5;
    const int row0 = blockIdx.y * 128;
    const int col0 = blockIdx.x * 128;
    const int wm0  = (wid & 1) * 64;
    const int wn0  = (wid >> 1) * 32;
    const int nkc  = K >> 5;

    float acc[4][4][4];
#pragma unroll
    for (int a = 0; a < 4; a++)
#pragma unroll
        for (int b = 0; b < 4; b++)
#pragma unroll
            for (int c = 0; c < 4; c++) acc[a][b][c] = 0.f;

    auto load_stage = [&](int st, int kb) {
        char* base = smr + st * GSTG;
#pragma unroll
        for (int j = 0; j < 2; j++) {
            int idx = tid + j * 256;
            int r = idx >> 2, c = idx & 3;
            size_t g = (size_t)(row0 + r) * K + kb + c * 8;
            cp_async16(base + r * 80 + c * 16, Af + g);
        }
#pragma unroll
        for (int j = 0; j < 2; j++) {
            int idx = tid + j * 256;
            int r = idx >> 4, c = idx & 15;
            size_t g = (size_t)(kb + r) * Nb + col0 + c * 8;
            cp_async16(base + 10240 + r * 272 + c * 16, Bf + g);
        }
        cp_commit();
    };

    load_stage(0, 0);
    if (nkc > 1) load_stage(1, 32);
    if (nkc > 2) load_stage(2, 64);

    for (int i = 0; i < nkc; i++) {
        int pend = nkc - 1 - i;
        if (pend >= 2)      asm volatile("cp.async.wait_group 2;\n" ::: "memory");
        else if (pend == 1) asm volatile("cp.async.wait_group 1;\n" ::: "memory");
        else                asm volatile("cp.async.wait_group 0;\n" ::: "memory");
        __syncthreads();

        char* base = smr + (i % 3) * GSTG;
#pragma unroll
        for (int ks = 0; ks < 32; ks += 16) {
            unsigned fa[4][4], fb[4][2];
            {
                int r = lane & 15, seg = lane >> 4;
#pragma unroll
                for (int mt = 0; mt < 4; mt++) {
                    unsigned a0 = smem_u32(base + (wm0 + mt * 16 + r) * 80 + (ks + seg * 8) * 2);
                    asm volatile("ldmatrix.sync.aligned.m8n8.x4.shared.b16 {%0,%1,%2,%3}, [%4];"
                        : "=r"(fa[mt][0]), "=r"(fa[mt][1]), "=r"(fa[mt][2]), "=r"(fa[mt][3]) : "r"(a0));
                }
            }
            {
                // x4.trans feeding two n-tiles per load (lanes 16-31 -> nt+1)
                int l = lane & 15;
#pragma unroll
                for (int np = 0; np < 2; np++) {
                    int ncol = wn0 + (np * 2 + (lane >> 4)) * 8;
                    unsigned b0 = smem_u32(base + 10240 + (ks + l) * 272 + ncol * 2);
                    asm volatile("ldmatrix.sync.aligned.m8n8.x4.trans.shared.b16 {%0,%1,%2,%3}, [%4];"
                        : "=r"(fb[np * 2][0]), "=r"(fb[np * 2][1]),
                          "=r"(fb[np * 2 + 1][0]), "=r"(fb[np * 2 + 1][1]) : "r"(b0));
                }
            }
#pragma unroll
            for (int mt = 0; mt < 4; mt++)
#pragma unroll
                for (int nt = 0; nt < 4; nt++) { float* d = acc[mt][nt]; MMA_F16(d, fa[mt], fb[nt]); }
        }
        __syncthreads();
        if (i + 3 < nkc) load_stage(i % 3, (i + 3) * 32);
    }

#pragma unroll
    for (int mt = 0; mt < 4; mt++) {
        int gr = row0 + wm0 + mt * 16 + (lane >> 2);
#pragma unroll
        for (int nt = 0; nt < 4; nt++) {
            int gc = col0 + wn0 + nt * 8 + (lane & 3) * 2;
            if (gc < Nc) {
                *(float2*)&C[(size_t)gr * Nc + gc]       = make_float2(acc[mt][nt][0], acc[mt][nt][1]);
                *(float2*)&C[(size_t)(gr + 8) * Nc + gc] = make_float2(acc[mt][nt][2], acc[mt][nt][3]);
            }
        }
    }
}

// ---------------- rmsnorm + k_pe rope (single-plane fp16 kva) ---------------
__global__ __launch_bounds__(256) void rmsnorm_ropek_kernel(
    const float* __restrict__ latent, const float* __restrict__ w,
    const float* __restrict__ ct, const float* __restrict__ st,
    __half* __restrict__ kvaf, float* __restrict__ kpe)
{
    int t = blockIdx.x;
    const float* x = latent + (size_t)t * (L_KV + D_ROPE);
    __shared__ float red[256];
    float ss = 0.f;
    for (int i = threadIdx.x; i < L_KV; i += 256) { float v = x[i]; ss += v * v; }
    red[threadIdx.x] = ss;
    __syncthreads();
    for (int s = 128; s > 0; s >>= 1) {
        if (threadIdx.x < s) red[threadIdx.x] += red[threadIdx.x + s];
        __syncthreads();
    }
    float inv = rsqrtf(red[0] / (float)L_KV + 1e-6f);
    for (int i = threadIdx.x; i < L_KV; i += 256)
        kvaf[(size_t)t * L_KV + i] = __float2half(x[i] * inv * w[i]);
    if (threadIdx.x < 32) {
        int i = threadIdx.x;
        float c = ct[t * 32 + i], s = st[t * 32 + i];
        float x1 = x[L_KV + i], x2 = x[L_KV + 32 + i];
        kpe[(size_t)t * D_ROPE + i]      = x1 * c - x2 * s;
        kpe[(size_t)t * D_ROPE + 32 + i] = x2 * c + x1 * s;
    }
}

// ---------------- q prep: rope + scale -> single fp16 plane -----------------
__global__ __launch_bounds__(256) void qprep_kernel(
    const float* __restrict__ q, const float* __restrict__ ct, const float* __restrict__ st,
    __half* __restrict__ qf)
{
    int t = blockIdx.x;
    const float SC = 0.07216878364870323f * 1.4426950408889634f;
    for (int idx = threadIdx.x; idx < H_HEADS * D_QK; idx += 256) {
        int c = idx % D_QK;
        const float* qr = q + (size_t)t * 3072 + (idx - c);
        float v;
        if (c < D_NOPE) v = qr[c];
        else {
            int i = c - D_NOPE;
            if (i < 32) v = qr[c] * ct[t * 32 + i] - qr[c + 32] * st[t * 32 + i];
            else { int j = i - 32; v = qr[c] * ct[t * 32 + j] + qr[c - 32] * st[t * 32 + j]; }
        }
        qf[(size_t)t * 3072 + idx] = __float2half(v * SC);
    }
}

// ---------------- k/v prep: K single fp16 plane + V fp16 --------------------
__global__ __launch_bounds__(256) void kprep_kernel(
    const float* __restrict__ kv, const float* __restrict__ kpe,
    __half* __restrict__ kf, __half* __restrict__ vf)
{
    int t = blockIdx.x;
    for (int idx = threadIdx.x; idx < H_HEADS * D_QK; idx += 256) {
        int hh = idx / D_QK, c = idx % D_QK;
        float v = (c < D_NOPE) ? kv[((size_t)t * H_HEADS + hh) * KV_W + c]
                               : kpe[(size_t)t * D_ROPE + (c - D_NOPE)];
        kf[(size_t)t * 3072 + idx] = __float2half(v);
    }
    for (int idx = threadIdx.x; idx < H_HEADS * D_V; idx += 256) {
        int hh = idx / D_V, d = idx % D_V;
        vf[(size_t)t * 2048 + idx] =
            __float2half(kv[((size_t)t * H_HEADS + hh) * KV_W + D_NOPE + d]);
    }
}

// ---------------- tensor-core causal flash attention ------------------------
// BM=128, BN=128, 256 threads (8 warps x 16 q rows).
// smem: Qf(49152) + 2 stages of [Kf 49152 | V 32768] = 212992 B
#define ASTG 81920
#define ATT_SMEM (49152 + 2 * ASTG)

__global__ __launch_bounds__(256, 1) void attn_mma_kernel(
    const __half* __restrict__ qf, const __half* __restrict__ kf,
    const __half* __restrict__ vf, __half* __restrict__ of)
{
    extern __shared__ char smr[];
    char* sQf = smr;

    const int tid = threadIdx.x, lane = tid & 31, w = tid >> 5;
    const int b  = gridDim.x - 1 - blockIdx.x;   // heavy blocks first
    const int q0 = b * 128;
    const int h  = blockIdx.y;
    const int niter = b + 1;                     // 128-wide KV tiles

    for (int idx = tid; idx < 128 * 24; idx += 256) {
        int r = idx / 24, c = idx % 24;
        int sw = ((c ^ (r & 7)) << 4);
        size_t g = ((size_t)(q0 + r) * H_HEADS + h) * D_QK + c * 8;
        cp_async16(sQf + r * 384 + sw, qf + g);
    }

    auto load_stage = [&](int st, int s0) {
        char* base = smr + 49152 + st * ASTG;
        char* sKf = base, *sV = base + 49152;
        for (int idx = tid; idx < 128 * 24; idx += 256) {
            int r = idx / 24, c = idx % 24;
            int sw = ((c ^ (r & 7)) << 4);
            size_t g = ((size_t)(s0 + r) * H_HEADS + h) * D_QK + c * 8;
            cp_async16(sKf + r * 384 + sw, kf + g);
        }
        for (int idx = tid; idx < 128 * 16; idx += 256) {
            int r = idx / 16, c = idx % 16;
            int sw = ((c ^ (r & 7)) << 4);
            cp_async16(sV + r * 256 + sw,
                       vf + ((size_t)(s0 + r) * H_HEADS + h) * D_V + c * 8);
        }
    };

    load_stage(0, 0);
    cp_commit();

    float m0 = -1e30f, m1 = -1e30f, l0 = 0.f, l1 = 0.f;
    float oacc[16][4];
#pragma unroll
    for (int i = 0; i < 16; i++)
#pragma unroll
        for (int j = 0; j < 4; j++) oacc[i][j] = 0.f;

    for (int it = 0; it < niter; it++) {
        const int s0 = it * 128;
        if (it + 1 < niter) { load_stage((it + 1) & 1, s0 + 128); cp_commit(); }
        if (it + 1 < niter) asm volatile("cp.async.wait_group 1;\n");
        else                asm volatile("cp.async.wait_group 0;\n");
        __syncthreads();

        char* base = smr + 49152 + (it & 1) * ASTG;
        char* sKf = base, *sV = base + 49152;

        // ---- S = Q K^T (x4 B-loads feed two n-tiles each) ----
        float sacc[16][4];
#pragma unroll
        for (int i = 0; i < 16; i++)
#pragma unroll
            for (int j = 0; j < 4; j++) sacc[i][j] = 0.f;

#pragma unroll
        for (int kk = 0; kk < 12; kk++) {
            unsigned ah[4];
            {
                int r = 16 * w + (lane & 15);
                int cc = 2 * kk + (lane >> 4);
                unsigned qa = smem_u32(sQf + r * 384 + (((cc ^ (r & 7)) << 4)));
                asm volatile("ldmatrix.sync.aligned.m8n8.x4.shared.b16 {%0,%1,%2,%3}, [%4];"
                    : "=r"(ah[0]), "=r"(ah[1]), "=r"(ah[2]), "=r"(ah[3]) : "r"(qa));
            }
#pragma unroll
            for (int nt2 = 0; nt2 < 8; nt2++) {
                unsigned bf[4];
                int rK = nt2 * 16 + ((lane >> 4) << 3) + (lane & 7);
                int cc = 2 * kk + ((lane >> 3) & 1);
                unsigned ka = smem_u32(sKf + rK * 384 + (((cc ^ (rK & 7)) << 4)));
                asm volatile("ldmatrix.sync.aligned.m8n8.x4.shared.b16 {%0,%1,%2,%3}, [%4];"
                    : "=r"(bf[0]), "=r"(bf[1]), "=r"(bf[2]), "=r"(bf[3]) : "r"(ka));
                { float* d = sacc[2 * nt2];     MMA_F16(d, ah, (bf)); }
                { float* d = sacc[2 * nt2 + 1]; MMA_F16(d, ah, (bf + 2)); }
            }
        }

        // ---- causal mask (diagonal tile = last iteration) ----
        if (s0 + 128 > q0) {
            int row0 = q0 + 16 * w + (lane >> 2);
#pragma unroll
            for (int nt = 0; nt < 16; nt++) {
                int c = s0 + nt * 8 + (lane & 3) * 2;
                if (c     > row0)     sacc[nt][0] = -1e30f;
                if (c + 1 > row0)     sacc[nt][1] = -1e30f;
                if (c     > row0 + 8) sacc[nt][2] = -1e30f;
                if (c + 1 > row0 + 8) sacc[nt][3] = -1e30f;
            }
        }

        // ---- online softmax (exp2 domain) ----
        float mx0 = -1e30f, mx1 = -1e30f;
#pragma unroll
        for (int nt = 0; nt < 16; nt++) {
            mx0 = fmaxf(mx0, fmaxf(sacc[nt][0], sacc[nt][1]));
            mx1 = fmaxf(mx1, fmaxf(sacc[nt][2], sacc[nt][3]));
        }
        mx0 = fmaxf(mx0, __shfl_xor_sync(0xffffffffu, mx0, 1));
        mx0 = fmaxf(mx0, __shfl_xor_sync(0xffffffffu, mx0, 2));
        mx1 = fmaxf(mx1, __shfl_xor_sync(0xffffffffu, mx1, 1));
        mx1 = fmaxf(mx1, __shfl_xor_sync(0xffffffffu, mx1, 2));
        float mn0 = fmaxf(m0, mx0), mn1 = fmaxf(m1, mx1);
        float a0 = ex2f(m0 - mn0), a1 = ex2f(m1 - mn1);
        m0 = mn0; m1 = mn1;
        float ps0 = 0.f, ps1 = 0.f;
#pragma unroll
        for (int nt = 0; nt < 16; nt++) {
            float p0 = ex2f(sacc[nt][0] - mn0);
            float p1 = ex2f(sacc[nt][1] - mn0);
            float p2 = ex2f(sacc[nt][2] - mn1);
            float p3 = ex2f(sacc[nt][3] - mn1);
            sacc[nt][0] = p0; sacc[nt][1] = p1; sacc[nt][2] = p2; sacc[nt][3] = p3;
            ps0 += p0 + p1; ps1 += p2 + p3;
        }
        ps0 += __shfl_xor_sync(0xffffffffu, ps0, 1);
        ps0 += __shfl_xor_sync(0xffffffffu, ps0, 2);
        ps1 += __shfl_xor_sync(0xffffffffu, ps1, 1);
        ps1 += __shfl_xor_sync(0xffffffffu, ps1, 2);
        l0 = l0 * a0 + ps0;
        l1 = l1 * a1 + ps1;
#pragma unroll
        for (int nd = 0; nd < 16; nd++) {
            oacc[nd][0] *= a0; oacc[nd][1] *= a0;
            oacc[nd][2] *= a1; oacc[nd][3] *= a1;
        }

        // ---- P fragments (fp16): 8 k-steps of 16 ----
        unsigned pa[8][4];
#pragma unroll
        for (int k2 = 0; k2 < 8; k2++) {
            pa[k2][0] = pack_h2(sacc[2 * k2][0],     sacc[2 * k2][1]);
            pa[k2][1] = pack_h2(sacc[2 * k2][2],     sacc[2 * k2][3]);
            pa[k2][2] = pack_h2(sacc[2 * k2 + 1][0], sacc[2 * k2 + 1][1]);
            pa[k2][3] = pack_h2(sacc[2 * k2 + 1][2], sacc[2 * k2 + 1][3]);
        }

        // ---- O += P V (x4.trans feeds two nd tiles each) ----
#pragma unroll
        for (int k2 = 0; k2 < 8; k2++) {
            int rV = k2 * 16 + (lane & 15);
#pragma unroll
            for (int nd2 = 0; nd2 < 8; nd2++) {
                unsigned vb[4];
                int nds = nd2 * 2 + (lane >> 4);
                unsigned va = smem_u32(sV + rV * 256 + (((nds ^ (rV & 7)) << 4)));
                asm volatile("ldmatrix.sync.aligned.m8n8.x4.trans.shared.b16 {%0,%1,%2,%3}, [%4];"
                    : "=r"(vb[0]), "=r"(vb[1]), "=r"(vb[2]), "=r"(vb[3]) : "r"(va));
                { float* d = oacc[2 * nd2];     MMA_F16(d, pa[k2], (vb)); }
                { float* d = oacc[2 * nd2 + 1]; MMA_F16(d, pa[k2], (vb + 2)); }
            }
        }
        __syncthreads();
    }

    // epilogue: normalize + write single fp16 plane (Wo GEMM A operand)
    float il0 = 1.f / l0, il1 = 1.f / l1;
    int r0 = q0 + 16 * w + (lane >> 2);
    int cb = h * D_V + (lane & 3) * 2;
#pragma unroll
    for (int nd = 0; nd < 16; nd++) {
        size_t p0 = (size_t)r0 * 2048 + cb + nd * 8;
        size_t p1 = (size_t)(r0 + 8) * 2048 + cb + nd * 8;
        *(__half2*)&of[p0] = __floats2half2_rn(oacc[nd][0] * il0, oacc[nd][1] * il0);
        *(__half2*)&of[p1] = __floats2half2_rn(oacc[nd][2] * il1, oacc[nd][3] * il1);
    }
}

// ---------------- launch ---------------------------------------------------
static inline void hgemm(const __half* Af, const __half* Bf,
                         float* C, int M, int Nc, int Nb, int K) {
    cudaFuncSetAttribute(hgemm_kernel, cudaFuncAttributeMaxDynamicSharedMemorySize, GEMM_SMEM);
    hgemm_kernel<<<dim3(Nb / 128, M / 128), 256, GEMM_SMEM>>>(Af, Bf, C, M, Nc, Nb, K);
}

extern "C" void kernel_launch(void* const* d_in, const int* in_sizes, int n_in,
                              void* d_out, int out_size)
{
    const int*   positions = (const int*)d_in[0];
    const float* hidden    = (const float*)d_in[1];
    const float* Wq        = (const float*)d_in[2];
    const float* Wkva      = (const float*)d_in[3];
    const float* lnw       = (const float*)d_in[4];
    const float* Wkvb      = (const float*)d_in[5];
    const float* Wo        = (const float*)d_in[6];
    float* out = (float*)d_out;

    float *q, *latent, *kpe, *kv, *tcos, *tsin;
    cudaGetSymbolAddress((void**)&q,      g_q);
    cudaGetSymbolAddress((void**)&latent, g_latent);
    cudaGetSymbolAddress((void**)&kpe,    g_kpe);
    cudaGetSymbolAddress((void**)&kv,     g_kv);
    cudaGetSymbolAddress((void**)&tcos,   g_cos);
    cudaGetSymbolAddress((void**)&tsin,   g_sin);

    __half *hid_f, *kva_f, *attn_f;
    __half *Wq_f, *Wkva_f, *Wkvb_f, *Wo_f;
    __half *qaf, *kaf, *vaf;
    cudaGetSymbolAddress((void**)&hid_f,  g_hid_f);
    cudaGetSymbolAddress((void**)&kva_f,  g_kva_f);
    cudaGetSymbolAddress((void**)&attn_f, g_attn_f);
    cudaGetSymbolAddress((void**)&Wq_f,   g_Wq_f);
    cudaGetSymbolAddress((void**)&Wkva_f, g_Wkva_f);
    cudaGetSymbolAddress((void**)&Wkvb_f, g_Wkvb_f);
    cudaGetSymbolAddress((void**)&Wo_f,   g_Wo_f);
    cudaGetSymbolAddress((void**)&qaf,    g_qaf);
    cudaGetSymbolAddress((void**)&kaf,    g_kaf);
    cudaGetSymbolAddress((void**)&vaf,    g_vaf);

    rope_table_kernel<<<T_TOK, 32>>>(positions, tcos, tsin);

    hconv_kernel<<<(T_TOK * HID + 255) / 256, 256>>>(hidden, hid_f, T_TOK * HID);
    wconv_kernel<<<(2048 * 3072 + 255) / 256, 256>>>(Wq,   Wq_f,   3072, 3072, 2048 * 3072);
    wconv_kernel<<<(2048 * 640  + 255) / 256, 256>>>(Wkva, Wkva_f, 576,  640,  2048 * 640);

    // 1. q = hidden @ Wq
    hgemm(hid_f, Wq_f, q, T_TOK, 3072, 3072, HID);
    // 2. latent = hidden @ Wkva
    hgemm(hid_f, Wkva_f, latent, T_TOK, 576, 640, HID);
    // 3. rmsnorm (fp16 out) + k_pe rope
    rmsnorm_ropek_kernel<<<T_TOK, 256>>>(latent, lnw, tcos, tsin, kva_f, kpe);
    // 4. kv = kv_a @ Wkvb
    wconv_kernel<<<(512 * 4096 + 255) / 256, 256>>>(Wkvb, Wkvb_f, 4096, 4096, 512 * 4096);
    hgemm(kva_f, Wkvb_f, kv, T_TOK, 4096, 4096, L_KV);
    // 5. attention operand prep
    qprep_kernel<<<T_TOK, 256>>>(q, tcos, tsin, qaf);
    kprep_kernel<<<T_TOK, 256>>>(kv, kpe, kaf, vaf);
    // 6. tensor-core causal attention (BN=128, x4 ldmatrix)
    cudaFuncSetAttribute(attn_mma_kernel, cudaFuncAttributeMaxDynamicSharedMemorySize, ATT_SMEM);
    attn_mma_kernel<<<dim3(T_TOK / 128, H_HEADS), 256, ATT_SMEM>>>(
        qaf, kaf, vaf, attn_f);
    // 7. out = attn @ Wo
    wconv_kernel<<<(2048 * 2048 + 255) / 256, 256>>>(Wo, Wo_f, 2048, 2048, 2048 * 2048);
    hgemm(attn_f, Wo_f, out, T_TOK, 2048, 2048, 2048);
}

// round 17
// speedup vs baseline: 10.5500x; 1.0802x over previous
#include <cuda_runtime.h>
#include <cuda_bf16.h>
#include <cuda_fp16.h>
#include <math.h>
#include <stdint.h>
#include <cstdint>

#define T_TOK   4096
#define HID     2048
#define H_HEADS 16
#define D_NOPE  128
#define D_ROPE  64
#define D_V     128
#define L_KV    512
#define D_QK    192
#define KV_W    256
#define NQL     3712   // 3072 (q) + 640 (latent padded)

// ---------------- scratch (device globals) ---------------------------------
__device__ float g_qlat[(size_t)T_TOK * NQL];     // q (cols 0..3071) | latent (3072..)

__device__ float g_cos[(size_t)T_TOK * 32];
__device__ float g_sin[(size_t)T_TOK * 32];

// activations (fp16, single plane each)
__device__ __half g_hid_f [(size_t)T_TOK * HID];
__device__ __half g_kva_f [(size_t)T_TOK * L_KV];
__device__ __half g_attn_f[(size_t)T_TOK * 2048];

// weights fp16: Wq|Wkva merged, Wkvb, Wo
__device__ __half g_Wqa_f [(size_t)2048 * NQL];
__device__ __half g_Wkvb_f[(size_t)512 * 4096];
__device__ __half g_Wo_f  [(size_t)2048 * 2048];

// attention operand buffers (fp16)
__device__ __half g_qaf[(size_t)T_TOK * H_HEADS * D_QK];
__device__ __half g_kaf[(size_t)T_TOK * H_HEADS * D_QK];
__device__ __half g_vaf[(size_t)T_TOK * H_HEADS * D_V];

static __device__ __forceinline__ unsigned smem_u32(const void* p) {
    return (unsigned)__cvta_generic_to_shared(p);
}
static __device__ __forceinline__ void cp_async16(void* dst, const void* src) {
    asm volatile("cp.async.cg.shared.global [%0], [%1], 16;\n"
                 :: "r"(smem_u32(dst)), "l"(src));
}
static __device__ __forceinline__ void cp_commit() {
    asm volatile("cp.async.commit_group;\n");
}
static __device__ __forceinline__ unsigned pack_h2(float a, float b) {
    __half2 h = __floats2half2_rn(a, b);
    return *(unsigned*)&h;
}
static __device__ __forceinline__ float ex2f(float x) {
    float r;
    asm("ex2.approx.ftz.f32 %0, %1;" : "=f"(r) : "f"(x));
    return r;
}

#define MMA_F16(D, A, B)                                                     \
    asm volatile(                                                            \
        "mma.sync.aligned.m16n8k16.row.col.f32.f16.f16.f32 "                 \
        "{%0,%1,%2,%3}, {%4,%5,%6,%7}, {%8,%9}, {%0,%1,%2,%3};"              \
        : "+f"(D[0]), "+f"(D[1]), "+f"(D[2]), "+f"(D[3])                     \
        : "r"(A[0]), "r"(A[1]), "r"(A[2]), "r"(A[3]), "r"(B[0]), "r"(B[1]))

// ---------------- rope table ------------------------------------------------
__global__ __launch_bounds__(32) void rope_table_kernel(
    const int* __restrict__ positions, float* __restrict__ ct, float* __restrict__ st)
{
    int t = blockIdx.x, i = threadIdx.x;
    double pos  = (double)positions[t];
    double freq = pow(10000.0, -(double)i / 32.0);
    double ang  = pos * freq;
    ct[t * 32 + i] = (float)cos(ang);
    st[t * 32 + i] = (float)sin(ang);
}

// ---------------- fp32 -> fp16 plain convert --------------------------------
__global__ __launch_bounds__(256) void hconv_kernel(
    const float* __restrict__ x, __half* __restrict__ y, int n)
{
    int i = blockIdx.x * 256 + threadIdx.x;
    if (i < n) y[i] = __float2half(x[i]);
}

// ---- fp32 weight [K,N] -> fp16 strided slice Y[r*ostride + coff + c] -------
__global__ __launch_bounds__(256) void wconvs_kernel(
    const float* __restrict__ X, __half* __restrict__ Y,
    int N, int Ncopy, int coff, int ostride, int total)
{
    int i = blockIdx.x * 256 + threadIdx.x;
    if (i < total) {
        int r = i / Ncopy, c = i % Ncopy;
        Y[(size_t)r * ostride + coff + c] = __float2half(c < N ? X[(size_t)r * N + c] : 0.f);
    }
}

// ---------------- fp16 tensor-core GEMM -------------------------------------
// EPI 0: C fp32 [M,Nc]. EPI 1: fused kv epilogue -> kf/vf fp16 (Nb=4096).
// 128x128x32 tile, 256 threads, 3-stage cp.async.
#define GSTG 18944
#define GEMM_SMEM (3 * GSTG)

template <int EPI>
__global__ __launch_bounds__(256) void hgemm_kernel(
    const __half* __restrict__ Af, const __half* __restrict__ Bf,
    float* __restrict__ C, __half* __restrict__ kf, __half* __restrict__ vf,
    int M, int Nc, int Nb, int K)
{
    extern __shared__ char smr[];
    const int tid = threadIdx.x, lane = tid & 31, wid = tid >> 5;
    const int row0 = blockIdx.y * 128;
    const int col0 = blockIdx.x * 128;
    const int wm0  = (wid & 1) * 64;
    const int wn0  = (wid >> 1) * 32;
    const int nkc  = K >> 5;

    float acc[4][4][4];
#pragma unroll
    for (int a = 0; a < 4; a++)
#pragma unroll
        for (int b = 0; b < 4; b++)
#pragma unroll
            for (int c = 0; c < 4; c++) acc[a][b][c] = 0.f;

    auto load_stage = [&](int st, int kb) {
        char* base = smr + st * GSTG;
#pragma unroll
        for (int j = 0; j < 2; j++) {
            int idx = tid + j * 256;
            int r = idx >> 2, c = idx & 3;
            size_t g = (size_t)(row0 + r) * K + kb + c * 8;
            cp_async16(base + r * 80 + c * 16, Af + g);
        }
#pragma unroll
        for (int j = 0; j < 2; j++) {
            int idx = tid + j * 256;
            int r = idx >> 4, c = idx & 15;
            size_t g = (size_t)(kb + r) * Nb + col0 + c * 8;
            cp_async16(base + 10240 + r * 272 + c * 16, Bf + g);
        }
        cp_commit();
    };

    load_stage(0, 0);
    if (nkc > 1) load_stage(1, 32);
    if (nkc > 2) load_stage(2, 64);

    for (int i = 0; i < nkc; i++) {
        int pend = nkc - 1 - i;
        if (pend >= 2)      asm volatile("cp.async.wait_group 2;\n" ::: "memory");
        else if (pend == 1) asm volatile("cp.async.wait_group 1;\n" ::: "memory");
        else                asm volatile("cp.async.wait_group 0;\n" ::: "memory");
        __syncthreads();

        char* base = smr + (i % 3) * GSTG;
#pragma unroll
        for (int ks = 0; ks < 32; ks += 16) {
            unsigned fa[4][4], fb[4][2];
            {
                int r = lane & 15, seg = lane >> 4;
#pragma unroll
                for (int mt = 0; mt < 4; mt++) {
                    unsigned a0 = smem_u32(base + (wm0 + mt * 16 + r) * 80 + (ks + seg * 8) * 2);
                    asm volatile("ldmatrix.sync.aligned.m8n8.x4.shared.b16 {%0,%1,%2,%3}, [%4];"
                        : "=r"(fa[mt][0]), "=r"(fa[mt][1]), "=r"(fa[mt][2]), "=r"(fa[mt][3]) : "r"(a0));
                }
            }
            {
                int l = lane & 15;
#pragma unroll
                for (int np = 0; np < 2; np++) {
                    int ncol = wn0 + (np * 2 + (lane >> 4)) * 8;
                    unsigned b0 = smem_u32(base + 10240 + (ks + l) * 272 + ncol * 2);
                    asm volatile("ldmatrix.sync.aligned.m8n8.x4.trans.shared.b16 {%0,%1,%2,%3}, [%4];"
                        : "=r"(fb[np * 2][0]), "=r"(fb[np * 2][1]),
                          "=r"(fb[np * 2 + 1][0]), "=r"(fb[np * 2 + 1][1]) : "r"(b0));
                }
            }
#pragma unroll
            for (int mt = 0; mt < 4; mt++)
#pragma unroll
                for (int nt = 0; nt < 4; nt++) { float* d = acc[mt][nt]; MMA_F16(d, fa[mt], fb[nt]); }
        }
        __syncthreads();
        if (i + 3 < nkc) load_stage(i % 3, (i + 3) * 32);
    }

#pragma unroll
    for (int mt = 0; mt < 4; mt++) {
        int gr = row0 + wm0 + mt * 16 + (lane >> 2);
#pragma unroll
        for (int nt = 0; nt < 4; nt++) {
            int gc = col0 + wn0 + nt * 8 + (lane & 3) * 2;
            if (EPI == 0) {
                if (gc < Nc) {
                    *(float2*)&C[(size_t)gr * Nc + gc]       = make_float2(acc[mt][nt][0], acc[mt][nt][1]);
                    *(float2*)&C[(size_t)(gr + 8) * Nc + gc] = make_float2(acc[mt][nt][2], acc[mt][nt][3]);
                }
            } else {
                // fused kv epilogue: gc in [0,4096); head = gc>>8, c = gc&255
                int hh = gc >> 8, c = gc & 255;
                __half2 v0 = __floats2half2_rn(acc[mt][nt][0], acc[mt][nt][1]);
                __half2 v1 = __floats2half2_rn(acc[mt][nt][2], acc[mt][nt][3]);
                if (c < D_NOPE) {
                    size_t o0 = (size_t)gr * 3072 + hh * D_QK + c;
                    size_t o1 = (size_t)(gr + 8) * 3072 + hh * D_QK + c;
                    *(__half2*)&kf[o0] = v0;
                    *(__half2*)&kf[o1] = v1;
                } else {
                    size_t o0 = (size_t)gr * 2048 + hh * D_V + (c - D_NOPE);
                    size_t o1 = (size_t)(gr + 8) * 2048 + hh * D_V + (c - D_NOPE);
                    *(__half2*)&vf[o0] = v0;
                    *(__half2*)&vf[o1] = v1;
                }
            }
        }
    }
}

// ---------------- rmsnorm + k_pe rope (kva fp16 + kf rope broadcast) --------
__global__ __launch_bounds__(256) void rmsnorm_ropek_kernel(
    const float* __restrict__ qlat, const float* __restrict__ w,
    const float* __restrict__ ct, const float* __restrict__ st,
    __half* __restrict__ kvaf, __half* __restrict__ kf)
{
    int t = blockIdx.x;
    const float* x = qlat + (size_t)t * NQL + 3072;   // latent slice
    __shared__ float red[256];
    float ss = 0.f;
    for (int i = threadIdx.x; i < L_KV; i += 256) { float v = x[i]; ss += v * v; }
    red[threadIdx.x] = ss;
    __syncthreads();
    for (int s = 128; s > 0; s >>= 1) {
        if (threadIdx.x < s) red[threadIdx.x] += red[threadIdx.x + s];
        __syncthreads();
    }
    float inv = rsqrtf(red[0] / (float)L_KV + 1e-6f);
    for (int i = threadIdx.x; i < L_KV; i += 256)
        kvaf[(size_t)t * L_KV + i] = __float2half(x[i] * inv * w[i]);

    // k_pe rope, broadcast into all 16 heads of kf (cols 128..191)
    if (threadIdx.x < 32) {
        int i = threadIdx.x;
        float c = ct[t * 32 + i], s = st[t * 32 + i];
        float x1 = x[L_KV + i], x2 = x[L_KV + 32 + i];
        __half r0 = __float2half(x1 * c - x2 * s);
        __half r1 = __float2half(x2 * c + x1 * s);
#pragma unroll
        for (int hh = 0; hh < H_HEADS; hh++) {
            kf[(size_t)t * 3072 + hh * D_QK + D_NOPE + i]      = r0;
            kf[(size_t)t * 3072 + hh * D_QK + D_NOPE + 32 + i] = r1;
        }
    }
}

// ---------------- q prep: rope + scale -> single fp16 plane -----------------
__global__ __launch_bounds__(256) void qprep_kernel(
    const float* __restrict__ qlat, const float* __restrict__ ct, const float* __restrict__ st,
    __half* __restrict__ qf)
{
    int t = blockIdx.x;
    const float SC = 0.07216878364870323f * 1.4426950408889634f;
    for (int idx = threadIdx.x; idx < H_HEADS * D_QK; idx += 256) {
        int c = idx % D_QK;
        const float* qr = qlat + (size_t)t * NQL + (idx - c);
        float v;
        if (c < D_NOPE) v = qr[c];
        else {
            int i = c - D_NOPE;
            if (i < 32) v = qr[c] * ct[t * 32 + i] - qr[c + 32] * st[t * 32 + i];
            else { int j = i - 32; v = qr[c] * ct[t * 32 + j] + qr[c - 32] * st[t * 32 + j]; }
        }
        qf[(size_t)t * 3072 + idx] = __float2half(v * SC);
    }
}

// ---------------- tensor-core causal flash attention ------------------------
// BM=128, BN=128, 256 threads (8 warps x 16 q rows).
#define ASTG 81920
#define ATT_SMEM (49152 + 2 * ASTG)

__global__ __launch_bounds__(256, 1) void attn_mma_kernel(
    const __half* __restrict__ qf, const __half* __restrict__ kf,
    const __half* __restrict__ vf, __half* __restrict__ of)
{
    extern __shared__ char smr[];
    char* sQf = smr;

    const int tid = threadIdx.x, lane = tid & 31, w = tid >> 5;
    const int b  = gridDim.x - 1 - blockIdx.x;
    const int q0 = b * 128;
    const int h  = blockIdx.y;
    const int niter = b + 1;

    for (int idx = tid; idx < 128 * 24; idx += 256) {
        int r = idx / 24, c = idx % 24;
        int sw = ((c ^ (r & 7)) << 4);
        size_t g = ((size_t)(q0 + r) * H_HEADS + h) * D_QK + c * 8;
        cp_async16(sQf + r * 384 + sw, qf + g);
    }

    auto load_stage = [&](int st, int s0) {
        char* base = smr + 49152 + st * ASTG;
        char* sKf = base, *sV = base + 49152;
        for (int idx = tid; idx < 128 * 24; idx += 256) {
            int r = idx / 24, c = idx % 24;
            int sw = ((c ^ (r & 7)) << 4);
            size_t g = ((size_t)(s0 + r) * H_HEADS + h) * D_QK + c * 8;
            cp_async16(sKf + r * 384 + sw, kf + g);
        }
        for (int idx = tid; idx < 128 * 16; idx += 256) {
            int r = idx / 16, c = idx % 16;
            int sw = ((c ^ (r & 7)) << 4);
            cp_async16(sV + r * 256 + sw,
                       vf + ((size_t)(s0 + r) * H_HEADS + h) * D_V + c * 8);
        }
    };

    load_stage(0, 0);
    cp_commit();

    float m0 = -1e30f, m1 = -1e30f, l0 = 0.f, l1 = 0.f;
    float oacc[16][4];
#pragma unroll
    for (int i = 0; i < 16; i++)
#pragma unroll
        for (int j = 0; j < 4; j++) oacc[i][j] = 0.f;

    for (int it = 0; it < niter; it++) {
        const int s0 = it * 128;
        if (it + 1 < niter) { load_stage((it + 1) & 1, s0 + 128); cp_commit(); }
        if (it + 1 < niter) asm volatile("cp.async.wait_group 1;\n");
        else                asm volatile("cp.async.wait_group 0;\n");
        __syncthreads();

        char* base = smr + 49152 + (it & 1) * ASTG;
        char* sKf = base, *sV = base + 49152;

        float sacc[16][4];
#pragma unroll
        for (int i = 0; i < 16; i++)
#pragma unroll
            for (int j = 0; j < 4; j++) sacc[i][j] = 0.f;

#pragma unroll
        for (int kk = 0; kk < 12; kk++) {
            unsigned ah[4];
            {
                int r = 16 * w + (lane & 15);
                int cc = 2 * kk + (lane >> 4);
                unsigned qa = smem_u32(sQf + r * 384 + (((cc ^ (r & 7)) << 4)));
                asm volatile("ldmatrix.sync.aligned.m8n8.x4.shared.b16 {%0,%1,%2,%3}, [%4];"
                    : "=r"(ah[0]), "=r"(ah[1]), "=r"(ah[2]), "=r"(ah[3]) : "r"(qa));
            }
#pragma unroll
            for (int nt2 = 0; nt2 < 8; nt2++) {
                unsigned bf[4];
                int rK = nt2 * 16 + ((lane >> 4) << 3) + (lane & 7);
                int cc = 2 * kk + ((lane >> 3) & 1);
                unsigned ka = smem_u32(sKf + rK * 384 + (((cc ^ (rK & 7)) << 4)));
                asm volatile("ldmatrix.sync.aligned.m8n8.x4.shared.b16 {%0,%1,%2,%3}, [%4];"
                    : "=r"(bf[0]), "=r"(bf[1]), "=r"(bf[2]), "=r"(bf[3]) : "r"(ka));
                { float* d = sacc[2 * nt2];     MMA_F16(d, ah, (bf)); }
                { float* d = sacc[2 * nt2 + 1]; MMA_F16(d, ah, (bf + 2)); }
            }
        }

        if (s0 + 128 > q0) {
            int row0 = q0 + 16 * w + (lane >> 2);
#pragma unroll
            for (int nt = 0; nt < 16; nt++) {
                int c = s0 + nt * 8 + (lane & 3) * 2;
                if (c     > row0)     sacc[nt][0] = -1e30f;
                if (c + 1 > row0)     sacc[nt][1] = -1e30f;
                if (c     > row0 + 8) sacc[nt][2] = -1e30f;
                if (c + 1 > row0 + 8) sacc[nt][3] = -1e30f;
            }
        }

        float mx0 = -1e30f, mx1 = -1e30f;
#pragma unroll
        for (int nt = 0; nt < 16; nt++) {
            mx0 = fmaxf(mx0, fmaxf(sacc[nt][0], sacc[nt][1]));
            mx1 = fmaxf(mx1, fmaxf(sacc[nt][2], sacc[nt][3]));
        }
        mx0 = fmaxf(mx0, __shfl_xor_sync(0xffffffffu, mx0, 1));
        mx0 = fmaxf(mx0, __shfl_xor_sync(0xffffffffu, mx0, 2));
        mx1 = fmaxf(mx1, __shfl_xor_sync(0xffffffffu, mx1, 1));
        mx1 = fmaxf(mx1, __shfl_xor_sync(0xffffffffu, mx1, 2));
        float mn0 = fmaxf(m0, mx0), mn1 = fmaxf(m1, mx1);
        float a0 = ex2f(m0 - mn0), a1 = ex2f(m1 - mn1);
        m0 = mn0; m1 = mn1;
        float ps0 = 0.f, ps1 = 0.f;
#pragma unroll
        for (int nt = 0; nt < 16; nt++) {
            float p0 = ex2f(sacc[nt][0] - mn0);
            float p1 = ex2f(sacc[nt][1] - mn0);
            float p2 = ex2f(sacc[nt][2] - mn1);
            float p3 = ex2f(sacc[nt][3] - mn1);
            sacc[nt][0] = p0; sacc[nt][1] = p1; sacc[nt][2] = p2; sacc[nt][3] = p3;
            ps0 += p0 + p1; ps1 += p2 + p3;
        }
        ps0 += __shfl_xor_sync(0xffffffffu, ps0, 1);
        ps0 += __shfl_xor_sync(0xffffffffu, ps0, 2);
        ps1 += __shfl_xor_sync(0xffffffffu, ps1, 1);
        ps1 += __shfl_xor_sync(0xffffffffu, ps1, 2);
        l0 = l0 * a0 + ps0;
        l1 = l1 * a1 + ps1;
#pragma unroll
        for (int nd = 0; nd < 16; nd++) {
            oacc[nd][0] *= a0; oacc[nd][1] *= a0;
            oacc[nd][2] *= a1; oacc[nd][3] *= a1;
        }

        unsigned pa[8][4];
#pragma unroll
        for (int k2 = 0; k2 < 8; k2++) {
            pa[k2][0] = pack_h2(sacc[2 * k2][0],     sacc[2 * k2][1]);
            pa[k2][1] = pack_h2(sacc[2 * k2][2],     sacc[2 * k2][3]);
            pa[k2][2] = pack_h2(sacc[2 * k2 + 1][0], sacc[2 * k2 + 1][1]);
            pa[k2][3] = pack_h2(sacc[2 * k2 + 1][2], sacc[2 * k2 + 1][3]);
        }

#pragma unroll
        for (int k2 = 0; k2 < 8; k2++) {
            int rV = k2 * 16 + (lane & 15);
#pragma unroll
            for (int nd2 = 0; nd2 < 8; nd2++) {
                unsigned vb[4];
                int nds = nd2 * 2 + (lane >> 4);
                unsigned va = smem_u32(sV + rV * 256 + (((nds ^ (rV & 7)) << 4)));
                asm volatile("ldmatrix.sync.aligned.m8n8.x4.trans.shared.b16 {%0,%1,%2,%3}, [%4];"
                    : "=r"(vb[0]), "=r"(vb[1]), "=r"(vb[2]), "=r"(vb[3]) : "r"(va));
                { float* d = oacc[2 * nd2];     MMA_F16(d, pa[k2], (vb)); }
                { float* d = oacc[2 * nd2 + 1]; MMA_F16(d, pa[k2], (vb + 2)); }
            }
        }
        __syncthreads();
    }

    float il0 = 1.f / l0, il1 = 1.f / l1;
    int r0 = q0 + 16 * w + (lane >> 2);
    int cb = h * D_V + (lane & 3) * 2;
#pragma unroll
    for (int nd = 0; nd < 16; nd++) {
        size_t p0 = (size_t)r0 * 2048 + cb + nd * 8;
        size_t p1 = (size_t)(r0 + 8) * 2048 + cb + nd * 8;
        *(__half2*)&of[p0] = __floats2half2_rn(oacc[nd][0] * il0, oacc[nd][1] * il0);
        *(__half2*)&of[p1] = __floats2half2_rn(oacc[nd][2] * il1, oacc[nd][3] * il1);
    }
}

// ---------------- launch ---------------------------------------------------
extern "C" void kernel_launch(void* const* d_in, const int* in_sizes, int n_in,
                              void* d_out, int out_size)
{
    const int*   positions = (const int*)d_in[0];
    const float* hidden    = (const float*)d_in[1];
    const float* Wq        = (const float*)d_in[2];
    const float* Wkva      = (const float*)d_in[3];
    const float* lnw       = (const float*)d_in[4];
    const float* Wkvb      = (const float*)d_in[5];
    const float* Wo        = (const float*)d_in[6];
    float* out = (float*)d_out;

    float *qlat, *tcos, *tsin;
    cudaGetSymbolAddress((void**)&qlat, g_qlat);
    cudaGetSymbolAddress((void**)&tcos, g_cos);
    cudaGetSymbolAddress((void**)&tsin, g_sin);

    __half *hid_f, *kva_f, *attn_f, *Wqa_f, *Wkvb_f, *Wo_f, *qaf, *kaf, *vaf;
    cudaGetSymbolAddress((void**)&hid_f,  g_hid_f);
    cudaGetSymbolAddress((void**)&kva_f,  g_kva_f);
    cudaGetSymbolAddress((void**)&attn_f, g_attn_f);
    cudaGetSymbolAddress((void**)&Wqa_f,  g_Wqa_f);
    cudaGetSymbolAddress((void**)&Wkvb_f, g_Wkvb_f);
    cudaGetSymbolAddress((void**)&Wo_f,   g_Wo_f);
    cudaGetSymbolAddress((void**)&qaf,    g_qaf);
    cudaGetSymbolAddress((void**)&kaf,    g_kaf);
    cudaGetSymbolAddress((void**)&vaf,    g_vaf);

    cudaFuncSetAttribute(hgemm_kernel<0>, cudaFuncAttributeMaxDynamicSharedMemorySize, GEMM_SMEM);
    cudaFuncSetAttribute(hgemm_kernel<1>, cudaFuncAttributeMaxDynamicSharedMemorySize, GEMM_SMEM);
    cudaFuncSetAttribute(attn_mma_kernel, cudaFuncAttributeMaxDynamicSharedMemorySize, ATT_SMEM);

    rope_table_kernel<<<T_TOK, 32>>>(positions, tcos, tsin);

    hconv_kernel<<<(T_TOK * HID + 255) / 256, 256>>>(hidden, hid_f, T_TOK * HID);
    // merged Wq | Wkva -> [2048, 3712]
    wconvs_kernel<<<(2048 * 3072 + 255) / 256, 256>>>(Wq,   Wqa_f, 3072, 3072, 0,    NQL, 2048 * 3072);
    wconvs_kernel<<<(2048 * 640  + 255) / 256, 256>>>(Wkva, Wqa_f, 576,  640,  3072, NQL, 2048 * 640);

    // 1+2. qlat = hidden @ [Wq | Wkva]
    hgemm_kernel<0><<<dim3(NQL / 128, T_TOK / 128), 256, GEMM_SMEM>>>(
        hid_f, Wqa_f, qlat, nullptr, nullptr, T_TOK, NQL, NQL, HID);
    // 3. rmsnorm (fp16 out) + k_pe rope broadcast into kf
    rmsnorm_ropek_kernel<<<T_TOK, 256>>>(qlat, lnw, tcos, tsin, kva_f, kaf);
    // 4. kv GEMM with fused kf/vf epilogue
    wconvs_kernel<<<(512 * 4096 + 255) / 256, 256>>>(Wkvb, Wkvb_f, 4096, 4096, 0, 4096, 512 * 4096);
    hgemm_kernel<1><<<dim3(4096 / 128, T_TOK / 128), 256, GEMM_SMEM>>>(
        kva_f, Wkvb_f, nullptr, kaf, vaf, T_TOK, 4096, 4096, L_KV);
    // 5. q prep
    qprep_kernel<<<T_TOK, 256>>>(qlat, tcos, tsin, qaf);
    // 6. attention
    attn_mma_kernel<<<dim3(T_TOK / 128, H_HEADS), 256, ATT_SMEM>>>(
        qaf, kaf, vaf, attn_f);
    // 7. out = attn @ Wo
    wconvs_kernel<<<(2048 * 2048 + 255) / 256, 256>>>(Wo, Wo_f, 2048, 2048, 0, 2048, 2048 * 2048);
    hgemm_kernel<0><<<dim3(2048 / 128, T_TOK / 128), 256, GEMM_SMEM>>>(
        attn_f, Wo_f, out, nullptr, nullptr, T_TOK, 2048, 2048, 2048);
}